// round 3
// baseline (speedup 1.0000x reference)
#include <cuda_runtime.h>
#include <math.h>

#define BB 2
#define TT 2048
#define CC 1024
#define HH 16
#define DD 64
#define BT (BB*TT)

// ---------- scratch (__device__ globals; no runtime allocation) ----------
__device__ float g_q[BT*CC];
__device__ float g_k[BT*CC];
__device__ float g_v[BT*CC];
__device__ float g_att[BT*CC];
__device__ float g_z[BT*CC];
__device__ float g_f[BT*HH];
__device__ float g_den[BB*HH*TT];   // holds 1/denom
__device__ float g_cos[TT*32];
__device__ float g_sin[TT*32];

// ---------- packed f32x2 helpers ----------
__device__ __forceinline__ unsigned long long pack2(float lo, float hi) {
    unsigned long long r;
    asm("mov.b64 %0, {%1, %2};" : "=l"(r) : "f"(lo), "f"(hi));
    return r;
}
__device__ __forceinline__ float2 unpack2(unsigned long long v) {
    float2 f;
    asm("mov.b64 {%0, %1}, %2;" : "=f"(f.x), "=f"(f.y) : "l"(v));
    return f;
}
__device__ __forceinline__ unsigned long long mul2(unsigned long long a, unsigned long long b) {
    unsigned long long r;
    asm("mul.rn.f32x2 %0, %1, %2;" : "=l"(r) : "l"(a), "l"(b));
    return r;
}
#define FFMA2(acc, a, b) asm("fma.rn.f32x2 %0, %1, %2, %0;" : "+l"(acc) : "l"(a), "l"(b))

__device__ __forceinline__ float phi_f(float x) { return x > 0.0f ? x + 1.0f : expf(x); }

// ---------- GEMM: C[M,N] = A[M,K] * W[N,K]^T ----------
#define GBM 128
#define GBN 128
#define GBK 8

template<bool EPI>
__device__ __forceinline__ void gemm_body(const float* __restrict__ A,
                                          const float* __restrict__ W,
                                          float* __restrict__ Cout,
                                          const float* __restrict__ bias,
                                          const float* __restrict__ resid,
                                          int M, int N, int K)
{
    __shared__ float As[2][GBK][GBM];
    __shared__ float Bs[2][GBK][GBN];
    int tid = threadIdx.x;
    int m0 = blockIdx.y * GBM;
    int n0 = blockIdx.x * GBN;
    int lr = tid >> 1;            // 0..127
    int lk = (tid & 1) << 2;      // 0 or 4
    int ty = tid >> 4;            // 0..15
    int tx = tid & 15;            // 0..15

    const float* Aptr = A + (long)(m0 + lr) * K + lk;
    const float* Wptr = W + (long)(n0 + lr) * K + lk;

    {   // stage 0
        float4 av = *(const float4*)Aptr;
        float4 bv = *(const float4*)Wptr;
        As[0][lk+0][lr] = av.x; As[0][lk+1][lr] = av.y;
        As[0][lk+2][lr] = av.z; As[0][lk+3][lr] = av.w;
        Bs[0][lk+0][lr] = bv.x; Bs[0][lk+1][lr] = bv.y;
        Bs[0][lk+2][lr] = bv.z; Bs[0][lk+3][lr] = bv.w;
    }
    __syncthreads();

    unsigned long long acc[8][4];
    #pragma unroll
    for (int i = 0; i < 8; ++i)
        #pragma unroll
        for (int j = 0; j < 4; ++j) acc[i][j] = 0ull;

    int buf = 0;
    for (int k0 = 0; k0 < K; k0 += GBK) {
        bool hasNext = (k0 + GBK) < K;
        float4 an, bn;
        if (hasNext) {
            an = *(const float4*)(Aptr + k0 + GBK);
            bn = *(const float4*)(Wptr + k0 + GBK);
        }
        #pragma unroll
        for (int kk = 0; kk < GBK; ++kk) {
            ulonglong2 b01 = *(const ulonglong2*)&Bs[buf][kk][tx*8];
            ulonglong2 b23 = *(const ulonglong2*)&Bs[buf][kk][tx*8+4];
            float4 a0 = *(const float4*)&As[buf][kk][ty*8];
            float4 a1 = *(const float4*)&As[buf][kk][ty*8+4];
            float ar[8] = {a0.x,a0.y,a0.z,a0.w,a1.x,a1.y,a1.z,a1.w};
            #pragma unroll
            for (int i = 0; i < 8; ++i) {
                unsigned long long ad = pack2(ar[i], ar[i]);
                FFMA2(acc[i][0], ad, b01.x);
                FFMA2(acc[i][1], ad, b01.y);
                FFMA2(acc[i][2], ad, b23.x);
                FFMA2(acc[i][3], ad, b23.y);
            }
        }
        if (hasNext) {
            As[buf^1][lk+0][lr] = an.x; As[buf^1][lk+1][lr] = an.y;
            As[buf^1][lk+2][lr] = an.z; As[buf^1][lk+3][lr] = an.w;
            Bs[buf^1][lk+0][lr] = bn.x; Bs[buf^1][lk+1][lr] = bn.y;
            Bs[buf^1][lk+2][lr] = bn.z; Bs[buf^1][lk+3][lr] = bn.w;
        }
        __syncthreads();
        buf ^= 1;
    }

    #pragma unroll
    for (int i = 0; i < 8; ++i) {
        int m = m0 + ty*8 + i;
        #pragma unroll
        for (int j = 0; j < 4; ++j) {
            float2 p = unpack2(acc[i][j]);
            int n = n0 + tx*8 + j*2;
            if (EPI) {
                p.x += bias[n]   + resid[(long)m*N + n];
                p.y += bias[n+1] + resid[(long)m*N + n+1];
            }
            *(float2*)&Cout[(long)m*N + n] = p;
        }
    }
}

__global__ void __launch_bounds__(256) k_gemm_qkv(const float* __restrict__ x,
                                                 const float* __restrict__ Wq,
                                                 const float* __restrict__ Wk,
                                                 const float* __restrict__ Wv) {
    const float* W = blockIdx.z == 0 ? Wq : (blockIdx.z == 1 ? Wk : Wv);
    float* out = blockIdx.z == 0 ? g_q : (blockIdx.z == 1 ? g_k : g_v);
    gemm_body<false>(x, W, out, nullptr, nullptr, BT, CC, CC);
}

__global__ void __launch_bounds__(256) k_gemm_out(const float* __restrict__ Wo,
                                                 const float* __restrict__ bo,
                                                 const float* __restrict__ x) {
    gemm_body<true>(g_att, Wo, g_z, bo, x, BT, CC, CC);
}

// ---------- trig table ----------
__global__ void k_trig() {
    int gid = blockIdx.x * blockDim.x + threadIdx.x;   // t*32+i, 65536 total
    int t = gid >> 5, i = gid & 31;
    float e = (float)i * (1.0f / 32.0f);
    float inv = 1.0f / powf(10000.0f, e);
    float fr = (float)t * inv;
    g_cos[gid] = cosf(fr);
    g_sin[gid] = sinf(fr);
}

// ---------- RoPE + phi + mask (q,k), mask (v) ----------
__global__ void __launch_bounds__(256) k_rope(const int* __restrict__ mask) {
    int gid = blockIdx.x * blockDim.x + threadIdx.x;  // 4096*16*32
    int i = gid & 31;
    int bth = gid >> 5;
    int h = bth & 15;
    int bt = bth >> 4;
    int t = bt & (TT - 1);
    float mk = (float)mask[bt];
    float c = g_cos[t*32 + i], s = g_sin[t*32 + i];
    long off = (long)bt*CC + h*DD + i;

    float q1 = g_q[off], q2 = g_q[off+32];
    g_q[off]    = phi_f(q1*c - q2*s) * mk;
    g_q[off+32] = phi_f(q2*c + q1*s) * mk;

    float k1 = g_k[off], k2 = g_k[off+32];
    g_k[off]    = phi_f(k1*c - k2*s) * mk;
    g_k[off+32] = phi_f(k2*c + k1*s) * mk;

    float v1 = g_v[off], v2 = g_v[off+32];
    g_v[off]    = v1 * mk;
    g_v[off+32] = v2 * mk;
}

// ---------- forget gate: f = clip(sigmoid(x Wg^T + bg)); masked ----------
__global__ void __launch_bounds__(256) k_fgate(const float* __restrict__ x,
                                               const float* __restrict__ Wg,
                                               const float* __restrict__ bg,
                                               const int* __restrict__ mask) {
    __shared__ float xs[16][64];
    __shared__ float wsT[64][17];
    int tid = threadIdx.x;
    int row0 = blockIdx.x * 16;
    int lr = tid >> 4, lq = tid & 15;
    float acc = 0.0f;
    for (int k0 = 0; k0 < CC; k0 += 64) {
        float4 xv = *(const float4*)&x[(long)(row0+lr)*CC + k0 + lq*4];
        *(float4*)&xs[lr][lq*4] = xv;
        float4 wv = *(const float4*)&Wg[(long)lr*CC + k0 + lq*4];
        wsT[lq*4+0][lr] = wv.x; wsT[lq*4+1][lr] = wv.y;
        wsT[lq*4+2][lr] = wv.z; wsT[lq*4+3][lr] = wv.w;
        __syncthreads();
        #pragma unroll
        for (int kk = 0; kk < 64; ++kk) acc = fmaf(xs[lr][kk], wsT[kk][lq], acc);
        __syncthreads();
    }
    float zv = acc + bg[lq];
    float f = 1.0f / (1.0f + expf(-zv));
    f = fminf(fmaxf(f, 0.01f), 0.999f);
    float mk = (float)mask[row0 + lr];
    f = f * mk + (1.0f - mk);
    g_f[(long)(row0 + lr)*HH + lq] = f;
}

// ---------- denominator scan: one warp per (b,h) ----------
__global__ void __launch_bounds__(32) k_denom() {
    int bh = blockIdx.x;
    int b = bh >> 4, h = bh & 15;
    int lane = threadIdx.x;
    const float* K = g_k + (long)b*TT*CC + h*DD;
    const float* Q = g_q + (long)b*TT*CC + h*DD;
    const float* F = g_f + (long)b*TT*HH + h;
    float* Dst = g_den + (long)bh*TT;
    unsigned long long m2 = 0ull;
    for (int t0 = 0; t0 < TT; t0 += 8) {
        unsigned long long kk2[8], qq2[8];
        float ff[8];
        #pragma unroll
        for (int j = 0; j < 8; ++j) {
            const float* kp = K + (long)(t0+j)*CC;
            const float* qp = Q + (long)(t0+j)*CC;
            kk2[j] = pack2(kp[lane], kp[lane+32]);
            qq2[j] = pack2(qp[lane], qp[lane+32]);
            ff[j] = F[(long)(t0+j)*HH];
        }
        float part[8];
        #pragma unroll
        for (int j = 0; j < 8; ++j) {
            unsigned long long f2 = pack2(ff[j], ff[j]);
            unsigned long long t = mul2(m2, f2);
            // t += k
            asm("add.rn.f32x2 %0, %0, %1;" : "+l"(t) : "l"(kk2[j]));
            m2 = t;
            unsigned long long p2 = 0ull;
            FFMA2(p2, qq2[j], t);
            float2 pv = unpack2(p2);
            part[j] = pv.x + pv.y;
        }
        #pragma unroll
        for (int off = 16; off; off >>= 1)
            #pragma unroll
            for (int j = 0; j < 8; ++j)
                part[j] += __shfl_xor_sync(0xFFFFFFFFu, part[j], off);
        if (lane == 0) {
            #pragma unroll
            for (int j = 0; j < 8; ++j)
                Dst[t0 + j] = 1.0f / fmaxf(part[j], 1e-6f);
        }
    }
}

// ---------- main recurrent scan: 32 blocks x 256 threads ----------
#define SCH 16
__global__ void __launch_bounds__(256) k_scan() {
    int bh = blockIdx.x;
    int b = bh >> 4, h = bh & 15;
    int tid = threadIdx.x;
    int w = tid >> 5, l = tid & 31;
    int e = w*8 + (l >> 2);       // column 0..63
    int quarter = l & 3;
    int r0 = quarter * 16;        // row slice base

    __shared__ float ks[2][SCH][64], qs[2][SCH][64], vs[2][SCH][64];
    __shared__ float fs[2][SCH], ds[2][SCH];

    long base = (long)b*TT*CC + h*DD;
    const float* Kg = g_k + base;
    const float* Qg = g_q + base;
    const float* Vg = g_v + base;
    const float* Fg = g_f + (long)b*TT*HH + h;
    const float* Dg = g_den + (long)bh*TT;
    float* Og = g_att + base;

    unsigned long long S2[8];
    #pragma unroll
    for (int i = 0; i < 8; ++i) S2[i] = 0ull;

    int s_ld = tid >> 4, p_ld = tid & 15;
    long lo = (long)s_ld*CC + p_ld*4;
    float4 pk, pq, pv; float pf = 0.f, pd = 0.f;

    // preload chunk 0
    pk = *(const float4*)(Kg + lo);
    pq = *(const float4*)(Qg + lo);
    pv = *(const float4*)(Vg + lo);
    if (tid < SCH) pf = Fg[(long)tid*HH];
    else if (tid < 2*SCH) pd = Dg[tid - SCH];

    int buf = 0;
    const int NCH = TT / SCH;
    for (int c = 0; c < NCH; ++c) {
        *(float4*)&ks[buf][s_ld][p_ld*4] = pk;
        *(float4*)&qs[buf][s_ld][p_ld*4] = pq;
        *(float4*)&vs[buf][s_ld][p_ld*4] = pv;
        if (tid < SCH) fs[buf][tid] = pf;
        else if (tid < 2*SCH) ds[buf][tid - SCH] = pd;
        __syncthreads();

        if (c + 1 < NCH) {
            long off2 = (long)((c+1)*SCH)*CC + lo;
            pk = *(const float4*)(Kg + off2);
            pq = *(const float4*)(Qg + off2);
            pv = *(const float4*)(Vg + off2);
            if (tid < SCH) pf = Fg[(long)((c+1)*SCH + tid)*HH];
            else if (tid < 2*SCH) pd = Dg[(c+1)*SCH + (tid - SCH)];
        }

        #pragma unroll
        for (int s = 0; s < SCH; ++s) {
            float f = fs[buf][s];
            float v = vs[buf][s][e];
            float d = ds[buf][s];
            unsigned long long f2 = pack2(f, f);
            unsigned long long v2 = pack2(v, v);
            unsigned long long part2 = 0ull;
            #pragma unroll
            for (int i = 0; i < 8; ++i) {
                unsigned long long k2 = *(const unsigned long long*)&ks[buf][s][r0 + 2*i];
                unsigned long long q2 = *(const unsigned long long*)&qs[buf][s][r0 + 2*i];
                unsigned long long t = mul2(S2[i], f2);
                FFMA2(t, k2, v2);
                S2[i] = t;
                FFMA2(part2, q2, t);
            }
            float2 pp = unpack2(part2);
            float part = pp.x + pp.y;
            part += __shfl_xor_sync(0xFFFFFFFFu, part, 1);
            part += __shfl_xor_sync(0xFFFFFFFFu, part, 2);
            if (quarter == 0)
                Og[(long)(c*SCH + s)*CC + e] = part * d;
        }
        buf ^= 1;
    }
}

// ---------- LayerNorm ----------
__global__ void __launch_bounds__(256) k_ln(const float* __restrict__ lw,
                                            const float* __restrict__ lb,
                                            float* __restrict__ out) {
    int row = blockIdx.x, tid = threadIdx.x;
    int w = tid >> 5, l = tid & 31;
    const float4* y4 = (const float4*)(g_z + (long)row*CC);
    float4 a = y4[tid];
    float s1 = a.x + a.y + a.z + a.w;
    float s2 = a.x*a.x + a.y*a.y + a.z*a.z + a.w*a.w;
    #pragma unroll
    for (int off = 16; off; off >>= 1) {
        s1 += __shfl_xor_sync(0xFFFFFFFFu, s1, off);
        s2 += __shfl_xor_sync(0xFFFFFFFFu, s2, off);
    }
    __shared__ float r1[8], r2[8];
    if (l == 0) { r1[w] = s1; r2[w] = s2; }
    __syncthreads();
    if (w == 0) {
        s1 = (l < 8) ? r1[l] : 0.0f;
        s2 = (l < 8) ? r2[l] : 0.0f;
        #pragma unroll
        for (int off = 4; off; off >>= 1) {
            s1 += __shfl_xor_sync(0xFFFFFFFFu, s1, off);
            s2 += __shfl_xor_sync(0xFFFFFFFFu, s2, off);
        }
        if (l == 0) { r1[0] = s1; r2[0] = s2; }
    }
    __syncthreads();
    float mu = r1[0] * (1.0f / CC);
    float var = r2[0] * (1.0f / CC) - mu*mu;
    float rs = rsqrtf(var + 1e-5f);
    float4 wv = ((const float4*)lw)[tid];
    float4 bv = ((const float4*)lb)[tid];
    float4 o;
    o.x = (a.x - mu)*rs*wv.x + bv.x;
    o.y = (a.y - mu)*rs*wv.y + bv.y;
    o.z = (a.z - mu)*rs*wv.z + bv.z;
    o.w = (a.w - mu)*rs*wv.w + bv.w;
    ((float4*)(out + (long)row*CC))[tid] = o;
}

// ---------- launch ----------
extern "C" void kernel_launch(void* const* d_in, const int* in_sizes, int n_in,
                              void* d_out, int out_size) {
    (void)in_sizes; (void)n_in; (void)out_size;
    const float* x    = (const float*)d_in[0];
    const int*   mask = (const int*)  d_in[1];
    const float* Wq   = (const float*)d_in[2];
    const float* Wk   = (const float*)d_in[3];
    const float* Wv   = (const float*)d_in[4];
    const float* Wg   = (const float*)d_in[5];
    const float* bg   = (const float*)d_in[6];
    const float* Wo   = (const float*)d_in[7];
    const float* bo   = (const float*)d_in[8];
    const float* lw   = (const float*)d_in[9];
    const float* lb   = (const float*)d_in[10];
    float* out = (float*)d_out;

    k_trig<<<TT*32/256, 256>>>();
    k_gemm_qkv<<<dim3(CC/GBN, BT/GBM, 3), 256>>>(x, Wq, Wk, Wv);
    k_rope<<<BT*HH*32/256, 256>>>(mask);
    k_fgate<<<BT/16, 256>>>(x, Wg, bg, mask);
    k_denom<<<BB*HH, 32>>>();
    k_scan<<<BB*HH, 256>>>();
    k_gemm_out<<<dim3(CC/GBN, BT/GBM), 256>>>(Wo, bo, x);
    k_ln<<<BT, 256>>>(lw, lb, out);
}

// round 4
// speedup vs baseline: 1.2666x; 1.2666x over previous
#include <cuda_runtime.h>
#include <math.h>

#define BB 2
#define TT 2048
#define CC 1024
#define HH 16
#define DD 64
#define BT (BB*TT)

// ---------- scratch (__device__ globals; no runtime allocation) ----------
__device__ float g_q[BT*CC];
__device__ float g_k[BT*CC];
__device__ float g_v[BT*CC];
__device__ float g_att[BT*CC];
__device__ float g_z[BT*CC];
__device__ float g_f[BT*HH];
__device__ float g_den[BB*HH*TT];   // holds 1/denom
__device__ float g_cos[TT*32];
__device__ float g_sin[TT*32];

// ---------- packed f32x2 helpers ----------
__device__ __forceinline__ unsigned long long pack2(float lo, float hi) {
    unsigned long long r;
    asm("mov.b64 %0, {%1, %2};" : "=l"(r) : "f"(lo), "f"(hi));
    return r;
}
__device__ __forceinline__ float2 unpack2(unsigned long long v) {
    float2 f;
    asm("mov.b64 {%0, %1}, %2;" : "=f"(f.x), "=f"(f.y) : "l"(v));
    return f;
}
__device__ __forceinline__ unsigned long long mul2(unsigned long long a, unsigned long long b) {
    unsigned long long r;
    asm("mul.rn.f32x2 %0, %1, %2;" : "=l"(r) : "l"(a), "l"(b));
    return r;
}
#define FFMA2(acc, a, b) asm("fma.rn.f32x2 %0, %1, %2, %0;" : "+l"(acc) : "l"(a), "l"(b))

__device__ __forceinline__ float phi_f(float x) { return x > 0.0f ? x + 1.0f : expf(x); }

__device__ __forceinline__ unsigned f2tf(float f) {
    unsigned u;
    asm("cvt.rna.tf32.f32 %0, %1;" : "=r"(u) : "f"(f));
    return u;
}

// ---------- tf32 tensor-core GEMM: C[M,N] = A[M,K] * W[N,K]^T ----------
#define BM 128
#define BN 128
#define BK 16
#define SPAD 8

#define MMA_TF32(c, a, b) \
    asm volatile("mma.sync.aligned.m16n8k8.row.col.f32.tf32.tf32.f32 " \
                 "{%0,%1,%2,%3},{%4,%5,%6,%7},{%8,%9},{%0,%1,%2,%3};" \
                 : "+f"((c)[0]), "+f"((c)[1]), "+f"((c)[2]), "+f"((c)[3]) \
                 : "r"((a)[0]), "r"((a)[1]), "r"((a)[2]), "r"((a)[3]), \
                   "r"((b)[0]), "r"((b)[1]))

template<bool EPI>
__device__ __forceinline__ void gemm_tf32(const float* __restrict__ A,
                                          const float* __restrict__ W,
                                          float* __restrict__ Cout,
                                          const float* __restrict__ bias,
                                          const float* __restrict__ resid,
                                          int M, int N, int K)
{
    __shared__ unsigned As[2][BK][BM + SPAD];
    __shared__ unsigned Bs[2][BK][BN + SPAD];

    int tid = threadIdx.x;
    int m0 = blockIdx.y * BM;
    int n0 = blockIdx.x * BN;

    // producer indexing: one thread per row, 8 k-values (two float4)
    int r  = tid & 127;
    int kq = (tid >> 7) << 3;           // 0 or 8
    const float* Ap = A + (long)(m0 + r) * K + kq;
    const float* Wp = W + (long)(n0 + r) * K + kq;

    // consumer indexing
    int warp = tid >> 5;
    int lane = tid & 31;
    int g  = lane >> 2;                 // 0..7
    int tg = lane & 3;                  // 0..3
    int mbase = (warp >> 1) * 32;       // 4 warps over M
    int nbase = (warp & 1) * 64;        // 2 warps over N

    float c[2][8][4];
    #pragma unroll
    for (int mf = 0; mf < 2; ++mf)
        #pragma unroll
        for (int nf = 0; nf < 8; ++nf)
            #pragma unroll
            for (int j = 0; j < 4; ++j) c[mf][nf][j] = 0.0f;

    // stage tile 0
    {
        float4 a0 = *(const float4*)(Ap);
        float4 a1 = *(const float4*)(Ap + 4);
        float4 b0 = *(const float4*)(Wp);
        float4 b1 = *(const float4*)(Wp + 4);
        As[0][kq+0][r] = f2tf(a0.x); As[0][kq+1][r] = f2tf(a0.y);
        As[0][kq+2][r] = f2tf(a0.z); As[0][kq+3][r] = f2tf(a0.w);
        As[0][kq+4][r] = f2tf(a1.x); As[0][kq+5][r] = f2tf(a1.y);
        As[0][kq+6][r] = f2tf(a1.z); As[0][kq+7][r] = f2tf(a1.w);
        Bs[0][kq+0][r] = f2tf(b0.x); Bs[0][kq+1][r] = f2tf(b0.y);
        Bs[0][kq+2][r] = f2tf(b0.z); Bs[0][kq+3][r] = f2tf(b0.w);
        Bs[0][kq+4][r] = f2tf(b1.x); Bs[0][kq+5][r] = f2tf(b1.y);
        Bs[0][kq+6][r] = f2tf(b1.z); Bs[0][kq+7][r] = f2tf(b1.w);
    }
    __syncthreads();

    const int NT = K / BK;
    int buf = 0;
    for (int kt = 0; kt < NT; ++kt) {
        bool hasNext = (kt + 1) < NT;
        float4 a0v, a1v, b0v, b1v;
        if (hasNext) {
            const float* ap = Ap + (kt + 1) * BK;
            const float* wp = Wp + (kt + 1) * BK;
            a0v = *(const float4*)(ap);
            a1v = *(const float4*)(ap + 4);
            b0v = *(const float4*)(wp);
            b1v = *(const float4*)(wp + 4);
        }

        #pragma unroll
        for (int ks = 0; ks < 2; ++ks) {
            int kc = ks * 8;
            unsigned a[2][4], b[8][2];
            #pragma unroll
            for (int mf = 0; mf < 2; ++mf) {
                int m = mbase + mf*16 + g;
                a[mf][0] = As[buf][kc+tg  ][m];
                a[mf][1] = As[buf][kc+tg  ][m+8];
                a[mf][2] = As[buf][kc+tg+4][m];
                a[mf][3] = As[buf][kc+tg+4][m+8];
            }
            #pragma unroll
            for (int nf = 0; nf < 8; ++nf) {
                int n = nbase + nf*8 + g;
                b[nf][0] = Bs[buf][kc+tg  ][n];
                b[nf][1] = Bs[buf][kc+tg+4][n];
            }
            #pragma unroll
            for (int mf = 0; mf < 2; ++mf)
                #pragma unroll
                for (int nf = 0; nf < 8; ++nf)
                    MMA_TF32(c[mf][nf], a[mf], b[nf]);
        }

        if (hasNext) {
            int nb = buf ^ 1;
            As[nb][kq+0][r] = f2tf(a0v.x); As[nb][kq+1][r] = f2tf(a0v.y);
            As[nb][kq+2][r] = f2tf(a0v.z); As[nb][kq+3][r] = f2tf(a0v.w);
            As[nb][kq+4][r] = f2tf(a1v.x); As[nb][kq+5][r] = f2tf(a1v.y);
            As[nb][kq+6][r] = f2tf(a1v.z); As[nb][kq+7][r] = f2tf(a1v.w);
            Bs[nb][kq+0][r] = f2tf(b0v.x); Bs[nb][kq+1][r] = f2tf(b0v.y);
            Bs[nb][kq+2][r] = f2tf(b0v.z); Bs[nb][kq+3][r] = f2tf(b0v.w);
            Bs[nb][kq+4][r] = f2tf(b1v.x); Bs[nb][kq+5][r] = f2tf(b1v.y);
            Bs[nb][kq+6][r] = f2tf(b1v.z); Bs[nb][kq+7][r] = f2tf(b1v.w);
        }
        __syncthreads();
        buf ^= 1;
    }

    #pragma unroll
    for (int mf = 0; mf < 2; ++mf) {
        #pragma unroll
        for (int nf = 0; nf < 8; ++nf) {
            int row = m0 + mbase + mf*16 + g;
            int col = n0 + nbase + nf*8 + 2*tg;
            float2 v0 = make_float2(c[mf][nf][0], c[mf][nf][1]);
            float2 v1 = make_float2(c[mf][nf][2], c[mf][nf][3]);
            if (EPI) {
                float b0 = bias[col], b1 = bias[col+1];
                v0.x += b0 + resid[(long)row*N + col];
                v0.y += b1 + resid[(long)row*N + col + 1];
                v1.x += b0 + resid[(long)(row+8)*N + col];
                v1.y += b1 + resid[(long)(row+8)*N + col + 1];
            }
            *(float2*)&Cout[(long)row*N + col]     = v0;
            *(float2*)&Cout[(long)(row+8)*N + col] = v1;
        }
    }
}

__global__ void __launch_bounds__(256, 2) k_gemm_qkv(const float* __restrict__ x,
                                                     const float* __restrict__ Wq,
                                                     const float* __restrict__ Wk,
                                                     const float* __restrict__ Wv) {
    const float* W = blockIdx.z == 0 ? Wq : (blockIdx.z == 1 ? Wk : Wv);
    float* out = blockIdx.z == 0 ? g_q : (blockIdx.z == 1 ? g_k : g_v);
    gemm_tf32<false>(x, W, out, nullptr, nullptr, BT, CC, CC);
}

__global__ void __launch_bounds__(256, 2) k_gemm_out(const float* __restrict__ Wo,
                                                     const float* __restrict__ bo,
                                                     const float* __restrict__ x) {
    gemm_tf32<true>(g_att, Wo, g_z, bo, x, BT, CC, CC);
}

// ---------- trig table ----------
__global__ void k_trig() {
    int gid = blockIdx.x * blockDim.x + threadIdx.x;   // t*32+i, 65536 total
    int t = gid >> 5, i = gid & 31;
    float e = (float)i * (1.0f / 32.0f);
    float inv = 1.0f / powf(10000.0f, e);
    float fr = (float)t * inv;
    g_cos[gid] = cosf(fr);
    g_sin[gid] = sinf(fr);
}

// ---------- RoPE + phi + mask (q,k), mask (v) ----------
__global__ void __launch_bounds__(256) k_rope(const int* __restrict__ mask) {
    int gid = blockIdx.x * blockDim.x + threadIdx.x;  // 4096*16*32
    int i = gid & 31;
    int bth = gid >> 5;
    int h = bth & 15;
    int bt = bth >> 4;
    int t = bt & (TT - 1);
    float mk = (float)mask[bt];
    float c = g_cos[t*32 + i], s = g_sin[t*32 + i];
    long off = (long)bt*CC + h*DD + i;

    float q1 = g_q[off], q2 = g_q[off+32];
    g_q[off]    = phi_f(q1*c - q2*s) * mk;
    g_q[off+32] = phi_f(q2*c + q1*s) * mk;

    float k1 = g_k[off], k2 = g_k[off+32];
    g_k[off]    = phi_f(k1*c - k2*s) * mk;
    g_k[off+32] = phi_f(k2*c + k1*s) * mk;

    float v1 = g_v[off], v2 = g_v[off+32];
    g_v[off]    = v1 * mk;
    g_v[off+32] = v2 * mk;
}

// ---------- forget gate: f = clip(sigmoid(x Wg^T + bg)); masked ----------
__global__ void __launch_bounds__(256) k_fgate(const float* __restrict__ x,
                                               const float* __restrict__ Wg,
                                               const float* __restrict__ bg,
                                               const int* __restrict__ mask) {
    __shared__ float xs[16][64];
    __shared__ float wsT[64][17];
    int tid = threadIdx.x;
    int row0 = blockIdx.x * 16;
    int lr = tid >> 4, lq = tid & 15;
    float acc = 0.0f;
    for (int k0 = 0; k0 < CC; k0 += 64) {
        float4 xv = *(const float4*)&x[(long)(row0+lr)*CC + k0 + lq*4];
        *(float4*)&xs[lr][lq*4] = xv;
        float4 wv = *(const float4*)&Wg[(long)lr*CC + k0 + lq*4];
        wsT[lq*4+0][lr] = wv.x; wsT[lq*4+1][lr] = wv.y;
        wsT[lq*4+2][lr] = wv.z; wsT[lq*4+3][lr] = wv.w;
        __syncthreads();
        #pragma unroll
        for (int kk = 0; kk < 64; ++kk) acc = fmaf(xs[lr][kk], wsT[kk][lq], acc);
        __syncthreads();
    }
    float zv = acc + bg[lq];
    float f = 1.0f / (1.0f + expf(-zv));
    f = fminf(fmaxf(f, 0.01f), 0.999f);
    float mk = (float)mask[row0 + lr];
    f = f * mk + (1.0f - mk);
    g_f[(long)(row0 + lr)*HH + lq] = f;
}

// ---------- denominator scan: one warp per (b,h) ----------
__global__ void __launch_bounds__(32) k_denom() {
    int bh = blockIdx.x;
    int b = bh >> 4, h = bh & 15;
    int lane = threadIdx.x;
    const float* K = g_k + (long)b*TT*CC + h*DD;
    const float* Q = g_q + (long)b*TT*CC + h*DD;
    const float* F = g_f + (long)b*TT*HH + h;
    float* Dst = g_den + (long)bh*TT;
    unsigned long long m2 = 0ull;
    for (int t0 = 0; t0 < TT; t0 += 8) {
        unsigned long long kk2[8], qq2[8];
        float ff[8];
        #pragma unroll
        for (int j = 0; j < 8; ++j) {
            const float* kp = K + (long)(t0+j)*CC;
            const float* qp = Q + (long)(t0+j)*CC;
            kk2[j] = pack2(kp[lane], kp[lane+32]);
            qq2[j] = pack2(qp[lane], qp[lane+32]);
            ff[j] = F[(long)(t0+j)*HH];
        }
        float part[8];
        #pragma unroll
        for (int j = 0; j < 8; ++j) {
            unsigned long long f2 = pack2(ff[j], ff[j]);
            unsigned long long t = mul2(m2, f2);
            asm("add.rn.f32x2 %0, %0, %1;" : "+l"(t) : "l"(kk2[j]));
            m2 = t;
            unsigned long long p2 = 0ull;
            FFMA2(p2, qq2[j], t);
            float2 pv = unpack2(p2);
            part[j] = pv.x + pv.y;
        }
        #pragma unroll
        for (int off = 16; off; off >>= 1)
            #pragma unroll
            for (int j = 0; j < 8; ++j)
                part[j] += __shfl_xor_sync(0xFFFFFFFFu, part[j], off);
        if (lane == 0) {
            #pragma unroll
            for (int j = 0; j < 8; ++j)
                Dst[t0 + j] = 1.0f / fmaxf(part[j], 1e-6f);
        }
    }
}

// ---------- main recurrent scan: 32 blocks x 256 threads ----------
#define SCH 16
__global__ void __launch_bounds__(256) k_scan() {
    int bh = blockIdx.x;
    int b = bh >> 4, h = bh & 15;
    int tid = threadIdx.x;
    int w = tid >> 5, l = tid & 31;
    int e = w*8 + (l >> 2);       // column 0..63
    int quarter = l & 3;
    int r0 = quarter * 16;        // row slice base

    __shared__ float ks[2][SCH][64], qs[2][SCH][64], vs[2][SCH][64];
    __shared__ float fs[2][SCH], ds[2][SCH];

    long base = (long)b*TT*CC + h*DD;
    const float* Kg = g_k + base;
    const float* Qg = g_q + base;
    const float* Vg = g_v + base;
    const float* Fg = g_f + (long)b*TT*HH + h;
    const float* Dg = g_den + (long)bh*TT;
    float* Og = g_att + base;

    unsigned long long S2[8];
    #pragma unroll
    for (int i = 0; i < 8; ++i) S2[i] = 0ull;

    int s_ld = tid >> 4, p_ld = tid & 15;
    long lo = (long)s_ld*CC + p_ld*4;
    float4 pk, pq, pv; float pf = 0.f, pd = 0.f;

    // preload chunk 0
    pk = *(const float4*)(Kg + lo);
    pq = *(const float4*)(Qg + lo);
    pv = *(const float4*)(Vg + lo);
    if (tid < SCH) pf = Fg[(long)tid*HH];
    else if (tid < 2*SCH) pd = Dg[tid - SCH];

    int buf = 0;
    const int NCH = TT / SCH;
    for (int c = 0; c < NCH; ++c) {
        *(float4*)&ks[buf][s_ld][p_ld*4] = pk;
        *(float4*)&qs[buf][s_ld][p_ld*4] = pq;
        *(float4*)&vs[buf][s_ld][p_ld*4] = pv;
        if (tid < SCH) fs[buf][tid] = pf;
        else if (tid < 2*SCH) ds[buf][tid - SCH] = pd;
        __syncthreads();

        if (c + 1 < NCH) {
            long off2 = (long)((c+1)*SCH)*CC + lo;
            pk = *(const float4*)(Kg + off2);
            pq = *(const float4*)(Qg + off2);
            pv = *(const float4*)(Vg + off2);
            if (tid < SCH) pf = Fg[(long)((c+1)*SCH + tid)*HH];
            else if (tid < 2*SCH) pd = Dg[(c+1)*SCH + (tid - SCH)];
        }

        #pragma unroll
        for (int s = 0; s < SCH; ++s) {
            float f = fs[buf][s];
            float v = vs[buf][s][e];
            float d = ds[buf][s];
            unsigned long long f2 = pack2(f, f);
            unsigned long long v2 = pack2(v, v);
            unsigned long long part2 = 0ull;
            #pragma unroll
            for (int i = 0; i < 8; ++i) {
                unsigned long long k2 = *(const unsigned long long*)&ks[buf][s][r0 + 2*i];
                unsigned long long q2 = *(const unsigned long long*)&qs[buf][s][r0 + 2*i];
                unsigned long long t = mul2(S2[i], f2);
                FFMA2(t, k2, v2);
                S2[i] = t;
                FFMA2(part2, q2, t);
            }
            float2 pp = unpack2(part2);
            float part = pp.x + pp.y;
            part += __shfl_xor_sync(0xFFFFFFFFu, part, 1);
            part += __shfl_xor_sync(0xFFFFFFFFu, part, 2);
            if (quarter == 0)
                Og[(long)(c*SCH + s)*CC + e] = part * d;
        }
        buf ^= 1;
    }
}

// ---------- LayerNorm ----------
__global__ void __launch_bounds__(256) k_ln(const float* __restrict__ lw,
                                            const float* __restrict__ lb,
                                            float* __restrict__ out) {
    int row = blockIdx.x, tid = threadIdx.x;
    int w = tid >> 5, l = tid & 31;
    const float4* y4 = (const float4*)(g_z + (long)row*CC);
    float4 a = y4[tid];
    float s1 = a.x + a.y + a.z + a.w;
    float s2 = a.x*a.x + a.y*a.y + a.z*a.z + a.w*a.w;
    #pragma unroll
    for (int off = 16; off; off >>= 1) {
        s1 += __shfl_xor_sync(0xFFFFFFFFu, s1, off);
        s2 += __shfl_xor_sync(0xFFFFFFFFu, s2, off);
    }
    __shared__ float r1[8], r2[8];
    if (l == 0) { r1[w] = s1; r2[w] = s2; }
    __syncthreads();
    if (w == 0) {
        s1 = (l < 8) ? r1[l] : 0.0f;
        s2 = (l < 8) ? r2[l] : 0.0f;
        #pragma unroll
        for (int off = 4; off; off >>= 1) {
            s1 += __shfl_xor_sync(0xFFFFFFFFu, s1, off);
            s2 += __shfl_xor_sync(0xFFFFFFFFu, s2, off);
        }
        if (l == 0) { r1[0] = s1; r2[0] = s2; }
    }
    __syncthreads();
    float mu = r1[0] * (1.0f / CC);
    float var = r2[0] * (1.0f / CC) - mu*mu;
    float rs = rsqrtf(var + 1e-5f);
    float4 wv = ((const float4*)lw)[tid];
    float4 bv = ((const float4*)lb)[tid];
    float4 o;
    o.x = (a.x - mu)*rs*wv.x + bv.x;
    o.y = (a.y - mu)*rs*wv.y + bv.y;
    o.z = (a.z - mu)*rs*wv.z + bv.z;
    o.w = (a.w - mu)*rs*wv.w + bv.w;
    ((float4*)(out + (long)row*CC))[tid] = o;
}

// ---------- launch ----------
extern "C" void kernel_launch(void* const* d_in, const int* in_sizes, int n_in,
                              void* d_out, int out_size) {
    (void)in_sizes; (void)n_in; (void)out_size;
    const float* x    = (const float*)d_in[0];
    const int*   mask = (const int*)  d_in[1];
    const float* Wq   = (const float*)d_in[2];
    const float* Wk   = (const float*)d_in[3];
    const float* Wv   = (const float*)d_in[4];
    const float* Wg   = (const float*)d_in[5];
    const float* bg   = (const float*)d_in[6];
    const float* Wo   = (const float*)d_in[7];
    const float* bo   = (const float*)d_in[8];
    const float* lw   = (const float*)d_in[9];
    const float* lb   = (const float*)d_in[10];
    float* out = (float*)d_out;

    k_trig<<<TT*32/256, 256>>>();
    k_gemm_qkv<<<dim3(CC/BN, BT/BM, 3), 256>>>(x, Wq, Wk, Wv);
    k_rope<<<BT*HH*32/256, 256>>>(mask);
    k_fgate<<<BT/16, 256>>>(x, Wg, bg, mask);
    k_denom<<<BB*HH, 32>>>();
    k_scan<<<BB*HH, 256>>>();
    k_gemm_out<<<dim3(CC/BN, BT/BM), 256>>>(Wo, bo, x);
    k_ln<<<BT, 256>>>(lw, lb, out);
}

// round 6
// speedup vs baseline: 1.3688x; 1.0806x over previous
#include <cuda_runtime.h>
#include <cuda_bf16.h>
#include <math.h>

#define BB 2
#define TT 2048
#define CC 1024
#define HH 16
#define DD 64
#define BT (BB*TT)

// ---------- scratch (__device__ globals; no runtime allocation) ----------
__device__ float g_q[BT*CC];
__device__ float g_k[BT*CC];
__device__ float g_v[BT*CC];
__device__ float g_att[BT*CC];
__device__ float g_z[BT*CC];
__device__ float g_f[BT*HH];
__device__ float g_den[BB*HH*TT];   // holds 1/denom
__device__ float g_cos[TT*32];
__device__ float g_sin[TT*32];

// ---------- packed f32x2 helpers ----------
__device__ __forceinline__ unsigned long long pack2(float lo, float hi) {
    unsigned long long r;
    asm("mov.b64 %0, {%1, %2};" : "=l"(r) : "f"(lo), "f"(hi));
    return r;
}
__device__ __forceinline__ float2 unpack2(unsigned long long v) {
    float2 f;
    asm("mov.b64 {%0, %1}, %2;" : "=f"(f.x), "=f"(f.y) : "l"(v));
    return f;
}
__device__ __forceinline__ unsigned long long mul2(unsigned long long a, unsigned long long b) {
    unsigned long long r;
    asm("mul.rn.f32x2 %0, %1, %2;" : "=l"(r) : "l"(a), "l"(b));
    return r;
}
#define FFMA2(acc, a, b) asm("fma.rn.f32x2 %0, %1, %2, %0;" : "+l"(acc) : "l"(a), "l"(b))

__device__ __forceinline__ float phi_f(float x) { return x > 0.0f ? x + 1.0f : expf(x); }

// ---------- bf16 split helpers ----------
__device__ __forceinline__ void split2(float x0, float x1, unsigned &hi, unsigned &lo) {
    __nv_bfloat16 h0 = __float2bfloat16(x0);
    __nv_bfloat16 h1 = __float2bfloat16(x1);
    float r0 = x0 - __bfloat162float(h0);
    float r1 = x1 - __bfloat162float(h1);
    hi = (unsigned)__bfloat16_as_ushort(h0) | ((unsigned)__bfloat16_as_ushort(h1) << 16);
    lo = (unsigned)__bfloat16_as_ushort(__float2bfloat16(r0)) |
         ((unsigned)__bfloat16_as_ushort(__float2bfloat16(r1)) << 16);
}

// ---------- bf16x3 tensor-core GEMM: C[M,N] = A[M,K] * W[N,K]^T ----------
#define BM 128
#define BN 128
#define SROW 136   // 128 + 8 pad (words)

#define MMA_BF16(c, a, b) \
    asm volatile("mma.sync.aligned.m16n8k16.row.col.f32.bf16.bf16.f32 " \
                 "{%0,%1,%2,%3},{%4,%5,%6,%7},{%8,%9},{%0,%1,%2,%3};" \
                 : "+f"((c)[0]), "+f"((c)[1]), "+f"((c)[2]), "+f"((c)[3]) \
                 : "r"((a)[0]), "r"((a)[1]), "r"((a)[2]), "r"((a)[3]), \
                   "r"((b)[0]), "r"((b)[1]))

template<bool EPI>
__device__ __forceinline__ void gemm_bf3(const float* __restrict__ A,
                                         const float* __restrict__ W,
                                         float* __restrict__ Cout,
                                         const float* __restrict__ bias,
                                         const float* __restrict__ resid)
{
    // pair-words: [kpair 0..7][row 0..127]
    __shared__ unsigned AsH[2][8][SROW], AsL[2][8][SROW];
    __shared__ unsigned BsH[2][8][SROW], BsL[2][8][SROW];

    int tid = threadIdx.x;
    int m0 = blockIdx.y * BM;
    int n0 = blockIdx.x * BN;

    // producer: row = tid>>1, half = tid&1 covers k = half*8 .. half*8+7
    int row = tid >> 1;
    int half = tid & 1;
    const float* Ap = A + (long)(m0 + row) * CC + half * 8;
    const float* Wp = W + (long)(n0 + row) * CC + half * 8;
    int pb = half * 4;

    // consumer
    int warp = tid >> 5;
    int lane = tid & 31;
    int g  = lane >> 2;
    int tg = lane & 3;
    int mbase = (warp >> 1) * 32;
    int nbase = (warp & 1) * 64;

    float c[2][8][4];
    #pragma unroll
    for (int mf = 0; mf < 2; ++mf)
        #pragma unroll
        for (int nf = 0; nf < 8; ++nf)
            #pragma unroll
            for (int j = 0; j < 4; ++j) c[mf][nf][j] = 0.0f;

    // stage tile 0
    {
        float4 a0 = *(const float4*)(Ap);
        float4 a1 = *(const float4*)(Ap + 4);
        float4 b0 = *(const float4*)(Wp);
        float4 b1 = *(const float4*)(Wp + 4);
        unsigned h, l;
        split2(a0.x, a0.y, h, l); AsH[0][pb+0][row] = h; AsL[0][pb+0][row] = l;
        split2(a0.z, a0.w, h, l); AsH[0][pb+1][row] = h; AsL[0][pb+1][row] = l;
        split2(a1.x, a1.y, h, l); AsH[0][pb+2][row] = h; AsL[0][pb+2][row] = l;
        split2(a1.z, a1.w, h, l); AsH[0][pb+3][row] = h; AsL[0][pb+3][row] = l;
        split2(b0.x, b0.y, h, l); BsH[0][pb+0][row] = h; BsL[0][pb+0][row] = l;
        split2(b0.z, b0.w, h, l); BsH[0][pb+1][row] = h; BsL[0][pb+1][row] = l;
        split2(b1.x, b1.y, h, l); BsH[0][pb+2][row] = h; BsL[0][pb+2][row] = l;
        split2(b1.z, b1.w, h, l); BsH[0][pb+3][row] = h; BsL[0][pb+3][row] = l;
    }
    __syncthreads();

    const int NT = CC / 16;   // 64
    int buf = 0;
    for (int kt = 0; kt < NT; ++kt) {
        bool hasNext = (kt + 1) < NT;
        float4 a0v, a1v, b0v, b1v;
        if (hasNext) {
            const float* ap = Ap + (kt + 1) * 16;
            const float* wp = Wp + (kt + 1) * 16;
            a0v = *(const float4*)(ap);
            a1v = *(const float4*)(ap + 4);
            b0v = *(const float4*)(wp);
            b1v = *(const float4*)(wp + 4);
        }

        // fragments: a = 16 regs (hi+lo), b per-nf
        unsigned aH[2][4], aL[2][4];
        #pragma unroll
        for (int mf = 0; mf < 2; ++mf) {
            int m = mbase + mf*16 + g;
            aH[mf][0] = AsH[buf][tg  ][m];   aH[mf][1] = AsH[buf][tg  ][m+8];
            aH[mf][2] = AsH[buf][tg+4][m];   aH[mf][3] = AsH[buf][tg+4][m+8];
            aL[mf][0] = AsL[buf][tg  ][m];   aL[mf][1] = AsL[buf][tg  ][m+8];
            aL[mf][2] = AsL[buf][tg+4][m];   aL[mf][3] = AsL[buf][tg+4][m+8];
        }
        #pragma unroll
        for (int nf = 0; nf < 8; ++nf) {
            int n = nbase + nf*8 + g;
            unsigned bH[2], bL[2];
            bH[0] = BsH[buf][tg  ][n];  bH[1] = BsH[buf][tg+4][n];
            bL[0] = BsL[buf][tg  ][n];  bL[1] = BsL[buf][tg+4][n];
            #pragma unroll
            for (int mf = 0; mf < 2; ++mf) {
                MMA_BF16(c[mf][nf], aH[mf], bH);
                MMA_BF16(c[mf][nf], aH[mf], bL);
                MMA_BF16(c[mf][nf], aL[mf], bH);
            }
        }

        if (hasNext) {
            int nb = buf ^ 1;
            unsigned h, l;
            split2(a0v.x, a0v.y, h, l); AsH[nb][pb+0][row] = h; AsL[nb][pb+0][row] = l;
            split2(a0v.z, a0v.w, h, l); AsH[nb][pb+1][row] = h; AsL[nb][pb+1][row] = l;
            split2(a1v.x, a1v.y, h, l); AsH[nb][pb+2][row] = h; AsL[nb][pb+2][row] = l;
            split2(a1v.z, a1v.w, h, l); AsH[nb][pb+3][row] = h; AsL[nb][pb+3][row] = l;
            split2(b0v.x, b0v.y, h, l); BsH[nb][pb+0][row] = h; BsL[nb][pb+0][row] = l;
            split2(b0v.z, b0v.w, h, l); BsH[nb][pb+1][row] = h; BsL[nb][pb+1][row] = l;
            split2(b1v.x, b1v.y, h, l); BsH[nb][pb+2][row] = h; BsL[nb][pb+2][row] = l;
            split2(b1v.z, b1v.w, h, l); BsH[nb][pb+3][row] = h; BsL[nb][pb+3][row] = l;
        }
        __syncthreads();
        buf ^= 1;
    }

    #pragma unroll
    for (int mf = 0; mf < 2; ++mf) {
        #pragma unroll
        for (int nf = 0; nf < 8; ++nf) {
            int r = m0 + mbase + mf*16 + g;
            int col = n0 + nbase + nf*8 + 2*tg;
            float2 v0 = make_float2(c[mf][nf][0], c[mf][nf][1]);
            float2 v1 = make_float2(c[mf][nf][2], c[mf][nf][3]);
            if (EPI) {
                float b0 = bias[col], b1 = bias[col+1];
                v0.x += b0 + resid[(long)r*CC + col];
                v0.y += b1 + resid[(long)r*CC + col + 1];
                v1.x += b0 + resid[(long)(r+8)*CC + col];
                v1.y += b1 + resid[(long)(r+8)*CC + col + 1];
            }
            *(float2*)&Cout[(long)r*CC + col]     = v0;
            *(float2*)&Cout[(long)(r+8)*CC + col] = v1;
        }
    }
}

__global__ void __launch_bounds__(256, 2) k_gemm_qkv(const float* __restrict__ x,
                                                     const float* __restrict__ Wq,
                                                     const float* __restrict__ Wk,
                                                     const float* __restrict__ Wv) {
    const float* W = blockIdx.z == 0 ? Wq : (blockIdx.z == 1 ? Wk : Wv);
    float* out = blockIdx.z == 0 ? g_q : (blockIdx.z == 1 ? g_k : g_v);
    gemm_bf3<false>(x, W, out, nullptr, nullptr);
}

__global__ void __launch_bounds__(256, 2) k_gemm_out(const float* __restrict__ Wo,
                                                     const float* __restrict__ bo,
                                                     const float* __restrict__ x) {
    gemm_bf3<true>(g_att, Wo, g_z, bo, x);
}

// ---------- trig table (split into two launches for ncu slot alignment) ----------
__global__ void k_trig(int base) {
    int gid = base + blockIdx.x * blockDim.x + threadIdx.x;   // t*32+i
    int t = gid >> 5, i = gid & 31;
    float e = (float)i * (1.0f / 32.0f);
    float inv = 1.0f / powf(10000.0f, e);
    float fr = (float)t * inv;
    g_cos[gid] = cosf(fr);
    g_sin[gid] = sinf(fr);
}

// ---------- RoPE + phi + mask (q,k), mask (v) ----------
__global__ void __launch_bounds__(256) k_rope(const int* __restrict__ mask) {
    int gid = blockIdx.x * blockDim.x + threadIdx.x;  // 4096*16*32
    int i = gid & 31;
    int bth = gid >> 5;
    int h = bth & 15;
    int bt = bth >> 4;
    int t = bt & (TT - 1);
    float mk = (float)mask[bt];
    float c = g_cos[t*32 + i], s = g_sin[t*32 + i];
    long off = (long)bt*CC + h*DD + i;

    float q1 = g_q[off], q2 = g_q[off+32];
    g_q[off]    = phi_f(q1*c - q2*s) * mk;
    g_q[off+32] = phi_f(q2*c + q1*s) * mk;

    float k1 = g_k[off], k2 = g_k[off+32];
    g_k[off]    = phi_f(k1*c - k2*s) * mk;
    g_k[off+32] = phi_f(k2*c + k1*s) * mk;

    float v1 = g_v[off], v2 = g_v[off+32];
    g_v[off]    = v1 * mk;
    g_v[off+32] = v2 * mk;
}

// ---------- forget gate ----------
__global__ void __launch_bounds__(256) k_fgate(const float* __restrict__ x,
                                               const float* __restrict__ Wg,
                                               const float* __restrict__ bg,
                                               const int* __restrict__ mask) {
    __shared__ float xs[16][64];
    __shared__ float wsT[64][17];
    int tid = threadIdx.x;
    int row0 = blockIdx.x * 16;
    int lr = tid >> 4, lq = tid & 15;
    float acc = 0.0f;
    for (int k0 = 0; k0 < CC; k0 += 64) {
        float4 xv = *(const float4*)&x[(long)(row0+lr)*CC + k0 + lq*4];
        *(float4*)&xs[lr][lq*4] = xv;
        float4 wv = *(const float4*)&Wg[(long)lr*CC + k0 + lq*4];
        wsT[lq*4+0][lr] = wv.x; wsT[lq*4+1][lr] = wv.y;
        wsT[lq*4+2][lr] = wv.z; wsT[lq*4+3][lr] = wv.w;
        __syncthreads();
        #pragma unroll
        for (int kk = 0; kk < 64; ++kk) acc = fmaf(xs[lr][kk], wsT[kk][lq], acc);
        __syncthreads();
    }
    float zv = acc + bg[lq];
    float f = 1.0f / (1.0f + expf(-zv));
    f = fminf(fmaxf(f, 0.01f), 0.999f);
    float mk = (float)mask[row0 + lr];
    f = f * mk + (1.0f - mk);
    g_f[(long)(row0 + lr)*HH + lq] = f;
}

// ---------- denominator scan: one warp per (b,h) ----------
__global__ void __launch_bounds__(32) k_denom() {
    int bh = blockIdx.x;
    int b = bh >> 4, h = bh & 15;
    int lane = threadIdx.x;
    const float* K = g_k + (long)b*TT*CC + h*DD;
    const float* Q = g_q + (long)b*TT*CC + h*DD;
    const float* F = g_f + (long)b*TT*HH + h;
    float* Dst = g_den + (long)bh*TT;
    unsigned long long m2 = 0ull;
    for (int t0 = 0; t0 < TT; t0 += 8) {
        unsigned long long kk2[8], qq2[8];
        float ff[8];
        #pragma unroll
        for (int j = 0; j < 8; ++j) {
            const float* kp = K + (long)(t0+j)*CC;
            const float* qp = Q + (long)(t0+j)*CC;
            kk2[j] = pack2(kp[lane], kp[lane+32]);
            qq2[j] = pack2(qp[lane], qp[lane+32]);
            ff[j] = F[(long)(t0+j)*HH];
        }
        float part[8];
        #pragma unroll
        for (int j = 0; j < 8; ++j) {
            unsigned long long f2 = pack2(ff[j], ff[j]);
            unsigned long long t = mul2(m2, f2);
            asm("add.rn.f32x2 %0, %0, %1;" : "+l"(t) : "l"(kk2[j]));
            m2 = t;
            unsigned long long p2 = 0ull;
            FFMA2(p2, qq2[j], t);
            float2 pv = unpack2(p2);
            part[j] = pv.x + pv.y;
        }
        #pragma unroll
        for (int off = 16; off; off >>= 1)
            #pragma unroll
            for (int j = 0; j < 8; ++j)
                part[j] += __shfl_xor_sync(0xFFFFFFFFu, part[j], off);
        if (lane == 0) {
            #pragma unroll
            for (int j = 0; j < 8; ++j)
                Dst[t0 + j] = 1.0f / fmaxf(part[j], 1e-6f);
        }
    }
}

// ---------- main recurrent scan: 32 blocks x 256 threads ----------
#define SCH 16
__global__ void __launch_bounds__(256) k_scan() {
    int bh = blockIdx.x;
    int b = bh >> 4, h = bh & 15;
    int tid = threadIdx.x;
    int w = tid >> 5, l = tid & 31;
    int e = w*8 + (l >> 2);       // column 0..63
    int quarter = l & 3;
    int r0 = quarter * 16;        // row slice base

    __shared__ float ks[2][SCH][64], qs[2][SCH][64], vs[2][SCH][64];
    __shared__ float fs[2][SCH], ds[2][SCH];

    long base = (long)b*TT*CC + h*DD;
    const float* Kg = g_k + base;
    const float* Qg = g_q + base;
    const float* Vg = g_v + base;
    const float* Fg = g_f + (long)b*TT*HH + h;
    const float* Dg = g_den + (long)bh*TT;
    float* Og = g_att + base;

    unsigned long long S2[8];
    #pragma unroll
    for (int i = 0; i < 8; ++i) S2[i] = 0ull;

    int s_ld = tid >> 4, p_ld = tid & 15;
    long lo = (long)s_ld*CC + p_ld*4;
    float4 pk, pq, pv; float pf = 0.f, pd = 0.f;

    pk = *(const float4*)(Kg + lo);
    pq = *(const float4*)(Qg + lo);
    pv = *(const float4*)(Vg + lo);
    if (tid < SCH) pf = Fg[(long)tid*HH];
    else if (tid < 2*SCH) pd = Dg[tid - SCH];

    int buf = 0;
    const int NCH = TT / SCH;
    for (int c = 0; c < NCH; ++c) {
        *(float4*)&ks[buf][s_ld][p_ld*4] = pk;
        *(float4*)&qs[buf][s_ld][p_ld*4] = pq;
        *(float4*)&vs[buf][s_ld][p_ld*4] = pv;
        if (tid < SCH) fs[buf][tid] = pf;
        else if (tid < 2*SCH) ds[buf][tid - SCH] = pd;
        __syncthreads();

        if (c + 1 < NCH) {
            long off2 = (long)((c+1)*SCH)*CC + lo;
            pk = *(const float4*)(Kg + off2);
            pq = *(const float4*)(Qg + off2);
            pv = *(const float4*)(Vg + off2);
            if (tid < SCH) pf = Fg[(long)((c+1)*SCH + tid)*HH];
            else if (tid < 2*SCH) pd = Dg[(c+1)*SCH + (tid - SCH)];
        }

        #pragma unroll
        for (int s = 0; s < SCH; ++s) {
            float f = fs[buf][s];
            float v = vs[buf][s][e];
            float d = ds[buf][s];
            unsigned long long f2 = pack2(f, f);
            unsigned long long v2 = pack2(v, v);
            unsigned long long part2 = 0ull;
            #pragma unroll
            for (int i = 0; i < 8; ++i) {
                unsigned long long k2 = *(const unsigned long long*)&ks[buf][s][r0 + 2*i];
                unsigned long long q2 = *(const unsigned long long*)&qs[buf][s][r0 + 2*i];
                unsigned long long t = mul2(S2[i], f2);
                FFMA2(t, k2, v2);
                S2[i] = t;
                FFMA2(part2, q2, t);
            }
            float2 pp = unpack2(part2);
            float part = pp.x + pp.y;
            part += __shfl_xor_sync(0xFFFFFFFFu, part, 1);
            part += __shfl_xor_sync(0xFFFFFFFFu, part, 2);
            if (quarter == 0)
                Og[(long)(c*SCH + s)*CC + e] = part * d;
        }
        buf ^= 1;
    }
}

// ---------- LayerNorm ----------
__global__ void __launch_bounds__(256) k_ln(const float* __restrict__ lw,
                                            const float* __restrict__ lb,
                                            float* __restrict__ out) {
    int row = blockIdx.x, tid = threadIdx.x;
    int w = tid >> 5, l = tid & 31;
    const float4* y4 = (const float4*)(g_z + (long)row*CC);
    float4 a = y4[tid];
    float s1 = a.x + a.y + a.z + a.w;
    float s2 = a.x*a.x + a.y*a.y + a.z*a.z + a.w*a.w;
    #pragma unroll
    for (int off = 16; off; off >>= 1) {
        s1 += __shfl_xor_sync(0xFFFFFFFFu, s1, off);
        s2 += __shfl_xor_sync(0xFFFFFFFFu, s2, off);
    }
    __shared__ float r1[8], r2[8];
    if (l == 0) { r1[w] = s1; r2[w] = s2; }
    __syncthreads();
    if (w == 0) {
        s1 = (l < 8) ? r1[l] : 0.0f;
        s2 = (l < 8) ? r2[l] : 0.0f;
        #pragma unroll
        for (int off = 4; off; off >>= 1) {
            s1 += __shfl_xor_sync(0xFFFFFFFFu, s1, off);
            s2 += __shfl_xor_sync(0xFFFFFFFFu, s2, off);
        }
        if (l == 0) { r1[0] = s1; r2[0] = s2; }
    }
    __syncthreads();
    float mu = r1[0] * (1.0f / CC);
    float var = r2[0] * (1.0f / CC) - mu*mu;
    float rs = rsqrtf(var + 1e-5f);
    float4 wv = ((const float4*)lw)[tid];
    float4 bv = ((const float4*)lb)[tid];
    float4 o;
    o.x = (a.x - mu)*rs*wv.x + bv.x;
    o.y = (a.y - mu)*rs*wv.y + bv.y;
    o.z = (a.z - mu)*rs*wv.z + bv.z;
    o.w = (a.w - mu)*rs*wv.w + bv.w;
    ((float4*)(out + (long)row*CC))[tid] = o;
}

// ---------- launch ----------
extern "C" void kernel_launch(void* const* d_in, const int* in_sizes, int n_in,
                              void* d_out, int out_size) {
    (void)in_sizes; (void)n_in; (void)out_size;
    const float* x    = (const float*)d_in[0];
    const int*   mask = (const int*)  d_in[1];
    const float* Wq   = (const float*)d_in[2];
    const float* Wk   = (const float*)d_in[3];
    const float* Wv   = (const float*)d_in[4];
    const float* Wg   = (const float*)d_in[5];
    const float* bg   = (const float*)d_in[6];
    const float* Wo   = (const float*)d_in[7];
    const float* bo   = (const float*)d_in[8];
    const float* lw   = (const float*)d_in[9];
    const float* lb   = (const float*)d_in[10];
    float* out = (float*)d_out;

    k_trig<<<128, 256>>>(0);            // launch 1
    k_trig<<<128, 256>>>(32768);        // launch 2
    k_fgate<<<BT/16, 256>>>(x, Wg, bg, mask);                    // launch 3
    k_gemm_qkv<<<dim3(CC/BN, BT/BM, 3), 256>>>(x, Wq, Wk, Wv);   // launch 4 (ncu slot)
    k_rope<<<BT*HH*32/256, 256>>>(mask);                         // launch 5
    k_denom<<<BB*HH, 32>>>();                                    // launch 6
    k_scan<<<BB*HH, 256>>>();                                    // launch 7
    k_gemm_out<<<dim3(CC/BN, BT/BM), 256>>>(Wo, bo, x);          // launch 8
    k_ln<<<BT, 256>>>(lw, lb, out);                              // launch 9
}

// round 7
// speedup vs baseline: 1.9444x; 1.4206x over previous
#include <cuda_runtime.h>
#include <cuda_bf16.h>
#include <math.h>

#define BB 2
#define TT 2048
#define CC 1024
#define HH 16
#define DD 64
#define BT (BB*TT)

// ---------- scratch (__device__ globals; no runtime allocation) ----------
__device__ float g_q[BT*CC];
__device__ float g_k[BT*CC];
__device__ float g_v[BT*CC];
__device__ float g_att[BT*CC];
__device__ float g_z[BT*CC];
__device__ float g_f[BT*HH];
__device__ float g_den[BB*HH*TT];
__device__ float g_cos[TT*32];
__device__ float g_sin[TT*32];

// bf16 hi/lo split operands
__device__ __nv_bfloat16 g_xh[BT*CC], g_xl[BT*CC];      // x
__device__ __nv_bfloat16 g_ath[BT*CC], g_atl[BT*CC];    // att
__device__ __nv_bfloat16 g_wh[4][CC*CC], g_wl[4][CC*CC];// Wq,Wk,Wv,Wo

// ---------- packed f32x2 helpers ----------
__device__ __forceinline__ unsigned long long pack2(float lo, float hi) {
    unsigned long long r;
    asm("mov.b64 %0, {%1, %2};" : "=l"(r) : "f"(lo), "f"(hi));
    return r;
}
__device__ __forceinline__ float2 unpack2(unsigned long long v) {
    float2 f;
    asm("mov.b64 {%0, %1}, %2;" : "=f"(f.x), "=f"(f.y) : "l"(v));
    return f;
}
__device__ __forceinline__ unsigned long long mul2(unsigned long long a, unsigned long long b) {
    unsigned long long r;
    asm("mul.rn.f32x2 %0, %1, %2;" : "=l"(r) : "l"(a), "l"(b));
    return r;
}
#define FFMA2(acc, a, b) asm("fma.rn.f32x2 %0, %1, %2, %0;" : "+l"(acc) : "l"(a), "l"(b))

__device__ __forceinline__ float phi_f(float x) { return x > 0.0f ? x + 1.0f : expf(x); }

__device__ __forceinline__ unsigned smem_u32(const void* p) {
    unsigned a;
    asm("{ .reg .u64 t; cvta.to.shared.u64 t, %1; cvt.u32.u64 %0, t; }" : "=r"(a) : "l"(p));
    return a;
}

// ---------- cp.async / ldmatrix / mma ----------
#define CP_ASYNC16(dst, src) \
    asm volatile("cp.async.cg.shared.global [%0], [%1], 16;" :: "r"(dst), "l"(src))
#define CP_COMMIT() asm volatile("cp.async.commit_group;")
#define CP_WAIT1()  asm volatile("cp.async.wait_group 1;")

#define LDSM4(r, addr) \
    asm volatile("ldmatrix.sync.aligned.m8n8.x4.shared.b16 {%0,%1,%2,%3}, [%4];" \
        : "=r"((r)[0]), "=r"((r)[1]), "=r"((r)[2]), "=r"((r)[3]) : "r"(addr))

#define MMA_BF16(c, a, b) \
    asm volatile("mma.sync.aligned.m16n8k16.row.col.f32.bf16.bf16.f32 " \
                 "{%0,%1,%2,%3},{%4,%5,%6,%7},{%8,%9},{%0,%1,%2,%3};" \
                 : "+f"((c)[0]), "+f"((c)[1]), "+f"((c)[2]), "+f"((c)[3]) \
                 : "r"((a)[0]), "r"((a)[1]), "r"((a)[2]), "r"((a)[3]), \
                   "r"((b)[0]), "r"((b)[1]))

// ---------- fp32 -> bf16 hi/lo conversion ----------
__global__ void __launch_bounds__(256) k_cvt(const float* __restrict__ s,
                                             __nv_bfloat16* __restrict__ dh,
                                             __nv_bfloat16* __restrict__ dl, int n4) {
    int id = blockIdx.x * blockDim.x + threadIdx.x;
    if (id >= n4) return;
    float4 v = ((const float4*)s)[id];
    float vv[4] = {v.x, v.y, v.z, v.w};
    unsigned short h[4], l[4];
    #pragma unroll
    for (int i = 0; i < 4; ++i) {
        __nv_bfloat16 hb = __float2bfloat16(vv[i]);
        h[i] = __bfloat16_as_ushort(hb);
        l[i] = __bfloat16_as_ushort(__float2bfloat16(vv[i] - __bfloat162float(hb)));
    }
    *(uint2*)(dh + 4*id) = make_uint2(h[0] | ((unsigned)h[1]<<16), h[2] | ((unsigned)h[3]<<16));
    *(uint2*)(dl + 4*id) = make_uint2(l[0] | ((unsigned)l[1]<<16), l[2] | ((unsigned)l[3]<<16));
}

__global__ void __launch_bounds__(256) k_cvtW(const float* __restrict__ Wq,
                                              const float* __restrict__ Wk,
                                              const float* __restrict__ Wv,
                                              const float* __restrict__ Wo) {
    int id = blockIdx.x * blockDim.x + threadIdx.x;   // 4 * 262144
    int seg = id >> 18;
    int off = id & 0x3FFFF;
    const float* src = seg == 0 ? Wq : seg == 1 ? Wk : seg == 2 ? Wv : Wo;
    float4 v = ((const float4*)src)[off];
    float vv[4] = {v.x, v.y, v.z, v.w};
    unsigned short h[4], l[4];
    #pragma unroll
    for (int i = 0; i < 4; ++i) {
        __nv_bfloat16 hb = __float2bfloat16(vv[i]);
        h[i] = __bfloat16_as_ushort(hb);
        l[i] = __bfloat16_as_ushort(__float2bfloat16(vv[i] - __bfloat162float(hb)));
    }
    *(uint2*)(g_wh[seg] + 4*off) = make_uint2(h[0] | ((unsigned)h[1]<<16), h[2] | ((unsigned)h[3]<<16));
    *(uint2*)(g_wl[seg] + 4*off) = make_uint2(l[0] | ((unsigned)l[1]<<16), l[2] | ((unsigned)l[3]<<16));
}

// ---------- bf16x3 GEMM, cp.async + ldmatrix: C[M,N] = A[M,K] * W[N,K]^T ----------
// smem tile: 128 rows x 16 bf16 (32B/row); 16B chunk swizzled by row bit2.
template<bool EPI>
__device__ __forceinline__ void gemm_core(const __nv_bfloat16* __restrict__ Agh,
                                          const __nv_bfloat16* __restrict__ Agl,
                                          const __nv_bfloat16* __restrict__ Bgh,
                                          const __nv_bfloat16* __restrict__ Bgl,
                                          float* __restrict__ Cout,
                                          const float* __restrict__ bias,
                                          const float* __restrict__ resid)
{
    __shared__ __align__(16) char smbuf[2][4][4096];  // [stage][Ah,Al,Bh,Bl][128*32B]

    int tid = threadIdx.x;
    int m0 = blockIdx.y * 128;
    int n0 = blockIdx.x * 128;

    // producer
    int prow = tid >> 1;
    int phalf = tid & 1;
    const __nv_bfloat16* srcs[4];
    srcs[0] = Agh + (long)(m0 + prow) * CC + phalf * 8;
    srcs[1] = Agl + (long)(m0 + prow) * CC + phalf * 8;
    srcs[2] = Bgh + (long)(n0 + prow) * CC + phalf * 8;
    srcs[3] = Bgl + (long)(n0 + prow) * CC + phalf * 8;
    unsigned dsto = prow * 32 + ((phalf ^ ((prow >> 2) & 1)) << 4);
    unsigned sdst[2][4];
    unsigned tb[2][4];
    #pragma unroll
    for (int st = 0; st < 2; ++st)
        #pragma unroll
        for (int t = 0; t < 4; ++t) {
            tb[st][t] = smem_u32(&smbuf[st][t][0]);
            sdst[st][t] = tb[st][t] + dsto;
        }

    // consumer
    int warp = tid >> 5, lane = tid & 31;
    int g = lane >> 2, tg = lane & 3;
    int mbase = (warp >> 1) * 32;
    int nbase = (warp & 1) * 64;
    int lrow = lane & 15, lhi = lane >> 4;
    unsigned loff = lrow * 32 + ((lhi ^ ((lrow >> 2) & 1)) << 4);

    float c[2][8][4];
    #pragma unroll
    for (int mf = 0; mf < 2; ++mf)
        #pragma unroll
        for (int nf = 0; nf < 8; ++nf)
            #pragma unroll
            for (int j = 0; j < 4; ++j) c[mf][nf][j] = 0.0f;

    auto issue = [&](int kt, int st) {
        #pragma unroll
        for (int t = 0; t < 4; ++t)
            CP_ASYNC16(sdst[st][t], srcs[t] + kt * 16);
        CP_COMMIT();
    };

    const int NT = CC / 16;   // 64
    issue(0, 0);
    issue(1, 1);

    for (int kt = 0; kt < NT; ++kt) {
        int st = kt & 1;
        CP_WAIT1();
        __syncthreads();

        unsigned aH[2][4], aL[2][4];
        #pragma unroll
        for (int mf = 0; mf < 2; ++mf) {
            LDSM4(aH[mf], tb[st][0] + (unsigned)(mbase + mf*16) * 32 + loff);
            LDSM4(aL[mf], tb[st][1] + (unsigned)(mbase + mf*16) * 32 + loff);
        }
        #pragma unroll
        for (int nfp = 0; nfp < 4; ++nfp) {
            unsigned bh4[4], bl4[4];
            LDSM4(bh4, tb[st][2] + (unsigned)(nbase + nfp*16) * 32 + loff);
            LDSM4(bl4, tb[st][3] + (unsigned)(nbase + nfp*16) * 32 + loff);
            unsigned bh0[2] = {bh4[0], bh4[2]}, bh1[2] = {bh4[1], bh4[3]};
            unsigned bl0[2] = {bl4[0], bl4[2]}, bl1[2] = {bl4[1], bl4[3]};
            #pragma unroll
            for (int mf = 0; mf < 2; ++mf) {
                MMA_BF16(c[mf][nfp*2],   aH[mf], bh0);
                MMA_BF16(c[mf][nfp*2],   aH[mf], bl0);
                MMA_BF16(c[mf][nfp*2],   aL[mf], bh0);
                MMA_BF16(c[mf][nfp*2+1], aH[mf], bh1);
                MMA_BF16(c[mf][nfp*2+1], aH[mf], bl1);
                MMA_BF16(c[mf][nfp*2+1], aL[mf], bh1);
            }
        }

        __syncthreads();
        if (kt + 2 < NT) issue(kt + 2, st);
    }

    #pragma unroll
    for (int mf = 0; mf < 2; ++mf) {
        #pragma unroll
        for (int nf = 0; nf < 8; ++nf) {
            int r = m0 + mbase + mf*16 + g;
            int col = n0 + nbase + nf*8 + 2*tg;
            float2 v0 = make_float2(c[mf][nf][0], c[mf][nf][1]);
            float2 v1 = make_float2(c[mf][nf][2], c[mf][nf][3]);
            if (EPI) {
                float b0 = bias[col], b1 = bias[col+1];
                v0.x += b0 + resid[(long)r*CC + col];
                v0.y += b1 + resid[(long)r*CC + col + 1];
                v1.x += b0 + resid[(long)(r+8)*CC + col];
                v1.y += b1 + resid[(long)(r+8)*CC + col + 1];
            }
            *(float2*)&Cout[(long)r*CC + col]     = v0;
            *(float2*)&Cout[(long)(r+8)*CC + col] = v1;
        }
    }
}

__global__ void __launch_bounds__(256, 2) k_gemm_qkv() {
    int z = blockIdx.z;
    float* out = z == 0 ? g_q : (z == 1 ? g_k : g_v);
    gemm_core<false>(g_xh, g_xl, g_wh[z], g_wl[z], out, nullptr, nullptr);
}

__global__ void __launch_bounds__(256, 2) k_gemm_out(const float* __restrict__ bo,
                                                     const float* __restrict__ x) {
    gemm_core<true>(g_ath, g_atl, g_wh[3], g_wl[3], g_z, bo, x);
}

// ---------- trig table ----------
__global__ void __launch_bounds__(256) k_trig() {
    int gid = blockIdx.x * blockDim.x + threadIdx.x;   // t*32+i
    int t = gid >> 5, i = gid & 31;
    float e = (float)i * (1.0f / 32.0f);
    float inv = 1.0f / powf(10000.0f, e);
    float fr = (float)t * inv;
    g_cos[gid] = cosf(fr);
    g_sin[gid] = sinf(fr);
}

// ---------- RoPE + phi + mask ----------
__global__ void __launch_bounds__(256) k_rope(const int* __restrict__ mask) {
    int gid = blockIdx.x * blockDim.x + threadIdx.x;
    int i = gid & 31;
    int bth = gid >> 5;
    int h = bth & 15;
    int bt = bth >> 4;
    int t = bt & (TT - 1);
    float mk = (float)mask[bt];
    float c = g_cos[t*32 + i], s = g_sin[t*32 + i];
    long off = (long)bt*CC + h*DD + i;

    float q1 = g_q[off], q2 = g_q[off+32];
    g_q[off]    = phi_f(q1*c - q2*s) * mk;
    g_q[off+32] = phi_f(q2*c + q1*s) * mk;

    float k1 = g_k[off], k2 = g_k[off+32];
    g_k[off]    = phi_f(k1*c - k2*s) * mk;
    g_k[off+32] = phi_f(k2*c + k1*s) * mk;

    float v1 = g_v[off], v2 = g_v[off+32];
    g_v[off]    = v1 * mk;
    g_v[off+32] = v2 * mk;
}

// ---------- forget gate ----------
__global__ void __launch_bounds__(256) k_fgate(const float* __restrict__ x,
                                               const float* __restrict__ Wg,
                                               const float* __restrict__ bg,
                                               const int* __restrict__ mask) {
    __shared__ float xs[16][64];
    __shared__ float wsT[64][17];
    int tid = threadIdx.x;
    int row0 = blockIdx.x * 16;
    int lr = tid >> 4, lq = tid & 15;
    float acc = 0.0f;
    for (int k0 = 0; k0 < CC; k0 += 64) {
        float4 xv = *(const float4*)&x[(long)(row0+lr)*CC + k0 + lq*4];
        *(float4*)&xs[lr][lq*4] = xv;
        float4 wv = *(const float4*)&Wg[(long)lr*CC + k0 + lq*4];
        wsT[lq*4+0][lr] = wv.x; wsT[lq*4+1][lr] = wv.y;
        wsT[lq*4+2][lr] = wv.z; wsT[lq*4+3][lr] = wv.w;
        __syncthreads();
        #pragma unroll
        for (int kk = 0; kk < 64; ++kk) acc = fmaf(xs[lr][kk], wsT[kk][lq], acc);
        __syncthreads();
    }
    float zv = acc + bg[lq];
    float f = 1.0f / (1.0f + expf(-zv));
    f = fminf(fmaxf(f, 0.01f), 0.999f);
    float mk = (float)mask[row0 + lr];
    f = f * mk + (1.0f - mk);
    g_f[(long)(row0 + lr)*HH + lq] = f;
}

// ---------- denominator scan ----------
__global__ void __launch_bounds__(32) k_denom() {
    int bh = blockIdx.x;
    int b = bh >> 4, h = bh & 15;
    int lane = threadIdx.x;
    const float* K = g_k + (long)b*TT*CC + h*DD;
    const float* Q = g_q + (long)b*TT*CC + h*DD;
    const float* F = g_f + (long)b*TT*HH + h;
    float* Dst = g_den + (long)bh*TT;
    unsigned long long m2 = 0ull;
    for (int t0 = 0; t0 < TT; t0 += 8) {
        unsigned long long kk2[8], qq2[8];
        float ff[8];
        #pragma unroll
        for (int j = 0; j < 8; ++j) {
            const float* kp = K + (long)(t0+j)*CC;
            const float* qp = Q + (long)(t0+j)*CC;
            kk2[j] = pack2(kp[lane], kp[lane+32]);
            qq2[j] = pack2(qp[lane], qp[lane+32]);
            ff[j] = F[(long)(t0+j)*HH];
        }
        float part[8];
        #pragma unroll
        for (int j = 0; j < 8; ++j) {
            unsigned long long f2 = pack2(ff[j], ff[j]);
            unsigned long long t = mul2(m2, f2);
            asm("add.rn.f32x2 %0, %0, %1;" : "+l"(t) : "l"(kk2[j]));
            m2 = t;
            unsigned long long p2 = 0ull;
            FFMA2(p2, qq2[j], t);
            float2 pv = unpack2(p2);
            part[j] = pv.x + pv.y;
        }
        #pragma unroll
        for (int off = 16; off; off >>= 1)
            #pragma unroll
            for (int j = 0; j < 8; ++j)
                part[j] += __shfl_xor_sync(0xFFFFFFFFu, part[j], off);
        if (lane == 0) {
            #pragma unroll
            for (int j = 0; j < 8; ++j)
                Dst[t0 + j] = 1.0f / fmaxf(part[j], 1e-6f);
        }
    }
}

// ---------- main recurrent scan: 64 blocks x 256 threads ----------
#define SCH 16
__global__ void __launch_bounds__(256) k_scan() {
    int bh = blockIdx.x >> 1;
    int eh = blockIdx.x & 1;
    int b = bh >> 4, h = bh & 15;
    int tid = threadIdx.x;
    int w = tid >> 5, l = tid & 31;
    int e_loc = w*4 + (l >> 3);     // 0..31
    int e = eh*32 + e_loc;
    int oct = l & 7;
    int rbase = oct*8 + (oct >= 4 ? 4 : 0);   // swizzled row base

    __shared__ float ks[2][SCH][68], qs[2][SCH][68], vs[2][SCH][32];
    __shared__ float fs[2][SCH], ds[2][SCH];

    long base = (long)b*TT*CC + h*DD;
    const float* Kg = g_k + base;
    const float* Qg = g_q + base;
    const float* Vg = g_v + base;
    const float* Fg = g_f + (long)b*TT*HH + h;
    const float* Dg = g_den + (long)bh*TT;
    float* Og = g_att + base;

    unsigned long long S2[4] = {0ull, 0ull, 0ull, 0ull};

    int s_ld = tid >> 4, p_ld = tid & 15;
    int dphys = p_ld*4 + (p_ld >= 8 ? 4 : 0);
    long lo = (long)s_ld*CC + p_ld*4;
    int sv = tid >> 3, pvi = tid & 7;
    long lov = (long)sv*CC + eh*32 + pvi*4;

    float4 pk, pq, pv = make_float4(0,0,0,0);
    float pf = 0.f, pd = 0.f;
    pk = *(const float4*)(Kg + lo);
    pq = *(const float4*)(Qg + lo);
    if (tid < 128) pv = *(const float4*)(Vg + lov);
    if (tid >= 128 && tid < 128 + SCH) pf = Fg[(long)(tid - 128)*HH];
    if (tid >= 160 && tid < 160 + SCH) pd = Dg[tid - 160];

    int buf = 0;
    const int NCH = TT / SCH;
    for (int c = 0; c < NCH; ++c) {
        *(float4*)&ks[buf][s_ld][dphys] = pk;
        *(float4*)&qs[buf][s_ld][dphys] = pq;
        if (tid < 128) *(float4*)&vs[buf][sv][pvi*4] = pv;
        if (tid >= 128 && tid < 128 + SCH) fs[buf][tid - 128] = pf;
        if (tid >= 160 && tid < 160 + SCH) ds[buf][tid - 160] = pd;
        __syncthreads();

        if (c + 1 < NCH) {
            long o2 = (long)((c+1)*SCH)*CC;
            pk = *(const float4*)(Kg + o2 + lo);
            pq = *(const float4*)(Qg + o2 + lo);
            if (tid < 128) pv = *(const float4*)(Vg + o2 + lov);
            if (tid >= 128 && tid < 128 + SCH) pf = Fg[(long)((c+1)*SCH + tid - 128)*HH];
            if (tid >= 160 && tid < 160 + SCH) pd = Dg[(c+1)*SCH + tid - 160];
        }

        #pragma unroll
        for (int s = 0; s < SCH; ++s) {
            float f = fs[buf][s];
            float v = vs[buf][s][e_loc];
            float d = ds[buf][s];
            unsigned long long f2 = pack2(f, f);
            unsigned long long v2 = pack2(v, v);
            unsigned long long p2 = 0ull;
            #pragma unroll
            for (int i = 0; i < 4; ++i) {
                unsigned long long k2 = *(const unsigned long long*)&ks[buf][s][rbase + 2*i];
                unsigned long long q2 = *(const unsigned long long*)&qs[buf][s][rbase + 2*i];
                unsigned long long t = mul2(S2[i], f2);
                FFMA2(t, k2, v2);
                S2[i] = t;
                FFMA2(p2, q2, t);
            }
            float2 pp = unpack2(p2);
            float part = pp.x + pp.y;
            part += __shfl_xor_sync(0xFFFFFFFFu, part, 1);
            part += __shfl_xor_sync(0xFFFFFFFFu, part, 2);
            part += __shfl_xor_sync(0xFFFFFFFFu, part, 4);
            if (oct == 0)
                Og[(long)(c*SCH + s)*CC + e] = part * d;
        }
        buf ^= 1;
    }
}

// ---------- LayerNorm ----------
__global__ void __launch_bounds__(256) k_ln(const float* __restrict__ lw,
                                            const float* __restrict__ lb,
                                            float* __restrict__ out) {
    int row = blockIdx.x, tid = threadIdx.x;
    int w = tid >> 5, l = tid & 31;
    const float4* y4 = (const float4*)(g_z + (long)row*CC);
    float4 a = y4[tid];
    float s1 = a.x + a.y + a.z + a.w;
    float s2 = a.x*a.x + a.y*a.y + a.z*a.z + a.w*a.w;
    #pragma unroll
    for (int off = 16; off; off >>= 1) {
        s1 += __shfl_xor_sync(0xFFFFFFFFu, s1, off);
        s2 += __shfl_xor_sync(0xFFFFFFFFu, s2, off);
    }
    __shared__ float r1[8], r2[8];
    if (l == 0) { r1[w] = s1; r2[w] = s2; }
    __syncthreads();
    if (w == 0) {
        s1 = (l < 8) ? r1[l] : 0.0f;
        s2 = (l < 8) ? r2[l] : 0.0f;
        #pragma unroll
        for (int off = 4; off; off >>= 1) {
            s1 += __shfl_xor_sync(0xFFFFFFFFu, s1, off);
            s2 += __shfl_xor_sync(0xFFFFFFFFu, s2, off);
        }
        if (l == 0) { r1[0] = s1; r2[0] = s2; }
    }
    __syncthreads();
    float mu = r1[0] * (1.0f / CC);
    float var = r2[0] * (1.0f / CC) - mu*mu;
    float rs = rsqrtf(var + 1e-5f);
    float4 wv = ((const float4*)lw)[tid];
    float4 bv = ((const float4*)lb)[tid];
    float4 o;
    o.x = (a.x - mu)*rs*wv.x + bv.x;
    o.y = (a.y - mu)*rs*wv.y + bv.y;
    o.z = (a.z - mu)*rs*wv.z + bv.z;
    o.w = (a.w - mu)*rs*wv.w + bv.w;
    ((float4*)(out + (long)row*CC))[tid] = o;
}

// ---------- att pointer accessors for cvt launches ----------
__global__ void k_dummy() {}

extern "C" void kernel_launch(void* const* d_in, const int* in_sizes, int n_in,
                              void* d_out, int out_size) {
    (void)in_sizes; (void)n_in; (void)out_size;
    const float* x    = (const float*)d_in[0];
    const int*   mask = (const int*)  d_in[1];
    const float* Wq   = (const float*)d_in[2];
    const float* Wk   = (const float*)d_in[3];
    const float* Wv   = (const float*)d_in[4];
    const float* Wg   = (const float*)d_in[5];
    const float* bg   = (const float*)d_in[6];
    const float* Wo   = (const float*)d_in[7];
    const float* bo   = (const float*)d_in[8];
    const float* lw   = (const float*)d_in[9];
    const float* lb   = (const float*)d_in[10];
    float* out = (float*)d_out;

    // device-symbol addresses (host side)
    float* att_p; __nv_bfloat16 *xh_p, *xl_p, *ath_p, *atl_p;
    cudaGetSymbolAddress((void**)&att_p, g_att);
    cudaGetSymbolAddress((void**)&xh_p,  g_xh);
    cudaGetSymbolAddress((void**)&xl_p,  g_xl);
    cudaGetSymbolAddress((void**)&ath_p, g_ath);
    cudaGetSymbolAddress((void**)&atl_p, g_atl);

    k_cvt<<<(BT*CC/4 + 255)/256, 256>>>(x, xh_p, xl_p, BT*CC/4);        // 1
    k_cvtW<<<4*(CC*CC/4)/256, 256>>>(Wq, Wk, Wv, Wo);                    // 2
    k_trig<<<TT*32/256, 256>>>();                                        // 3
    k_gemm_qkv<<<dim3(CC/128, BT/128, 3), 256>>>();                      // 4 (ncu slot)
    k_rope<<<BT*HH*32/256, 256>>>(mask);                                 // 5
    k_fgate<<<BT/16, 256>>>(x, Wg, bg, mask);                            // 6
    k_denom<<<BB*HH, 32>>>();                                            // 7
    k_scan<<<BB*HH*2, 256>>>();                                          // 8
    k_cvt<<<(BT*CC/4 + 255)/256, 256>>>(att_p, ath_p, atl_p, BT*CC/4);   // 9
    k_gemm_out<<<dim3(CC/128, BT/128), 256>>>(bo, x);                    // 10
    k_ln<<<BT, 256>>>(lw, lb, out);                                      // 11
}

// round 8
// speedup vs baseline: 1.9958x; 1.0264x over previous
#include <cuda_runtime.h>
#include <cuda_bf16.h>
#include <math.h>

#define BB 2
#define TT 2048
#define CC 1024
#define HH 16
#define DD 64
#define BT (BB*TT)

// ---------- scratch (__device__ globals; no runtime allocation) ----------
__device__ float g_q[BT*CC];
__device__ float g_k[BT*CC];
__device__ float g_v[BT*CC];
__device__ float g_att[BT*CC];   // raw numerator
__device__ float g_z[BT*CC];
__device__ float g_f[BT*HH];
__device__ float g_den[BB*HH*TT];  // reciprocal of denom
__device__ float g_cos[TT*32];
__device__ float g_sin[TT*32];

// bf16 hi/lo split operands
__device__ __nv_bfloat16 g_xh[BT*CC], g_xl[BT*CC];
__device__ __nv_bfloat16 g_ath[BT*CC], g_atl[BT*CC];
__device__ __nv_bfloat16 g_wh[4][CC*CC], g_wl[4][CC*CC];

// ---------- packed f32x2 helpers ----------
__device__ __forceinline__ unsigned long long pack2(float lo, float hi) {
    unsigned long long r;
    asm("mov.b64 %0, {%1, %2};" : "=l"(r) : "f"(lo), "f"(hi));
    return r;
}
__device__ __forceinline__ float2 unpack2(unsigned long long v) {
    float2 f;
    asm("mov.b64 {%0, %1}, %2;" : "=f"(f.x), "=f"(f.y) : "l"(v));
    return f;
}
__device__ __forceinline__ unsigned long long mul2(unsigned long long a, unsigned long long b) {
    unsigned long long r;
    asm("mul.rn.f32x2 %0, %1, %2;" : "=l"(r) : "l"(a), "l"(b));
    return r;
}
#define FFMA2(acc, a, b) asm("fma.rn.f32x2 %0, %1, %2, %0;" : "+l"(acc) : "l"(a), "l"(b))
#define FADD2(acc, a)    asm("add.rn.f32x2 %0, %0, %1;" : "+l"(acc) : "l"(a))

__device__ __forceinline__ float phi_f(float x) { return x > 0.0f ? x + 1.0f : expf(x); }

__device__ __forceinline__ unsigned smem_u32(const void* p) {
    unsigned a;
    asm("{ .reg .u64 t; cvta.to.shared.u64 t, %1; cvt.u32.u64 %0, t; }" : "=r"(a) : "l"(p));
    return a;
}

// ---------- cp.async / ldmatrix / mma ----------
#define CP_ASYNC16(dst, src) \
    asm volatile("cp.async.cg.shared.global [%0], [%1], 16;" :: "r"(dst), "l"(src))
#define CP_COMMIT() asm volatile("cp.async.commit_group;")
#define CP_WAIT1()  asm volatile("cp.async.wait_group 1;")

#define LDSM4(r, addr) \
    asm volatile("ldmatrix.sync.aligned.m8n8.x4.shared.b16 {%0,%1,%2,%3}, [%4];" \
        : "=r"((r)[0]), "=r"((r)[1]), "=r"((r)[2]), "=r"((r)[3]) : "r"(addr))

#define MMA_BF16(c, a, b) \
    asm volatile("mma.sync.aligned.m16n8k16.row.col.f32.bf16.bf16.f32 " \
                 "{%0,%1,%2,%3},{%4,%5,%6,%7},{%8,%9},{%0,%1,%2,%3};" \
                 : "+f"((c)[0]), "+f"((c)[1]), "+f"((c)[2]), "+f"((c)[3]) \
                 : "r"((a)[0]), "r"((a)[1]), "r"((a)[2]), "r"((a)[3]), \
                   "r"((b)[0]), "r"((b)[1]))

// ---------- fp32 -> bf16 hi/lo conversion ----------
__global__ void __launch_bounds__(256) k_cvt(const float* __restrict__ s,
                                             __nv_bfloat16* __restrict__ dh,
                                             __nv_bfloat16* __restrict__ dl, int n4) {
    int id = blockIdx.x * blockDim.x + threadIdx.x;
    if (id >= n4) return;
    float4 v = ((const float4*)s)[id];
    float vv[4] = {v.x, v.y, v.z, v.w};
    unsigned short h[4], l[4];
    #pragma unroll
    for (int i = 0; i < 4; ++i) {
        __nv_bfloat16 hb = __float2bfloat16(vv[i]);
        h[i] = __bfloat16_as_ushort(hb);
        l[i] = __bfloat16_as_ushort(__float2bfloat16(vv[i] - __bfloat162float(hb)));
    }
    *(uint2*)(dh + 4*id) = make_uint2(h[0] | ((unsigned)h[1]<<16), h[2] | ((unsigned)h[3]<<16));
    *(uint2*)(dl + 4*id) = make_uint2(l[0] | ((unsigned)l[1]<<16), l[2] | ((unsigned)l[3]<<16));
}

__global__ void __launch_bounds__(256) k_cvtW(const float* __restrict__ Wq,
                                              const float* __restrict__ Wk,
                                              const float* __restrict__ Wv,
                                              const float* __restrict__ Wo) {
    int id = blockIdx.x * blockDim.x + threadIdx.x;
    int seg = id >> 18;
    int off = id & 0x3FFFF;
    const float* src = seg == 0 ? Wq : seg == 1 ? Wk : seg == 2 ? Wv : Wo;
    float4 v = ((const float4*)src)[off];
    float vv[4] = {v.x, v.y, v.z, v.w};
    unsigned short h[4], l[4];
    #pragma unroll
    for (int i = 0; i < 4; ++i) {
        __nv_bfloat16 hb = __float2bfloat16(vv[i]);
        h[i] = __bfloat16_as_ushort(hb);
        l[i] = __bfloat16_as_ushort(__float2bfloat16(vv[i] - __bfloat162float(hb)));
    }
    *(uint2*)(g_wh[seg] + 4*off) = make_uint2(h[0] | ((unsigned)h[1]<<16), h[2] | ((unsigned)h[3]<<16));
    *(uint2*)(g_wl[seg] + 4*off) = make_uint2(l[0] | ((unsigned)l[1]<<16), l[2] | ((unsigned)l[3]<<16));
}

// ---------- normalize att + split to bf16 hi/lo ----------
__global__ void __launch_bounds__(256) k_cvtatt() {
    int id = blockIdx.x * blockDim.x + threadIdx.x;   // BT*CC/4
    int elem = id * 4;
    int bt = elem >> 10;
    int rem = elem & 1023;
    int h = rem >> 6;
    int b = bt >> 11, t = bt & (TT - 1);
    float r = g_den[((long)(b*HH + h))*TT + t];
    float4 v = *(const float4*)(g_att + (long)elem);
    float vv[4] = {v.x*r, v.y*r, v.z*r, v.w*r};
    unsigned short hh[4], ll[4];
    #pragma unroll
    for (int i = 0; i < 4; ++i) {
        __nv_bfloat16 hb = __float2bfloat16(vv[i]);
        hh[i] = __bfloat16_as_ushort(hb);
        ll[i] = __bfloat16_as_ushort(__float2bfloat16(vv[i] - __bfloat162float(hb)));
    }
    *(uint2*)(g_ath + elem) = make_uint2(hh[0] | ((unsigned)hh[1]<<16), hh[2] | ((unsigned)hh[3]<<16));
    *(uint2*)(g_atl + elem) = make_uint2(ll[0] | ((unsigned)ll[1]<<16), ll[2] | ((unsigned)ll[3]<<16));
}

// ---------- bf16x3 GEMM: BK=32, 3-stage cp.async pipeline ----------
// smem tile per stage per operand: 128 rows x 32 bf16 (64B/row), 16B-chunk swizzle ((r>>1)&3)
#define GEMM_DSMEM (3*4*8192)

template<bool EPI>
__device__ __forceinline__ void gemm_core(const __nv_bfloat16* __restrict__ Agh,
                                          const __nv_bfloat16* __restrict__ Agl,
                                          const __nv_bfloat16* __restrict__ Bgh,
                                          const __nv_bfloat16* __restrict__ Bgl,
                                          float* __restrict__ Cout,
                                          const float* __restrict__ bias,
                                          const float* __restrict__ resid)
{
    extern __shared__ __align__(16) char dynsm[];
    unsigned smb = smem_u32(dynsm);

    int tid = threadIdx.x;
    int m0 = blockIdx.y * 128;
    int n0 = blockIdx.x * 128;

    // producer: row = tid>>1, chunk-pair ph = tid&1 (bf16 cols ph*16 .. +15)
    int prow = tid >> 1;
    int ph = tid & 1;
    const __nv_bfloat16* srcs[4];
    srcs[0] = Agh + (long)(m0 + prow) * CC + ph * 16;
    srcs[1] = Agl + (long)(m0 + prow) * CC + ph * 16;
    srcs[2] = Bgh + (long)(n0 + prow) * CC + ph * 16;
    srcs[3] = Bgl + (long)(n0 + prow) * CC + ph * 16;
    unsigned psw = (prow >> 1) & 3;
    unsigned d0off = prow * 64 + (((2u*ph) ^ psw) << 4);

    // consumer
    int warp = tid >> 5, lane = tid & 31;
    int g = lane >> 2, tg = lane & 3;
    int mbase = (warp >> 1) * 32;
    int nbase = (warp & 1) * 64;
    int lrow = lane & 15, lhi = lane >> 4;

    float c[2][8][4];
    #pragma unroll
    for (int mf = 0; mf < 2; ++mf)
        #pragma unroll
        for (int nf = 0; nf < 8; ++nf)
            #pragma unroll
            for (int j = 0; j < 4; ++j) c[mf][nf][j] = 0.0f;

    auto issue = [&](int kt) {
        unsigned sb = smb + (unsigned)(kt % 3) * 32768u;
        #pragma unroll
        for (int t = 0; t < 4; ++t) {
            const __nv_bfloat16* s = srcs[t] + kt * 32;
            unsigned d = sb + t * 8192 + d0off;
            CP_ASYNC16(d, s);
            CP_ASYNC16(d ^ 16u, s + 8);
        }
        CP_COMMIT();
    };

    auto lda = [&](unsigned sb, int t, int rowbase, int kh) -> unsigned {
        int r = rowbase + lrow;
        unsigned ch = (unsigned)(kh * 2 + lhi);
        return sb + t * 8192 + r * 64 + ((ch ^ ((unsigned)(r >> 1) & 3u)) << 4);
    };

    const int NT = CC / 32;   // 32
    issue(0);
    issue(1);

    for (int kt = 0; kt < NT; ++kt) {
        CP_WAIT1();
        __syncthreads();
        if (kt + 2 < NT) issue(kt + 2);

        unsigned sb = smb + (unsigned)(kt % 3) * 32768u;
        #pragma unroll
        for (int kh = 0; kh < 2; ++kh) {
            unsigned aH[2][4], aL[2][4];
            #pragma unroll
            for (int mf = 0; mf < 2; ++mf) {
                LDSM4(aH[mf], lda(sb, 0, mbase + mf*16, kh));
                LDSM4(aL[mf], lda(sb, 1, mbase + mf*16, kh));
            }
            #pragma unroll
            for (int nfp = 0; nfp < 4; ++nfp) {
                unsigned bh4[4], bl4[4];
                LDSM4(bh4, lda(sb, 2, nbase + nfp*16, kh));
                LDSM4(bl4, lda(sb, 3, nbase + nfp*16, kh));
                unsigned bh0[2] = {bh4[0], bh4[2]}, bh1[2] = {bh4[1], bh4[3]};
                unsigned bl0[2] = {bl4[0], bl4[2]}, bl1[2] = {bl4[1], bl4[3]};
                #pragma unroll
                for (int mf = 0; mf < 2; ++mf) {
                    MMA_BF16(c[mf][nfp*2],   aH[mf], bh0);
                    MMA_BF16(c[mf][nfp*2],   aH[mf], bl0);
                    MMA_BF16(c[mf][nfp*2],   aL[mf], bh0);
                    MMA_BF16(c[mf][nfp*2+1], aH[mf], bh1);
                    MMA_BF16(c[mf][nfp*2+1], aH[mf], bl1);
                    MMA_BF16(c[mf][nfp*2+1], aL[mf], bh1);
                }
            }
        }
    }

    #pragma unroll
    for (int mf = 0; mf < 2; ++mf) {
        #pragma unroll
        for (int nf = 0; nf < 8; ++nf) {
            int r = m0 + mbase + mf*16 + g;
            int col = n0 + nbase + nf*8 + 2*tg;
            float2 v0 = make_float2(c[mf][nf][0], c[mf][nf][1]);
            float2 v1 = make_float2(c[mf][nf][2], c[mf][nf][3]);
            if (EPI) {
                float b0 = bias[col], b1 = bias[col+1];
                v0.x += b0 + resid[(long)r*CC + col];
                v0.y += b1 + resid[(long)r*CC + col + 1];
                v1.x += b0 + resid[(long)(r+8)*CC + col];
                v1.y += b1 + resid[(long)(r+8)*CC + col + 1];
            }
            *(float2*)&Cout[(long)r*CC + col]     = v0;
            *(float2*)&Cout[(long)(r+8)*CC + col] = v1;
        }
    }
}

__global__ void __launch_bounds__(256, 2) k_gemm_qkv() {
    int z = blockIdx.z;
    float* out = z == 0 ? g_q : (z == 1 ? g_k : g_v);
    gemm_core<false>(g_xh, g_xl, g_wh[z], g_wl[z], out, nullptr, nullptr);
}

__global__ void __launch_bounds__(256, 2) k_gemm_out(const float* __restrict__ bo,
                                                     const float* __restrict__ x) {
    gemm_core<true>(g_ath, g_atl, g_wh[3], g_wl[3], g_z, bo, x);
}

// ---------- trig table ----------
__global__ void __launch_bounds__(256) k_trig() {
    int gid = blockIdx.x * blockDim.x + threadIdx.x;
    int t = gid >> 5, i = gid & 31;
    float e = (float)i * (1.0f / 32.0f);
    float inv = 1.0f / powf(10000.0f, e);
    float fr = (float)t * inv;
    g_cos[gid] = cosf(fr);
    g_sin[gid] = sinf(fr);
}

// ---------- RoPE + phi + mask ----------
__global__ void __launch_bounds__(256) k_rope(const int* __restrict__ mask) {
    int gid = blockIdx.x * blockDim.x + threadIdx.x;
    int i = gid & 31;
    int bth = gid >> 5;
    int h = bth & 15;
    int bt = bth >> 4;
    int t = bt & (TT - 1);
    float mk = (float)mask[bt];
    float c = g_cos[t*32 + i], s = g_sin[t*32 + i];
    long off = (long)bt*CC + h*DD + i;

    float q1 = g_q[off], q2 = g_q[off+32];
    g_q[off]    = phi_f(q1*c - q2*s) * mk;
    g_q[off+32] = phi_f(q2*c + q1*s) * mk;

    float k1 = g_k[off], k2 = g_k[off+32];
    g_k[off]    = phi_f(k1*c - k2*s) * mk;
    g_k[off+32] = phi_f(k2*c + k1*s) * mk;

    float v1 = g_v[off], v2 = g_v[off+32];
    g_v[off]    = v1 * mk;
    g_v[off+32] = v2 * mk;
}

// ---------- forget gate ----------
__global__ void __launch_bounds__(256) k_fgate(const float* __restrict__ x,
                                               const float* __restrict__ Wg,
                                               const float* __restrict__ bg,
                                               const int* __restrict__ mask) {
    __shared__ float xs[16][64];
    __shared__ float wsT[64][17];
    int tid = threadIdx.x;
    int row0 = blockIdx.x * 16;
    int lr = tid >> 4, lq = tid & 15;
    float acc = 0.0f;
    for (int k0 = 0; k0 < CC; k0 += 64) {
        float4 xv = *(const float4*)&x[(long)(row0+lr)*CC + k0 + lq*4];
        *(float4*)&xs[lr][lq*4] = xv;
        float4 wv = *(const float4*)&Wg[(long)lr*CC + k0 + lq*4];
        wsT[lq*4+0][lr] = wv.x; wsT[lq*4+1][lr] = wv.y;
        wsT[lq*4+2][lr] = wv.z; wsT[lq*4+3][lr] = wv.w;
        __syncthreads();
        #pragma unroll
        for (int kk = 0; kk < 64; ++kk) acc = fmaf(xs[lr][kk], wsT[kk][lq], acc);
        __syncthreads();
    }
    float zv = acc + bg[lq];
    float f = 1.0f / (1.0f + expf(-zv));
    f = fminf(fmaxf(f, 0.01f), 0.999f);
    float mk = (float)mask[row0 + lr];
    f = f * mk + (1.0f - mk);
    g_f[(long)(row0 + lr)*HH + lq] = f;
}

// ---------- main recurrent scan: 64 blocks x 288 threads (warp 8 = denom) ----------
#define SCH 16
__global__ void __launch_bounds__(288) k_scan() {
    int bh = blockIdx.x >> 1;
    int eh = blockIdx.x & 1;
    int b = bh >> 4, h = bh & 15;
    int tid = threadIdx.x;
    int w = tid >> 5, l = tid & 31;
    int e_loc = (w < 8) ? (w*4 + (l >> 3)) : 0;   // column 0..31
    int e = eh*32 + e_loc;
    int oct = l & 7;
    int rbase = oct*8 + (oct >= 4 ? 4 : 0);       // swizzled row base

    __shared__ float ks[2][SCH][68], qs[2][SCH][68], vs[2][SCH][32];
    __shared__ float fs[2][SCH];

    long base = (long)b*TT*CC + h*DD;
    const float* Kg = g_k + base;
    const float* Qg = g_q + base;
    const float* Vg = g_v + base;
    const float* Fg = g_f + (long)b*TT*HH + h;
    float* Og = g_att + base;
    float* DstD = g_den + (long)bh*TT;

    unsigned long long S2[4] = {0ull, 0ull, 0ull, 0ull};   // column state (w<8) or denom m (w==8)

    int s_ld = tid >> 4, p_ld = tid & 15;
    int dphys = p_ld*4 + (p_ld >= 8 ? 4 : 0);
    long lo = (long)s_ld*CC + p_ld*4;
    int sv = tid >> 3, pvi = tid & 7;
    long lov = (long)sv*CC + eh*32 + pvi*4;

    float4 pk = make_float4(0,0,0,0), pq = make_float4(0,0,0,0), pv = make_float4(0,0,0,0);
    float pf = 0.f;
    if (tid < 256) {
        pk = *(const float4*)(Kg + lo);
        pq = *(const float4*)(Qg + lo);
    }
    if (tid < 128) pv = *(const float4*)(Vg + lov);
    if (tid >= 128 && tid < 128 + SCH) pf = Fg[(long)(tid - 128)*HH];

    int buf = 0;
    const int NCH = TT / SCH;
    for (int c = 0; c < NCH; ++c) {
        if (tid < 256) {
            *(float4*)&ks[buf][s_ld][dphys] = pk;
            *(float4*)&qs[buf][s_ld][dphys] = pq;
        }
        if (tid < 128) *(float4*)&vs[buf][sv][pvi*4] = pv;
        if (tid >= 128 && tid < 128 + SCH) fs[buf][tid - 128] = pf;
        __syncthreads();

        if (c + 1 < NCH) {
            long o2 = (long)((c+1)*SCH)*CC;
            if (tid < 256) {
                pk = *(const float4*)(Kg + o2 + lo);
                pq = *(const float4*)(Qg + o2 + lo);
            }
            if (tid < 128) pv = *(const float4*)(Vg + o2 + lov);
            if (tid >= 128 && tid < 128 + SCH) pf = Fg[(long)((c+1)*SCH + tid - 128)*HH];
        }

        #pragma unroll
        for (int s = 0; s < SCH; ++s) {
            float f = fs[buf][s];
            unsigned long long f2 = pack2(f, f);
            if (w < 8) {
                float v = vs[buf][s][e_loc];
                unsigned long long v2 = pack2(v, v);
                unsigned long long p2 = 0ull;
                #pragma unroll
                for (int i = 0; i < 4; ++i) {
                    unsigned long long k2 = *(const unsigned long long*)&ks[buf][s][rbase + 2*i];
                    unsigned long long q2 = *(const unsigned long long*)&qs[buf][s][rbase + 2*i];
                    unsigned long long t = mul2(S2[i], f2);
                    FFMA2(t, k2, v2);
                    S2[i] = t;
                    FFMA2(p2, q2, t);
                }
                float2 pp = unpack2(p2);
                float part = pp.x + pp.y;
                part += __shfl_xor_sync(0xFFFFFFFFu, part, 1);
                part += __shfl_xor_sync(0xFFFFFFFFu, part, 2);
                part += __shfl_xor_sync(0xFFFFFFFFu, part, 4);
                if (oct == 0)
                    Og[(long)(c*SCH + s)*CC + e] = part;
            } else if (l < 8 && eh == 0) {
                // denominator column: m = f*m + k ; den = q . m
                unsigned long long p2 = 0ull;
                #pragma unroll
                for (int i = 0; i < 4; ++i) {
                    unsigned long long k2 = *(const unsigned long long*)&ks[buf][s][rbase + 2*i];
                    unsigned long long q2 = *(const unsigned long long*)&qs[buf][s][rbase + 2*i];
                    unsigned long long t = mul2(S2[i], f2);
                    FADD2(t, k2);
                    S2[i] = t;
                    FFMA2(p2, q2, t);
                }
                float2 pp = unpack2(p2);
                float part = pp.x + pp.y;
                part += __shfl_xor_sync(0xFFu, part, 1);
                part += __shfl_xor_sync(0xFFu, part, 2);
                part += __shfl_xor_sync(0xFFu, part, 4);
                if (l == 0)
                    DstD[c*SCH + s] = 1.0f / fmaxf(part, 1e-6f);
            }
        }
        buf ^= 1;
    }
}

// ---------- LayerNorm ----------
__global__ void __launch_bounds__(256) k_ln(const float* __restrict__ lw,
                                            const float* __restrict__ lb,
                                            float* __restrict__ out) {
    int row = blockIdx.x, tid = threadIdx.x;
    int w = tid >> 5, l = tid & 31;
    const float4* y4 = (const float4*)(g_z + (long)row*CC);
    float4 a = y4[tid];
    float s1 = a.x + a.y + a.z + a.w;
    float s2 = a.x*a.x + a.y*a.y + a.z*a.z + a.w*a.w;
    #pragma unroll
    for (int off = 16; off; off >>= 1) {
        s1 += __shfl_xor_sync(0xFFFFFFFFu, s1, off);
        s2 += __shfl_xor_sync(0xFFFFFFFFu, s2, off);
    }
    __shared__ float r1[8], r2[8];
    if (l == 0) { r1[w] = s1; r2[w] = s2; }
    __syncthreads();
    if (w == 0) {
        s1 = (l < 8) ? r1[l] : 0.0f;
        s2 = (l < 8) ? r2[l] : 0.0f;
        #pragma unroll
        for (int off = 4; off; off >>= 1) {
            s1 += __shfl_xor_sync(0xFFFFFFFFu, s1, off);
            s2 += __shfl_xor_sync(0xFFFFFFFFu, s2, off);
        }
        if (l == 0) { r1[0] = s1; r2[0] = s2; }
    }
    __syncthreads();
    float mu = r1[0] * (1.0f / CC);
    float var = r2[0] * (1.0f / CC) - mu*mu;
    float rs = rsqrtf(var + 1e-5f);
    float4 wv = ((const float4*)lw)[tid];
    float4 bv = ((const float4*)lb)[tid];
    float4 o;
    o.x = (a.x - mu)*rs*wv.x + bv.x;
    o.y = (a.y - mu)*rs*wv.y + bv.y;
    o.z = (a.z - mu)*rs*wv.z + bv.z;
    o.w = (a.w - mu)*rs*wv.w + bv.w;
    ((float4*)(out + (long)row*CC))[tid] = o;
}

extern "C" void kernel_launch(void* const* d_in, const int* in_sizes, int n_in,
                              void* d_out, int out_size) {
    (void)in_sizes; (void)n_in; (void)out_size;
    const float* x    = (const float*)d_in[0];
    const int*   mask = (const int*)  d_in[1];
    const float* Wq   = (const float*)d_in[2];
    const float* Wk   = (const float*)d_in[3];
    const float* Wv   = (const float*)d_in[4];
    const float* Wg   = (const float*)d_in[5];
    const float* bg   = (const float*)d_in[6];
    const float* Wo   = (const float*)d_in[7];
    const float* bo   = (const float*)d_in[8];
    const float* lw   = (const float*)d_in[9];
    const float* lb   = (const float*)d_in[10];
    float* out = (float*)d_out;

    __nv_bfloat16 *xh_p, *xl_p;
    cudaGetSymbolAddress((void**)&xh_p, g_xh);
    cudaGetSymbolAddress((void**)&xl_p, g_xl);

    cudaFuncSetAttribute(k_gemm_qkv, cudaFuncAttributeMaxDynamicSharedMemorySize, GEMM_DSMEM);
    cudaFuncSetAttribute(k_gemm_out, cudaFuncAttributeMaxDynamicSharedMemorySize, GEMM_DSMEM);

    k_cvt<<<(BT*CC/4 + 255)/256, 256>>>(x, xh_p, xl_p, BT*CC/4);            // 1
    k_cvtW<<<4*(CC*CC/4)/256, 256>>>(Wq, Wk, Wv, Wo);                        // 2
    k_trig<<<TT*32/256, 256>>>();                                            // 3
    k_gemm_qkv<<<dim3(CC/128, BT/128, 3), 256, GEMM_DSMEM>>>();              // 4 (ncu slot)
    k_rope<<<BT*HH*32/256, 256>>>(mask);                                     // 5
    k_fgate<<<BT/16, 256>>>(x, Wg, bg, mask);                                // 6
    k_scan<<<BB*HH*2, 288>>>();                                              // 7
    k_cvtatt<<<(BT*CC/4)/256, 256>>>();                                      // 8
    k_gemm_out<<<dim3(CC/128, BT/128), 256, GEMM_DSMEM>>>(bo, x);            // 9
    k_ln<<<BT, 256>>>(lw, lb, out);                                          // 10
}

// round 9
// speedup vs baseline: 2.0138x; 1.0090x over previous
#include <cuda_runtime.h>
#include <cuda_bf16.h>
#include <math.h>

#define BB 2
#define TT 2048
#define CC 1024
#define HH 16
#define DD 64
#define BT (BB*TT)

// ---------- scratch ----------
__device__ float g_q[BT*CC];
__device__ float g_k[BT*CC];
__device__ float g_v[BT*CC];
__device__ float g_att[BT*CC];   // raw numerator
__device__ float g_z[BT*CC];
__device__ float g_f[BT*HH];
__device__ float g_den[BB*HH*TT];  // reciprocal of denom
__device__ float g_cos[TT*32];
__device__ float g_sin[TT*32];

__device__ __nv_bfloat16 g_xh[BT*CC], g_xl[BT*CC];
__device__ __nv_bfloat16 g_ath[BT*CC], g_atl[BT*CC];
__device__ __nv_bfloat16 g_wh[4][CC*CC], g_wl[4][CC*CC];

// ---------- f32x2 helpers ----------
__device__ __forceinline__ unsigned long long pack2(float lo, float hi) {
    unsigned long long r;
    asm("mov.b64 %0, {%1, %2};" : "=l"(r) : "f"(lo), "f"(hi));
    return r;
}
__device__ __forceinline__ float2 unpack2(unsigned long long v) {
    float2 f;
    asm("mov.b64 {%0, %1}, %2;" : "=f"(f.x), "=f"(f.y) : "l"(v));
    return f;
}
__device__ __forceinline__ unsigned long long mul2(unsigned long long a, unsigned long long b) {
    unsigned long long r;
    asm("mul.rn.f32x2 %0, %1, %2;" : "=l"(r) : "l"(a), "l"(b));
    return r;
}
#define FFMA2(acc, a, b) asm("fma.rn.f32x2 %0, %1, %2, %0;" : "+l"(acc) : "l"(a), "l"(b))
#define FADD2(acc, a)    asm("add.rn.f32x2 %0, %0, %1;" : "+l"(acc) : "l"(a))

__device__ __forceinline__ float phi_f(float x) { return x > 0.0f ? x + 1.0f : expf(x); }

__device__ __forceinline__ unsigned smem_u32(const void* p) {
    unsigned a;
    asm("{ .reg .u64 t; cvta.to.shared.u64 t, %1; cvt.u32.u64 %0, t; }" : "=r"(a) : "l"(p));
    return a;
}

// ---------- cp.async / ldmatrix / mma ----------
#define CP_ASYNC16(dst, src) \
    asm volatile("cp.async.cg.shared.global [%0], [%1], 16;" :: "r"(dst), "l"(src))
#define CP_COMMIT() asm volatile("cp.async.commit_group;")
#define CP_WAIT1()  asm volatile("cp.async.wait_group 1;")

#define LDSM4(r, addr) \
    asm volatile("ldmatrix.sync.aligned.m8n8.x4.shared.b16 {%0,%1,%2,%3}, [%4];" \
        : "=r"((r)[0]), "=r"((r)[1]), "=r"((r)[2]), "=r"((r)[3]) : "r"(addr))

#define MMA_BF16(c, a, b) \
    asm volatile("mma.sync.aligned.m16n8k16.row.col.f32.bf16.bf16.f32 " \
                 "{%0,%1,%2,%3},{%4,%5,%6,%7},{%8,%9},{%0,%1,%2,%3};" \
                 : "+f"((c)[0]), "+f"((c)[1]), "+f"((c)[2]), "+f"((c)[3]) \
                 : "r"((a)[0]), "r"((a)[1]), "r"((a)[2]), "r"((a)[3]), \
                   "r"((b)[0]), "r"((b)[1]))

// ---------- fused fp32->bf16 hi/lo conversion: x (blocks<4096) + weights ----------
__device__ __forceinline__ void split_store(float4 v, __nv_bfloat16* dh, __nv_bfloat16* dl, long idx) {
    float vv[4] = {v.x, v.y, v.z, v.w};
    unsigned short h[4], l[4];
    #pragma unroll
    for (int i = 0; i < 4; ++i) {
        __nv_bfloat16 hb = __float2bfloat16(vv[i]);
        h[i] = __bfloat16_as_ushort(hb);
        l[i] = __bfloat16_as_ushort(__float2bfloat16(vv[i] - __bfloat162float(hb)));
    }
    *(uint2*)(dh + idx) = make_uint2(h[0] | ((unsigned)h[1]<<16), h[2] | ((unsigned)h[3]<<16));
    *(uint2*)(dl + idx) = make_uint2(l[0] | ((unsigned)l[1]<<16), l[2] | ((unsigned)l[3]<<16));
}

__global__ void __launch_bounds__(256) k_cvtall(const float* __restrict__ x,
                                                const float* __restrict__ Wq,
                                                const float* __restrict__ Wk,
                                                const float* __restrict__ Wv,
                                                const float* __restrict__ Wo) {
    int id = blockIdx.x * blockDim.x + threadIdx.x;
    if (blockIdx.x < 4096) {
        float4 v = ((const float4*)x)[id];
        split_store(v, g_xh, g_xl, (long)id*4);
    } else {
        int wid = id - 4096*256;
        int seg = wid >> 16;            // 65536 float4 per weight
        int off = wid & 0xFFFF;
        const float* src = seg == 0 ? Wq : seg == 1 ? Wk : seg == 2 ? Wv : Wo;
        // each weight: 262144 float4 -> need 4 per thread
        #pragma unroll
        for (int r = 0; r < 4; ++r) {
            int o = off + r * 65536;
            float4 v = ((const float4*)src)[o];
            split_store(v, g_wh[seg], g_wl[seg], (long)o*4);
        }
    }
}

// ---------- fused fgate (blocks 0..255) + trig (blocks 256..511) ----------
__global__ void __launch_bounds__(256) k_misc(const float* __restrict__ x,
                                              const float* __restrict__ Wg,
                                              const float* __restrict__ bg,
                                              const int* __restrict__ mask) {
    if (blockIdx.x < 256) {
        __shared__ float xs[16][64];
        __shared__ float wsT[64][17];
        int tid = threadIdx.x;
        int row0 = blockIdx.x * 16;
        int lr = tid >> 4, lq = tid & 15;
        float acc = 0.0f;
        for (int k0 = 0; k0 < CC; k0 += 64) {
            float4 xv = *(const float4*)&x[(long)(row0+lr)*CC + k0 + lq*4];
            *(float4*)&xs[lr][lq*4] = xv;
            float4 wv = *(const float4*)&Wg[(long)lr*CC + k0 + lq*4];
            wsT[lq*4+0][lr] = wv.x; wsT[lq*4+1][lr] = wv.y;
            wsT[lq*4+2][lr] = wv.z; wsT[lq*4+3][lr] = wv.w;
            __syncthreads();
            #pragma unroll
            for (int kk = 0; kk < 64; ++kk) acc = fmaf(xs[lr][kk], wsT[kk][lq], acc);
            __syncthreads();
        }
        float zv = acc + bg[lq];
        float f = 1.0f / (1.0f + expf(-zv));
        f = fminf(fmaxf(f, 0.01f), 0.999f);
        float mk = (float)mask[row0 + lr];
        f = f * mk + (1.0f - mk);
        g_f[(long)(row0 + lr)*HH + lq] = f;
    } else {
        int gid = (blockIdx.x - 256) * 256 + threadIdx.x;
        int t = gid >> 5, i = gid & 31;
        float e = (float)i * (1.0f / 32.0f);
        float inv = 1.0f / powf(10000.0f, e);
        float fr = (float)t * inv;
        g_cos[gid] = cosf(fr);
        g_sin[gid] = sinf(fr);
    }
}

// ---------- normalize att + split to bf16 hi/lo ----------
__global__ void __launch_bounds__(256) k_cvtatt() {
    int id = blockIdx.x * blockDim.x + threadIdx.x;
    int elem = id * 4;
    int bt = elem >> 10;
    int rem = elem & 1023;
    int h = rem >> 6;
    int b = bt >> 11, t = bt & (TT - 1);
    float r = g_den[((long)(b*HH + h))*TT + t];
    float4 v = *(const float4*)(g_att + (long)elem);
    v.x *= r; v.y *= r; v.z *= r; v.w *= r;
    split_store(v, g_ath, g_atl, (long)elem);
}

// ---------- bf16x3 GEMM: BK=32, 3-stage cp.async, reordered MMAs ----------
#define GEMM_DSMEM (3*4*8192)

template<bool EPI>
__device__ __forceinline__ void gemm_core(const __nv_bfloat16* __restrict__ Agh,
                                          const __nv_bfloat16* __restrict__ Agl,
                                          const __nv_bfloat16* __restrict__ Bgh,
                                          const __nv_bfloat16* __restrict__ Bgl,
                                          float* __restrict__ Cout,
                                          const float* __restrict__ bias,
                                          const float* __restrict__ resid)
{
    extern __shared__ __align__(16) char dynsm[];
    unsigned smb = smem_u32(dynsm);

    int tid = threadIdx.x;
    int m0 = blockIdx.y * 128;
    int n0 = blockIdx.x * 128;

    int prow = tid >> 1;
    int ph = tid & 1;
    const __nv_bfloat16* srcs[4];
    srcs[0] = Agh + (long)(m0 + prow) * CC + ph * 16;
    srcs[1] = Agl + (long)(m0 + prow) * CC + ph * 16;
    srcs[2] = Bgh + (long)(n0 + prow) * CC + ph * 16;
    srcs[3] = Bgl + (long)(n0 + prow) * CC + ph * 16;
    unsigned psw = (prow >> 1) & 3;
    unsigned d0off = prow * 64 + (((2u*ph) ^ psw) << 4);

    int warp = tid >> 5, lane = tid & 31;
    int g = lane >> 2, tg = lane & 3;
    int mbase = (warp >> 1) * 32;
    int nbase = (warp & 1) * 64;
    int lrow = lane & 15, lhi = lane >> 4;

    float c[2][8][4];
    #pragma unroll
    for (int mf = 0; mf < 2; ++mf)
        #pragma unroll
        for (int nf = 0; nf < 8; ++nf)
            #pragma unroll
            for (int j = 0; j < 4; ++j) c[mf][nf][j] = 0.0f;

    auto issue = [&](int kt) {
        unsigned sb = smb + (unsigned)(kt % 3) * 32768u;
        #pragma unroll
        for (int t = 0; t < 4; ++t) {
            const __nv_bfloat16* s = srcs[t] + kt * 32;
            unsigned d = sb + t * 8192 + d0off;
            CP_ASYNC16(d, s);
            CP_ASYNC16(d ^ 16u, s + 8);
        }
        CP_COMMIT();
    };

    auto lda = [&](unsigned sb, int t, int rowbase, int kh) -> unsigned {
        int r = rowbase + lrow;
        unsigned ch = (unsigned)(kh * 2 + lhi);
        return sb + t * 8192 + r * 64 + ((ch ^ ((unsigned)(r >> 1) & 3u)) << 4);
    };

    const int NT = CC / 32;
    issue(0);
    issue(1);

    for (int kt = 0; kt < NT; ++kt) {
        CP_WAIT1();
        __syncthreads();
        if (kt + 2 < NT) issue(kt + 2);

        unsigned sb = smb + (unsigned)(kt % 3) * 32768u;
        #pragma unroll
        for (int kh = 0; kh < 2; ++kh) {
            unsigned aH[2][4], aL[2][4];
            #pragma unroll
            for (int mf = 0; mf < 2; ++mf) {
                LDSM4(aH[mf], lda(sb, 0, mbase + mf*16, kh));
                LDSM4(aL[mf], lda(sb, 1, mbase + mf*16, kh));
            }
            #pragma unroll
            for (int nfp = 0; nfp < 4; ++nfp) {
                unsigned bh4[4], bl4[4];
                LDSM4(bh4, lda(sb, 2, nbase + nfp*16, kh));
                LDSM4(bl4, lda(sb, 3, nbase + nfp*16, kh));
                unsigned bh0[2] = {bh4[0], bh4[2]}, bh1[2] = {bh4[1], bh4[3]};
                unsigned bl0[2] = {bl4[0], bl4[2]}, bl1[2] = {bl4[1], bl4[3]};
                // term-major order: same accumulator reused at distance 4
                MMA_BF16(c[0][nfp*2],   aH[0], bh0);
                MMA_BF16(c[1][nfp*2],   aH[1], bh0);
                MMA_BF16(c[0][nfp*2+1], aH[0], bh1);
                MMA_BF16(c[1][nfp*2+1], aH[1], bh1);
                MMA_BF16(c[0][nfp*2],   aH[0], bl0);
                MMA_BF16(c[1][nfp*2],   aH[1], bl0);
                MMA_BF16(c[0][nfp*2+1], aH[0], bl1);
                MMA_BF16(c[1][nfp*2+1], aH[1], bl1);
                MMA_BF16(c[0][nfp*2],   aL[0], bh0);
                MMA_BF16(c[1][nfp*2],   aL[1], bh0);
                MMA_BF16(c[0][nfp*2+1], aL[0], bh1);
                MMA_BF16(c[1][nfp*2+1], aL[1], bh1);
            }
        }
    }

    #pragma unroll
    for (int mf = 0; mf < 2; ++mf) {
        #pragma unroll
        for (int nf = 0; nf < 8; ++nf) {
            int r = m0 + mbase + mf*16 + g;
            int col = n0 + nbase + nf*8 + 2*tg;
            float2 v0 = make_float2(c[mf][nf][0], c[mf][nf][1]);
            float2 v1 = make_float2(c[mf][nf][2], c[mf][nf][3]);
            if (EPI) {
                float b0 = bias[col], b1 = bias[col+1];
                v0.x += b0 + resid[(long)r*CC + col];
                v0.y += b1 + resid[(long)r*CC + col + 1];
                v1.x += b0 + resid[(long)(r+8)*CC + col];
                v1.y += b1 + resid[(long)(r+8)*CC + col + 1];
            }
            *(float2*)&Cout[(long)r*CC + col]     = v0;
            *(float2*)&Cout[(long)(r+8)*CC + col] = v1;
        }
    }
}

__global__ void __launch_bounds__(256, 2) k_gemm_qkv() {
    int z = blockIdx.z;
    float* out = z == 0 ? g_q : (z == 1 ? g_k : g_v);
    gemm_core<false>(g_xh, g_xl, g_wh[z], g_wl[z], out, nullptr, nullptr);
}

__global__ void __launch_bounds__(256, 2) k_gemm_out(const float* __restrict__ bo,
                                                     const float* __restrict__ x) {
    gemm_core<true>(g_ath, g_atl, g_wh[3], g_wl[3], g_z, bo, x);
}

// ---------- recurrent scan: 128 blocks x 128 threads, RoPE fused into staging ----------
// warps 0-1: compute (2 columns/thread); warp 2 lanes 0-7: denominator (eh==0); warp 3: staging only
#define SCH 16
__global__ void __launch_bounds__(128) k_scan(const int* __restrict__ mask) {
    int bh = blockIdx.x >> 2;
    int eh = blockIdx.x & 3;
    int b = bh >> 4, h = bh & 15;
    int tid = threadIdx.x;
    int w = tid >> 5, l = tid & 31;
    int oct = l & 7;
    int cp = w*4 + (l >> 3);               // 0..7 column-pair (valid w<2)
    int rbase = oct*8 + (oct >= 4 ? 4 : 0);

    __shared__ float ks[2][SCH][68], qs[2][SCH][68], vs[2][SCH][16], fs[2][SCH];

    long base = (long)b*TT*CC + h*DD;
    const float* Kg = g_k + base;
    const float* Qg = g_q + base;
    const float* Vg = g_v + base;
    const float* Fg = g_f + (long)b*TT*HH + h;
    float* Og = g_att + base;
    float* DstD = g_den + (long)bh*TT;

    unsigned long long Sa[4] = {0,0,0,0}, Sb[4] = {0,0,0,0};  // also denom state in w==2

    // staging indices: all 128 threads handle one k/q row-pair of float4s
    int s_ld = tid >> 3;          // row 0..15
    int p_ld = tid & 7;           // float4 pos 0..7 (plus +8 partner)
    int d0 = p_ld*4;
    int d1 = (p_ld+8)*4 + 4;
    int sv = tid >> 2, pvi = tid & 3;      // v staging (tid<64)

    float4 rk0, rk1, rq0, rq1, rc, rs4;
    float4 rv = make_float4(0,0,0,0);
    float rm = 1.0f, rmv = 1.0f, rf = 0.0f;

    auto prefetch = [&](int c) {
        int t = c*SCH + s_ld;
        long lo = (long)t*CC + p_ld*4;
        rk0 = *(const float4*)(Kg + lo);
        rk1 = *(const float4*)(Kg + lo + 32);
        rq0 = *(const float4*)(Qg + lo);
        rq1 = *(const float4*)(Qg + lo + 32);
        rc  = *(const float4*)(g_cos + t*32 + p_ld*4);
        rs4 = *(const float4*)(g_sin + t*32 + p_ld*4);
        rm  = (float)mask[b*TT + t];
        if (tid < 64) {
            int tv = c*SCH + sv;
            rv = *(const float4*)(Vg + (long)tv*CC + eh*16 + pvi*4);
            rmv = (float)mask[b*TT + tv];
        }
        if (tid >= 64 && tid < 64 + SCH) rf = Fg[(long)(c*SCH + tid - 64)*HH];
    };

    auto stage = [&](int buf) {
        float c1[4], c2[4], q1[4], q2[4];
        float cc[4] = {rc.x, rc.y, rc.z, rc.w};
        float ss[4] = {rs4.x, rs4.y, rs4.z, rs4.w};
        float k1[4] = {rk0.x, rk0.y, rk0.z, rk0.w};
        float k2[4] = {rk1.x, rk1.y, rk1.z, rk1.w};
        float u1[4] = {rq0.x, rq0.y, rq0.z, rq0.w};
        float u2[4] = {rq1.x, rq1.y, rq1.z, rq1.w};
        #pragma unroll
        for (int j = 0; j < 4; ++j) {
            c1[j] = phi_f(k1[j]*cc[j] - k2[j]*ss[j]) * rm;
            c2[j] = phi_f(k2[j]*cc[j] + k1[j]*ss[j]) * rm;
            q1[j] = phi_f(u1[j]*cc[j] - u2[j]*ss[j]) * rm;
            q2[j] = phi_f(u2[j]*cc[j] + u1[j]*ss[j]) * rm;
        }
        *(float4*)&ks[buf][s_ld][d0] = make_float4(c1[0], c1[1], c1[2], c1[3]);
        *(float4*)&ks[buf][s_ld][d1] = make_float4(c2[0], c2[1], c2[2], c2[3]);
        *(float4*)&qs[buf][s_ld][d0] = make_float4(q1[0], q1[1], q1[2], q1[3]);
        *(float4*)&qs[buf][s_ld][d1] = make_float4(q2[0], q2[1], q2[2], q2[3]);
        if (tid < 64)
            *(float4*)&vs[buf][sv][pvi*4] =
                make_float4(rv.x*rmv, rv.y*rmv, rv.z*rmv, rv.w*rmv);
        if (tid >= 64 && tid < 64 + SCH) fs[buf][tid - 64] = rf;
    };

    prefetch(0);
    int buf = 0;
    const int NCH = TT / SCH;
    for (int c = 0; c < NCH; ++c) {
        stage(buf);
        __syncthreads();
        if (c + 1 < NCH) prefetch(c + 1);

        if (w < 2) {
            #pragma unroll
            for (int s = 0; s < SCH; ++s) {
                float f = fs[buf][s];
                float2 vv = *(const float2*)&vs[buf][s][cp*2];
                unsigned long long f2 = pack2(f, f);
                unsigned long long va = pack2(vv.x, vv.x);
                unsigned long long vb = pack2(vv.y, vv.y);
                unsigned long long pa = 0ull, pb = 0ull;
                #pragma unroll
                for (int i = 0; i < 4; ++i) {
                    unsigned long long k2 = *(const unsigned long long*)&ks[buf][s][rbase + 2*i];
                    unsigned long long q2 = *(const unsigned long long*)&qs[buf][s][rbase + 2*i];
                    unsigned long long ta = mul2(Sa[i], f2);
                    FFMA2(ta, k2, va);
                    Sa[i] = ta;
                    FFMA2(pa, q2, ta);
                    unsigned long long tb = mul2(Sb[i], f2);
                    FFMA2(tb, k2, vb);
                    Sb[i] = tb;
                    FFMA2(pb, q2, tb);
                }
                float2 xa = unpack2(pa), xb = unpack2(pb);
                float ra = xa.x + xa.y, rb = xb.x + xb.y;
                ra += __shfl_xor_sync(0xFFFFFFFFu, ra, 1);
                rb += __shfl_xor_sync(0xFFFFFFFFu, rb, 1);
                ra += __shfl_xor_sync(0xFFFFFFFFu, ra, 2);
                rb += __shfl_xor_sync(0xFFFFFFFFu, rb, 2);
                ra += __shfl_xor_sync(0xFFFFFFFFu, ra, 4);
                rb += __shfl_xor_sync(0xFFFFFFFFu, rb, 4);
                if (oct == 0)
                    *(float2*)&Og[(long)(c*SCH + s)*CC + eh*16 + cp*2] = make_float2(ra, rb);
            }
        } else if (w == 2 && eh == 0 && l < 8) {
            #pragma unroll
            for (int s = 0; s < SCH; ++s) {
                float f = fs[buf][s];
                unsigned long long f2 = pack2(f, f);
                unsigned long long p2 = 0ull;
                #pragma unroll
                for (int i = 0; i < 4; ++i) {
                    unsigned long long k2 = *(const unsigned long long*)&ks[buf][s][rbase + 2*i];
                    unsigned long long q2 = *(const unsigned long long*)&qs[buf][s][rbase + 2*i];
                    unsigned long long t = mul2(Sa[i], f2);
                    FADD2(t, k2);
                    Sa[i] = t;
                    FFMA2(p2, q2, t);
                }
                float2 pp = unpack2(p2);
                float part = pp.x + pp.y;
                part += __shfl_xor_sync(0xFFu, part, 1);
                part += __shfl_xor_sync(0xFFu, part, 2);
                part += __shfl_xor_sync(0xFFu, part, 4);
                if (l == 0)
                    DstD[c*SCH + s] = 1.0f / fmaxf(part, 1e-6f);
            }
        }
        __syncthreads();
        buf ^= 1;
    }
}

// ---------- LayerNorm ----------
__global__ void __launch_bounds__(256) k_ln(const float* __restrict__ lw,
                                            const float* __restrict__ lb,
                                            float* __restrict__ out) {
    int row = blockIdx.x, tid = threadIdx.x;
    int w = tid >> 5, l = tid & 31;
    const float4* y4 = (const float4*)(g_z + (long)row*CC);
    float4 a = y4[tid];
    float s1 = a.x + a.y + a.z + a.w;
    float s2 = a.x*a.x + a.y*a.y + a.z*a.z + a.w*a.w;
    #pragma unroll
    for (int off = 16; off; off >>= 1) {
        s1 += __shfl_xor_sync(0xFFFFFFFFu, s1, off);
        s2 += __shfl_xor_sync(0xFFFFFFFFu, s2, off);
    }
    __shared__ float r1[8], r2[8];
    if (l == 0) { r1[w] = s1; r2[w] = s2; }
    __syncthreads();
    if (w == 0) {
        s1 = (l < 8) ? r1[l] : 0.0f;
        s2 = (l < 8) ? r2[l] : 0.0f;
        #pragma unroll
        for (int off = 4; off; off >>= 1) {
            s1 += __shfl_xor_sync(0xFFFFFFFFu, s1, off);
            s2 += __shfl_xor_sync(0xFFFFFFFFu, s2, off);
        }
        if (l == 0) { r1[0] = s1; r2[0] = s2; }
    }
    __syncthreads();
    float mu = r1[0] * (1.0f / CC);
    float var = r2[0] * (1.0f / CC) - mu*mu;
    float rs = rsqrtf(var + 1e-5f);
    float4 wv = ((const float4*)lw)[tid];
    float4 bv = ((const float4*)lb)[tid];
    float4 o;
    o.x = (a.x - mu)*rs*wv.x + bv.x;
    o.y = (a.y - mu)*rs*wv.y + bv.y;
    o.z = (a.z - mu)*rs*wv.z + bv.z;
    o.w = (a.w - mu)*rs*wv.w + bv.w;
    ((float4*)(out + (long)row*CC))[tid] = o;
}

extern "C" void kernel_launch(void* const* d_in, const int* in_sizes, int n_in,
                              void* d_out, int out_size) {
    (void)in_sizes; (void)n_in; (void)out_size;
    const float* x    = (const float*)d_in[0];
    const int*   mask = (const int*)  d_in[1];
    const float* Wq   = (const float*)d_in[2];
    const float* Wk   = (const float*)d_in[3];
    const float* Wv   = (const float*)d_in[4];
    const float* Wg   = (const float*)d_in[5];
    const float* bg   = (const float*)d_in[6];
    const float* Wo   = (const float*)d_in[7];
    const float* bo   = (const float*)d_in[8];
    const float* lw   = (const float*)d_in[9];
    const float* lb   = (const float*)d_in[10];
    float* out = (float*)d_out;

    cudaFuncSetAttribute(k_gemm_qkv, cudaFuncAttributeMaxDynamicSharedMemorySize, GEMM_DSMEM);
    cudaFuncSetAttribute(k_gemm_out, cudaFuncAttributeMaxDynamicSharedMemorySize, GEMM_DSMEM);

    k_cvtall<<<4096 + 1024, 256>>>(x, Wq, Wk, Wv, Wo);                  // 1
    k_misc<<<512, 256>>>(x, Wg, bg, mask);                              // 2
    k_gemm_qkv<<<dim3(CC/128, BT/128, 3), 256, GEMM_DSMEM>>>();         // 3
    k_scan<<<BB*HH*4, 128>>>(mask);                                     // 4 (ncu slot)
    k_cvtatt<<<(BT*CC/4)/256, 256>>>();                                 // 5
    k_gemm_out<<<dim3(CC/128, BT/128), 256, GEMM_DSMEM>>>(bo, x);       // 6
    k_ln<<<BT, 256>>>(lw, lb, out);                                     // 7
}

// round 10
// speedup vs baseline: 2.1625x; 1.0739x over previous
#include <cuda_runtime.h>
#include <cuda_bf16.h>
#include <math.h>

#define BB 2
#define TT 2048
#define CC 1024
#define HH 16
#define DD 64
#define BT (BB*TT)

// ---------- scratch ----------
__device__ float g_q[BT*CC];
__device__ float g_k[BT*CC];
__device__ float g_v[BT*CC];
__device__ float g_att[BT*CC];   // raw numerator
__device__ float g_z[BT*CC];
__device__ float g_f[BT*HH];
__device__ float g_den[BB*HH*TT];  // reciprocal of denom
__device__ float g_lc[BB*HH*TT];   // per-chunk log-f prefix
__device__ float g_cos[TT*32];
__device__ float g_sin[TT*32];

__device__ __nv_bfloat16 g_xh[BT*CC], g_xl[BT*CC];
__device__ __nv_bfloat16 g_ath[BT*CC], g_atl[BT*CC];
__device__ __nv_bfloat16 g_wh[4][CC*CC], g_wl[4][CC*CC];

// ---------- f32x2 helpers ----------
__device__ __forceinline__ unsigned long long pack2(float lo, float hi) {
    unsigned long long r;
    asm("mov.b64 %0, {%1, %2};" : "=l"(r) : "f"(lo), "f"(hi));
    return r;
}
__device__ __forceinline__ float2 unpack2(unsigned long long v) {
    float2 f;
    asm("mov.b64 {%0, %1}, %2;" : "=f"(f.x), "=f"(f.y) : "l"(v));
    return f;
}
#define FFMA2(acc, a, b) asm("fma.rn.f32x2 %0, %1, %2, %0;" : "+l"(acc) : "l"(a), "l"(b))

__device__ __forceinline__ float phi_f(float x) { return x > 0.0f ? x + 1.0f : expf(x); }

__device__ __forceinline__ unsigned smem_u32(const void* p) {
    unsigned a;
    asm("{ .reg .u64 t; cvta.to.shared.u64 t, %1; cvt.u32.u64 %0, t; }" : "=r"(a) : "l"(p));
    return a;
}

// ---------- cp.async / ldmatrix / mma ----------
#define CP_ASYNC16(dst, src) \
    asm volatile("cp.async.cg.shared.global [%0], [%1], 16;" :: "r"(dst), "l"(src))
#define CP_COMMIT() asm volatile("cp.async.commit_group;")
#define CP_WAIT1()  asm volatile("cp.async.wait_group 1;")

#define LDSM4(r, addr) \
    asm volatile("ldmatrix.sync.aligned.m8n8.x4.shared.b16 {%0,%1,%2,%3}, [%4];" \
        : "=r"((r)[0]), "=r"((r)[1]), "=r"((r)[2]), "=r"((r)[3]) : "r"(addr))

#define MMA_BF16(c, a, b) \
    asm volatile("mma.sync.aligned.m16n8k16.row.col.f32.bf16.bf16.f32 " \
                 "{%0,%1,%2,%3},{%4,%5,%6,%7},{%8,%9},{%0,%1,%2,%3};" \
                 : "+f"((c)[0]), "+f"((c)[1]), "+f"((c)[2]), "+f"((c)[3]) \
                 : "r"((a)[0]), "r"((a)[1]), "r"((a)[2]), "r"((a)[3]), \
                   "r"((b)[0]), "r"((b)[1]))

// ---------- fused fp32->bf16 hi/lo conversion ----------
__device__ __forceinline__ void split_store(float4 v, __nv_bfloat16* dh, __nv_bfloat16* dl, long idx) {
    float vv[4] = {v.x, v.y, v.z, v.w};
    unsigned short h[4], l[4];
    #pragma unroll
    for (int i = 0; i < 4; ++i) {
        __nv_bfloat16 hb = __float2bfloat16(vv[i]);
        h[i] = __bfloat16_as_ushort(hb);
        l[i] = __bfloat16_as_ushort(__float2bfloat16(vv[i] - __bfloat162float(hb)));
    }
    *(uint2*)(dh + idx) = make_uint2(h[0] | ((unsigned)h[1]<<16), h[2] | ((unsigned)h[3]<<16));
    *(uint2*)(dl + idx) = make_uint2(l[0] | ((unsigned)l[1]<<16), l[2] | ((unsigned)l[3]<<16));
}

__global__ void __launch_bounds__(256) k_cvtall(const float* __restrict__ x,
                                                const float* __restrict__ Wq,
                                                const float* __restrict__ Wk,
                                                const float* __restrict__ Wv,
                                                const float* __restrict__ Wo) {
    int id = blockIdx.x * blockDim.x + threadIdx.x;
    if (blockIdx.x < 4096) {
        float4 v = ((const float4*)x)[id];
        split_store(v, g_xh, g_xl, (long)id*4);
    } else {
        int wid = id - 4096*256;
        int seg = wid >> 16;
        int off = wid & 0xFFFF;
        const float* src = seg == 0 ? Wq : seg == 1 ? Wk : seg == 2 ? Wv : Wo;
        #pragma unroll
        for (int r = 0; r < 4; ++r) {
            int o = off + r * 65536;
            float4 v = ((const float4*)src)[o];
            split_store(v, g_wh[seg], g_wl[seg], (long)o*4);
        }
    }
}

// ---------- fused fgate (blocks 0..255) + trig (blocks 256..511) ----------
__global__ void __launch_bounds__(256) k_misc(const float* __restrict__ x,
                                              const float* __restrict__ Wg,
                                              const float* __restrict__ bg,
                                              const int* __restrict__ mask) {
    if (blockIdx.x < 256) {
        __shared__ float xs[16][64];
        __shared__ float wsT[64][17];
        int tid = threadIdx.x;
        int row0 = blockIdx.x * 16;
        int lr = tid >> 4, lq = tid & 15;
        float acc = 0.0f;
        for (int k0 = 0; k0 < CC; k0 += 64) {
            float4 xv = *(const float4*)&x[(long)(row0+lr)*CC + k0 + lq*4];
            *(float4*)&xs[lr][lq*4] = xv;
            float4 wv = *(const float4*)&Wg[(long)lr*CC + k0 + lq*4];
            wsT[lq*4+0][lr] = wv.x; wsT[lq*4+1][lr] = wv.y;
            wsT[lq*4+2][lr] = wv.z; wsT[lq*4+3][lr] = wv.w;
            __syncthreads();
            #pragma unroll
            for (int kk = 0; kk < 64; ++kk) acc = fmaf(xs[lr][kk], wsT[kk][lq], acc);
            __syncthreads();
        }
        float zv = acc + bg[lq];
        float f = 1.0f / (1.0f + expf(-zv));
        f = fminf(fmaxf(f, 0.01f), 0.999f);
        float mk = (float)mask[row0 + lr];
        f = f * mk + (1.0f - mk);
        g_f[(long)(row0 + lr)*HH + lq] = f;
    } else {
        int gid = (blockIdx.x - 256) * 256 + threadIdx.x;
        int t = gid >> 5, i = gid & 31;
        float e = (float)i * (1.0f / 32.0f);
        float inv = 1.0f / powf(10000.0f, e);
        float fr = (float)t * inv;
        g_cos[gid] = cosf(fr);
        g_sin[gid] = sinf(fr);
    }
}

// ---------- per-chunk log-f prefix: 32 blocks x 256 (warp per chunk) ----------
__global__ void __launch_bounds__(256) k_gates() {
    int bh = blockIdx.x;
    int b = bh >> 4, h = bh & 15;
    int tid = threadIdx.x;
    int w = tid >> 5, l = tid & 31;
    for (int cc = w; cc < 32; cc += 8) {
        int t0 = cc * 64;
        float f0 = g_f[(long)(b*TT + t0 + l)*HH + h];
        float f1 = g_f[(long)(b*TT + t0 + 32 + l)*HH + h];
        float l0 = logf(f0), l1 = logf(f1);
        #pragma unroll
        for (int o = 1; o < 32; o <<= 1) {
            float n = __shfl_up_sync(0xFFFFFFFFu, l0, o);
            if (l >= o) l0 += n;
        }
        #pragma unroll
        for (int o = 1; o < 32; o <<= 1) {
            float n = __shfl_up_sync(0xFFFFFFFFu, l1, o);
            if (l >= o) l1 += n;
        }
        l1 += __shfl_sync(0xFFFFFFFFu, l0, 31);
        g_lc[(long)bh*TT + t0 + l]      = l0;
        g_lc[(long)bh*TT + t0 + 32 + l] = l1;
    }
}

// ---------- normalize att + split to bf16 hi/lo ----------
__global__ void __launch_bounds__(256) k_cvtatt() {
    int id = blockIdx.x * blockDim.x + threadIdx.x;
    int elem = id * 4;
    int bt = elem >> 10;
    int rem = elem & 1023;
    int h = rem >> 6;
    int b = bt >> 11, t = bt & (TT - 1);
    float r = g_den[((long)(b*HH + h))*TT + t];
    float4 v = *(const float4*)(g_att + (long)elem);
    v.x *= r; v.y *= r; v.z *= r; v.w *= r;
    split_store(v, g_ath, g_atl, (long)elem);
}

// ---------- bf16x3 GEMM: BK=32, 3-stage cp.async; fused epilogues ----------
// mode 0: v (mask), 1: q/k (rope+phi+mask), 2: out (bias+resid)
#define GEMM_DSMEM (3*4*8192)

__device__ __forceinline__ void gemm_core(const __nv_bfloat16* __restrict__ Agh,
                                          const __nv_bfloat16* __restrict__ Agl,
                                          const __nv_bfloat16* __restrict__ Bgh,
                                          const __nv_bfloat16* __restrict__ Bgl,
                                          float* __restrict__ Cout,
                                          const float* __restrict__ bias,
                                          const float* __restrict__ resid,
                                          const int* __restrict__ mask,
                                          int mode)
{
    extern __shared__ __align__(16) char dynsm[];
    unsigned smb = smem_u32(dynsm);

    int tid = threadIdx.x;
    int m0 = blockIdx.y * 128;
    int n0 = blockIdx.x * 128;

    int prow = tid >> 1;
    int ph = tid & 1;
    const __nv_bfloat16* srcs[4];
    srcs[0] = Agh + (long)(m0 + prow) * CC + ph * 16;
    srcs[1] = Agl + (long)(m0 + prow) * CC + ph * 16;
    srcs[2] = Bgh + (long)(n0 + prow) * CC + ph * 16;
    srcs[3] = Bgl + (long)(n0 + prow) * CC + ph * 16;
    unsigned psw = (prow >> 1) & 3;
    unsigned d0off = prow * 64 + (((2u*ph) ^ psw) << 4);

    int warp = tid >> 5, lane = tid & 31;
    int g = lane >> 2, tg = lane & 3;
    int mbase = (warp >> 1) * 32;
    int nbase = (warp & 1) * 64;
    int lrow = lane & 15, lhi = lane >> 4;

    float c[2][8][4];
    #pragma unroll
    for (int mf = 0; mf < 2; ++mf)
        #pragma unroll
        for (int nf = 0; nf < 8; ++nf)
            #pragma unroll
            for (int j = 0; j < 4; ++j) c[mf][nf][j] = 0.0f;

    auto issue = [&](int kt) {
        unsigned sb = smb + (unsigned)(kt % 3) * 32768u;
        #pragma unroll
        for (int t = 0; t < 4; ++t) {
            const __nv_bfloat16* s = srcs[t] + kt * 32;
            unsigned d = sb + t * 8192 + d0off;
            CP_ASYNC16(d, s);
            CP_ASYNC16(d ^ 16u, s + 8);
        }
        CP_COMMIT();
    };

    auto lda = [&](unsigned sb, int t, int rowbase, int kh) -> unsigned {
        int r = rowbase + lrow;
        unsigned ch = (unsigned)(kh * 2 + lhi);
        return sb + t * 8192 + r * 64 + ((ch ^ ((unsigned)(r >> 1) & 3u)) << 4);
    };

    const int NT = CC / 32;
    issue(0);
    issue(1);

    for (int kt = 0; kt < NT; ++kt) {
        CP_WAIT1();
        __syncthreads();
        if (kt + 2 < NT) issue(kt + 2);

        unsigned sb = smb + (unsigned)(kt % 3) * 32768u;
        #pragma unroll
        for (int kh = 0; kh < 2; ++kh) {
            unsigned aH[2][4], aL[2][4];
            #pragma unroll
            for (int mf = 0; mf < 2; ++mf) {
                LDSM4(aH[mf], lda(sb, 0, mbase + mf*16, kh));
                LDSM4(aL[mf], lda(sb, 1, mbase + mf*16, kh));
            }
            #pragma unroll
            for (int nfp = 0; nfp < 4; ++nfp) {
                unsigned bh4[4], bl4[4];
                LDSM4(bh4, lda(sb, 2, nbase + nfp*16, kh));
                LDSM4(bl4, lda(sb, 3, nbase + nfp*16, kh));
                unsigned bh0[2] = {bh4[0], bh4[2]}, bh1[2] = {bh4[1], bh4[3]};
                unsigned bl0[2] = {bl4[0], bl4[2]}, bl1[2] = {bl4[1], bl4[3]};
                MMA_BF16(c[0][nfp*2],   aH[0], bh0);
                MMA_BF16(c[1][nfp*2],   aH[1], bh0);
                MMA_BF16(c[0][nfp*2+1], aH[0], bh1);
                MMA_BF16(c[1][nfp*2+1], aH[1], bh1);
                MMA_BF16(c[0][nfp*2],   aH[0], bl0);
                MMA_BF16(c[1][nfp*2],   aH[1], bl0);
                MMA_BF16(c[0][nfp*2+1], aH[0], bl1);
                MMA_BF16(c[1][nfp*2+1], aH[1], bl1);
                MMA_BF16(c[0][nfp*2],   aL[0], bh0);
                MMA_BF16(c[1][nfp*2],   aL[1], bh0);
                MMA_BF16(c[0][nfp*2+1], aL[0], bh1);
                MMA_BF16(c[1][nfp*2+1], aL[1], bh1);
            }
        }
    }

    // epilogue
    if (mode != 2) {
        #pragma unroll
        for (int mf = 0; mf < 2; ++mf) {
            int r0_ = m0 + mbase + mf*16 + g;
            float mk0 = (float)mask[r0_];
            float mk1 = (float)mask[r0_ + 8];
            if (mode == 0) {
                #pragma unroll
                for (int nf = 0; nf < 8; ++nf) {
                    c[mf][nf][0] *= mk0; c[mf][nf][1] *= mk0;
                    c[mf][nf][2] *= mk1; c[mf][nf][3] *= mk1;
                }
            } else {
                int t_0 = r0_ & (TT-1), t_1 = (r0_+8) & (TT-1);
                #pragma unroll
                for (int nf = 0; nf < 4; ++nf) {
                    #pragma unroll
                    for (int idx = 0; idx < 2; ++idx) {
                        int i = nf*8 + 2*tg + idx;
                        float c0 = g_cos[t_0*32 + i], s0 = g_sin[t_0*32 + i];
                        float c1 = g_cos[t_1*32 + i], s1 = g_sin[t_1*32 + i];
                        float x1a = c[mf][nf][idx],   x2a = c[mf][nf+4][idx];
                        float x1b = c[mf][nf][idx+2], x2b = c[mf][nf+4][idx+2];
                        c[mf][nf][idx]     = phi_f(x1a*c0 - x2a*s0) * mk0;
                        c[mf][nf+4][idx]   = phi_f(x2a*c0 + x1a*s0) * mk0;
                        c[mf][nf][idx+2]   = phi_f(x1b*c1 - x2b*s1) * mk1;
                        c[mf][nf+4][idx+2] = phi_f(x2b*c1 + x1b*s1) * mk1;
                    }
                }
            }
        }
    }

    #pragma unroll
    for (int mf = 0; mf < 2; ++mf) {
        #pragma unroll
        for (int nf = 0; nf < 8; ++nf) {
            int r = m0 + mbase + mf*16 + g;
            int col = n0 + nbase + nf*8 + 2*tg;
            float2 v0 = make_float2(c[mf][nf][0], c[mf][nf][1]);
            float2 v1 = make_float2(c[mf][nf][2], c[mf][nf][3]);
            if (mode == 2) {
                float b0 = bias[col], b1 = bias[col+1];
                v0.x += b0 + resid[(long)r*CC + col];
                v0.y += b1 + resid[(long)r*CC + col + 1];
                v1.x += b0 + resid[(long)(r+8)*CC + col];
                v1.y += b1 + resid[(long)(r+8)*CC + col + 1];
            }
            *(float2*)&Cout[(long)r*CC + col]     = v0;
            *(float2*)&Cout[(long)(r+8)*CC + col] = v1;
        }
    }
}

__global__ void __launch_bounds__(256, 2) k_gemm_qkv(const int* __restrict__ mask) {
    int z = blockIdx.z;
    float* out = z == 0 ? g_q : (z == 1 ? g_k : g_v);
    gemm_core(g_xh, g_xl, g_wh[z], g_wl[z], out, nullptr, nullptr, mask, z == 2 ? 0 : 1);
}

__global__ void __launch_bounds__(256, 2) k_gemm_out(const float* __restrict__ bo,
                                                     const float* __restrict__ x) {
    gemm_core(g_ath, g_atl, g_wh[3], g_wl[3], g_z, bo, x, nullptr, 2);
}

// ---------- chunked scan: 64 blocks (bh x e-half) x 128 threads ----------
struct ScanSmem {
    float Qt[64][68];   // [d][t]
    float Kt[64][68];   // [d][t]
    float At[64][68];   // [s][t]
    float V[64][36];    // [s][e]
    float S0[64][36];   // [d][e]
    float Lc[64], Ft[64], RL[64], m0[64];
};
#define SCAN_DSMEM ((int)sizeof(ScanSmem))

__global__ void __launch_bounds__(128) k_scan() {
    extern __shared__ __align__(16) char sbuf[];
    ScanSmem* sm = (ScanSmem*)sbuf;
    int bh = blockIdx.x >> 1;
    int eh = blockIdx.x & 1;
    int b = bh >> 4, h = bh & 15;
    int tid = threadIdx.x;

    long base = (long)b*TT*CC + h*DD;
    const float* Qg = g_q + base;
    const float* Kg = g_k + base;
    const float* Vg = g_v + base;
    const float* Lcg = g_lc + (long)bh*TT;
    float* Og = g_att + base;
    float* Dg = g_den + (long)bh*TT;

    for (int i = tid; i < 64*36; i += 128) ((float*)sm->S0)[i] = 0.0f;
    if (tid < 64) sm->m0[tid] = 0.0f;
    __syncthreads();

    for (int c = 0; c < TT/64; ++c) {
        // ---- stage (transpose q,k; copy v-half; gates) ----
        {
            int t = tid >> 1, db = (tid & 1) * 32;
            const float* qp = Qg + (long)(c*64 + t)*CC + db;
            const float* kp = Kg + (long)(c*64 + t)*CC + db;
            #pragma unroll
            for (int j4 = 0; j4 < 8; ++j4) {
                float4 qv = *(const float4*)(qp + j4*4);
                float4 kv = *(const float4*)(kp + j4*4);
                int d = db + j4*4;
                sm->Qt[d+0][t] = qv.x; sm->Qt[d+1][t] = qv.y;
                sm->Qt[d+2][t] = qv.z; sm->Qt[d+3][t] = qv.w;
                sm->Kt[d+0][t] = kv.x; sm->Kt[d+1][t] = kv.y;
                sm->Kt[d+2][t] = kv.z; sm->Kt[d+3][t] = kv.w;
            }
            int s = tid >> 1, part = (tid & 1) * 16;
            const float* vp = Vg + (long)(c*64 + s)*CC + eh*32 + part;
            #pragma unroll
            for (int j4 = 0; j4 < 4; ++j4)
                *(float4*)&sm->V[s][part + j4*4] = *(const float4*)(vp + j4*4);
            if (tid < 64) {
                float lc = Lcg[c*64 + tid];
                float lcl = Lcg[c*64 + 63];
                sm->Lc[tid] = lc;
                sm->Ft[tid] = __expf(lc);
                sm->RL[tid] = __expf(lcl - lc);
            }
        }
        __syncthreads();

        // ---- A phase: A[t][s] = (q_t.k_s) * exp(Lc_t-Lc_s), s<=t ----
        {
            int t0 = (tid & 7) * 8, s0 = (tid >> 3) * 4;
            unsigned long long acc[4][4];
            #pragma unroll
            for (int i = 0; i < 4; ++i)
                #pragma unroll
                for (int j = 0; j < 4; ++j) acc[i][j] = 0ull;
            #pragma unroll 4
            for (int d = 0; d < 64; ++d) {
                float4 q0 = *(const float4*)&sm->Qt[d][t0];
                float4 q1 = *(const float4*)&sm->Qt[d][t0+4];
                float4 kv = *(const float4*)&sm->Kt[d][s0];
                unsigned long long qp_[4] = {
                    pack2(q0.x, q0.y), pack2(q0.z, q0.w),
                    pack2(q1.x, q1.y), pack2(q1.z, q1.w)
                };
                float ks[4] = {kv.x, kv.y, kv.z, kv.w};
                #pragma unroll
                for (int si = 0; si < 4; ++si) {
                    unsigned long long k2 = pack2(ks[si], ks[si]);
                    FFMA2(acc[si][0], qp_[0], k2);
                    FFMA2(acc[si][1], qp_[1], k2);
                    FFMA2(acc[si][2], qp_[2], k2);
                    FFMA2(acc[si][3], qp_[3], k2);
                }
            }
            #pragma unroll
            for (int si = 0; si < 4; ++si) {
                int s = s0 + si;
                float row[8];
                #pragma unroll
                for (int tp = 0; tp < 4; ++tp) {
                    float2 p = unpack2(acc[si][tp]);
                    row[tp*2] = p.x; row[tp*2+1] = p.y;
                }
                float lcs = sm->Lc[s];
                #pragma unroll
                for (int tj = 0; tj < 8; ++tj) {
                    int t = t0 + tj;
                    row[tj] = (s <= t) ? row[tj] * __expf(sm->Lc[t] - lcs) : 0.0f;
                }
                *(float4*)&sm->At[s][t0]   = make_float4(row[0], row[1], row[2], row[3]);
                *(float4*)&sm->At[s][t0+4] = make_float4(row[4], row[5], row[6], row[7]);
            }
        }
        __syncthreads();

        // ---- denominator (eh==0, threads<64): den = Ft*(q.m0) + rowsum(A) ----
        if (eh == 0 && tid < 64) {
            int t = tid;
            float qm = 0.0f, rs = 0.0f;
            #pragma unroll 8
            for (int d = 0; d < 64; ++d) qm += sm->Qt[d][t] * sm->m0[d];
            #pragma unroll 8
            for (int s = 0; s < 64; ++s) rs += sm->At[s][t];
            float den = sm->Ft[t] * qm + rs;
            Dg[c*64 + t] = 1.0f / fmaxf(den, 1e-6f);
        }

        // ---- out phase: out = Ft*(Q@S0) + A@V ----
        {
            int t0 = (tid >> 3) * 4, e0 = (tid & 7) * 4;
            unsigned long long a1[4][2], a2[4][2];
            #pragma unroll
            for (int i = 0; i < 4; ++i) {
                a1[i][0] = a1[i][1] = 0ull;
                a2[i][0] = a2[i][1] = 0ull;
            }
            #pragma unroll 8
            for (int d = 0; d < 64; ++d) {
                float4 qv = *(const float4*)&sm->Qt[d][t0];
                float4 sv = *(const float4*)&sm->S0[d][e0];
                unsigned long long s01 = pack2(sv.x, sv.y), s23 = pack2(sv.z, sv.w);
                float qq[4] = {qv.x, qv.y, qv.z, qv.w};
                #pragma unroll
                for (int ti = 0; ti < 4; ++ti) {
                    unsigned long long q2 = pack2(qq[ti], qq[ti]);
                    FFMA2(a1[ti][0], q2, s01);
                    FFMA2(a1[ti][1], q2, s23);
                }
            }
            #pragma unroll 8
            for (int s = 0; s < 64; ++s) {
                float4 av = *(const float4*)&sm->At[s][t0];
                float4 vv = *(const float4*)&sm->V[s][e0];
                unsigned long long v01 = pack2(vv.x, vv.y), v23 = pack2(vv.z, vv.w);
                float aa[4] = {av.x, av.y, av.z, av.w};
                #pragma unroll
                for (int ti = 0; ti < 4; ++ti) {
                    unsigned long long a2r = pack2(aa[ti], aa[ti]);
                    FFMA2(a2[ti][0], a2r, v01);
                    FFMA2(a2[ti][1], a2r, v23);
                }
            }
            #pragma unroll
            for (int ti = 0; ti < 4; ++ti) {
                float F = sm->Ft[t0 + ti];
                float2 p01 = unpack2(a1[ti][0]), p23 = unpack2(a1[ti][1]);
                float2 r01 = unpack2(a2[ti][0]), r23 = unpack2(a2[ti][1]);
                float4 o;
                o.x = F*p01.x + r01.x; o.y = F*p01.y + r01.y;
                o.z = F*p23.x + r23.x; o.w = F*p23.y + r23.y;
                *(float4*)&Og[(long)(c*64 + t0 + ti)*CC + eh*32 + e0] = o;
            }
        }
        __syncthreads();

        // ---- state update: S0 = FL*S0 + (RL*K)^T @ V ; m0 = FL*m0 + sum RL*k ----
        {
            int d0 = (tid >> 3) * 4, e0 = (tid & 7) * 4;
            unsigned long long acc[4][2];
            #pragma unroll
            for (int i = 0; i < 4; ++i) { acc[i][0] = acc[i][1] = 0ull; }
            #pragma unroll 8
            for (int s = 0; s < 64; ++s) {
                float rl = sm->RL[s];
                float4 vv = *(const float4*)&sm->V[s][e0];
                unsigned long long v01 = pack2(vv.x, vv.y), v23 = pack2(vv.z, vv.w);
                #pragma unroll
                for (int di = 0; di < 4; ++di) {
                    float kk = sm->Kt[d0+di][s] * rl;
                    unsigned long long k2 = pack2(kk, kk);
                    FFMA2(acc[di][0], k2, v01);
                    FFMA2(acc[di][1], k2, v23);
                }
            }
            float FL = sm->Ft[63];
            #pragma unroll
            for (int di = 0; di < 4; ++di) {
                float4 so = *(float4*)&sm->S0[d0+di][e0];
                float2 a01 = unpack2(acc[di][0]), a23 = unpack2(acc[di][1]);
                so.x = FL*so.x + a01.x; so.y = FL*so.y + a01.y;
                so.z = FL*so.z + a23.x; so.w = FL*so.w + a23.y;
                *(float4*)&sm->S0[d0+di][e0] = so;
            }
            if (eh == 0 && tid < 64) {
                int d = tid;
                float am = 0.0f;
                #pragma unroll 8
                for (int s = 0; s < 64; ++s) am += sm->RL[s] * sm->Kt[d][s];
                sm->m0[d] = FL * sm->m0[d] + am;
            }
        }
        __syncthreads();
    }
}

// ---------- LayerNorm ----------
__global__ void __launch_bounds__(256) k_ln(const float* __restrict__ lw,
                                            const float* __restrict__ lb,
                                            float* __restrict__ out) {
    int row = blockIdx.x, tid = threadIdx.x;
    int w = tid >> 5, l = tid & 31;
    const float4* y4 = (const float4*)(g_z + (long)row*CC);
    float4 a = y4[tid];
    float s1 = a.x + a.y + a.z + a.w;
    float s2 = a.x*a.x + a.y*a.y + a.z*a.z + a.w*a.w;
    #pragma unroll
    for (int off = 16; off; off >>= 1) {
        s1 += __shfl_xor_sync(0xFFFFFFFFu, s1, off);
        s2 += __shfl_xor_sync(0xFFFFFFFFu, s2, off);
    }
    __shared__ float r1[8], r2[8];
    if (l == 0) { r1[w] = s1; r2[w] = s2; }
    __syncthreads();
    if (w == 0) {
        s1 = (l < 8) ? r1[l] : 0.0f;
        s2 = (l < 8) ? r2[l] : 0.0f;
        #pragma unroll
        for (int off = 4; off; off >>= 1) {
            s1 += __shfl_xor_sync(0xFFFFFFFFu, s1, off);
            s2 += __shfl_xor_sync(0xFFFFFFFFu, s2, off);
        }
        if (l == 0) { r1[0] = s1; r2[0] = s2; }
    }
    __syncthreads();
    float mu = r1[0] * (1.0f / CC);
    float var = r2[0] * (1.0f / CC) - mu*mu;
    float rs = rsqrtf(var + 1e-5f);
    float4 wv = ((const float4*)lw)[tid];
    float4 bv = ((const float4*)lb)[tid];
    float4 o;
    o.x = (a.x - mu)*rs*wv.x + bv.x;
    o.y = (a.y - mu)*rs*wv.y + bv.y;
    o.z = (a.z - mu)*rs*wv.z + bv.z;
    o.w = (a.w - mu)*rs*wv.w + bv.w;
    ((float4*)(out + (long)row*CC))[tid] = o;
}

extern "C" void kernel_launch(void* const* d_in, const int* in_sizes, int n_in,
                              void* d_out, int out_size) {
    (void)in_sizes; (void)n_in; (void)out_size;
    const float* x    = (const float*)d_in[0];
    const int*   mask = (const int*)  d_in[1];
    const float* Wq   = (const float*)d_in[2];
    const float* Wk   = (const float*)d_in[3];
    const float* Wv   = (const float*)d_in[4];
    const float* Wg   = (const float*)d_in[5];
    const float* bg   = (const float*)d_in[6];
    const float* Wo   = (const float*)d_in[7];
    const float* bo   = (const float*)d_in[8];
    const float* lw   = (const float*)d_in[9];
    const float* lb   = (const float*)d_in[10];
    float* out = (float*)d_out;

    cudaFuncSetAttribute(k_gemm_qkv, cudaFuncAttributeMaxDynamicSharedMemorySize, GEMM_DSMEM);
    cudaFuncSetAttribute(k_gemm_out, cudaFuncAttributeMaxDynamicSharedMemorySize, GEMM_DSMEM);
    cudaFuncSetAttribute(k_scan, cudaFuncAttributeMaxDynamicSharedMemorySize, SCAN_DSMEM);

    k_cvtall<<<4096 + 1024, 256>>>(x, Wq, Wk, Wv, Wo);                   // 1
    k_misc<<<512, 256>>>(x, Wg, bg, mask);                               // 2
    k_gates<<<BB*HH, 256>>>();                                           // 3
    k_gemm_qkv<<<dim3(CC/128, BT/128, 3), 256, GEMM_DSMEM>>>(mask);      // 4 (ncu slot)
    k_scan<<<BB*HH*2, 128, SCAN_DSMEM>>>();                              // 5
    k_cvtatt<<<(BT*CC/4)/256, 256>>>();                                  // 6
    k_gemm_out<<<dim3(CC/128, BT/128), 256, GEMM_DSMEM>>>(bo, x);        // 7
    k_ln<<<BT, 256>>>(lw, lb, out);                                      // 8
}

// round 12
// speedup vs baseline: 2.7374x; 1.2659x over previous
#include <cuda_runtime.h>
#include <cuda_bf16.h>
#include <math.h>

#define BB 2
#define TT 2048
#define CC 1024
#define HH 16
#define DD 64
#define BT (BB*TT)

// ---------- scratch ----------
__device__ float g_q[BT*CC];
__device__ float g_k[BT*CC];
__device__ float g_v[BT*CC];
__device__ float g_att[BT*CC];   // raw numerator
__device__ float g_z[BT*CC];
__device__ float g_f[BT*HH];
__device__ float g_den[BB*HH*TT];  // reciprocal of denom
__device__ float g_cos[TT*32];
__device__ float g_sin[TT*32];

__device__ __nv_bfloat16 g_xh[BT*CC], g_xl[BT*CC];
__device__ __nv_bfloat16 g_ath[BT*CC], g_atl[BT*CC];
__device__ __nv_bfloat16 g_wh[4][CC*CC], g_wl[4][CC*CC];

__device__ __forceinline__ float phi_f(float x) { return x > 0.0f ? x + 1.0f : expf(x); }

__device__ __forceinline__ unsigned smem_u32(const void* p) {
    unsigned a;
    asm("{ .reg .u64 t; cvta.to.shared.u64 t, %1; cvt.u32.u64 %0, t; }" : "=r"(a) : "l"(p));
    return a;
}

// ---------- cp.async / ldmatrix / mma ----------
#define CP_ASYNC16(dst, src) \
    asm volatile("cp.async.cg.shared.global [%0], [%1], 16;" :: "r"(dst), "l"(src))
#define CP_COMMIT() asm volatile("cp.async.commit_group;")
#define CP_WAIT1()  asm volatile("cp.async.wait_group 1;")

#define LDSM4(r, addr) \
    asm volatile("ldmatrix.sync.aligned.m8n8.x4.shared.b16 {%0,%1,%2,%3}, [%4];" \
        : "=r"((r)[0]), "=r"((r)[1]), "=r"((r)[2]), "=r"((r)[3]) : "r"(addr))

#define MMA_BF16(c, a, b) \
    asm volatile("mma.sync.aligned.m16n8k16.row.col.f32.bf16.bf16.f32 " \
                 "{%0,%1,%2,%3},{%4,%5,%6,%7},{%8,%9},{%0,%1,%2,%3};" \
                 : "+f"((c)[0]), "+f"((c)[1]), "+f"((c)[2]), "+f"((c)[3]) \
                 : "r"((a)[0]), "r"((a)[1]), "r"((a)[2]), "r"((a)[3]), \
                   "r"((b)[0]), "r"((b)[1]))

// ---------- bf16 hi/lo split stores ----------
__device__ __forceinline__ void store_hl(__nv_bfloat16* H, __nv_bfloat16* L, int idx,
                                         float v0, float v1) {
    __nv_bfloat16 h0 = __float2bfloat16(v0), h1 = __float2bfloat16(v1);
    __nv_bfloat162 hh; hh.x = h0; hh.y = h1;
    *(__nv_bfloat162*)(H + idx) = hh;
    __nv_bfloat162 ll;
    ll.x = __float2bfloat16(v0 - __bfloat162float(h0));
    ll.y = __float2bfloat16(v1 - __bfloat162float(h1));
    *(__nv_bfloat162*)(L + idx) = ll;
}

__device__ __forceinline__ void split_store(float4 v, __nv_bfloat16* dh, __nv_bfloat16* dl, long idx) {
    float vv[4] = {v.x, v.y, v.z, v.w};
    unsigned short h[4], l[4];
    #pragma unroll
    for (int i = 0; i < 4; ++i) {
        __nv_bfloat16 hb = __float2bfloat16(vv[i]);
        h[i] = __bfloat16_as_ushort(hb);
        l[i] = __bfloat16_as_ushort(__float2bfloat16(vv[i] - __bfloat162float(hb)));
    }
    *(uint2*)(dh + idx) = make_uint2(h[0] | ((unsigned)h[1]<<16), h[2] | ((unsigned)h[3]<<16));
    *(uint2*)(dl + idx) = make_uint2(l[0] | ((unsigned)l[1]<<16), l[2] | ((unsigned)l[3]<<16));
}

__global__ void __launch_bounds__(256) k_cvtall(const float* __restrict__ x,
                                                const float* __restrict__ Wq,
                                                const float* __restrict__ Wk,
                                                const float* __restrict__ Wv,
                                                const float* __restrict__ Wo) {
    int id = blockIdx.x * blockDim.x + threadIdx.x;
    if (blockIdx.x < 4096) {
        float4 v = ((const float4*)x)[id];
        split_store(v, g_xh, g_xl, (long)id*4);
    } else {
        int wid = id - 4096*256;
        int seg = wid >> 16;
        int off = wid & 0xFFFF;
        const float* src = seg == 0 ? Wq : seg == 1 ? Wk : seg == 2 ? Wv : Wo;
        #pragma unroll
        for (int r = 0; r < 4; ++r) {
            int o = off + r * 65536;
            float4 v = ((const float4*)src)[o];
            split_store(v, g_wh[seg], g_wl[seg], (long)o*4);
        }
    }
}

// ---------- fused fgate (blocks 0..255) + trig (blocks 256..511) ----------
__global__ void __launch_bounds__(256) k_misc(const float* __restrict__ x,
                                              const float* __restrict__ Wg,
                                              const float* __restrict__ bg,
                                              const int* __restrict__ mask) {
    if (blockIdx.x < 256) {
        __shared__ float xs[16][64];
        __shared__ float wsT[64][17];
        int tid = threadIdx.x;
        int row0 = blockIdx.x * 16;
        int lr = tid >> 4, lq = tid & 15;
        float acc = 0.0f;
        for (int k0 = 0; k0 < CC; k0 += 64) {
            float4 xv = *(const float4*)&x[(long)(row0+lr)*CC + k0 + lq*4];
            *(float4*)&xs[lr][lq*4] = xv;
            float4 wv = *(const float4*)&Wg[(long)lr*CC + k0 + lq*4];
            wsT[lq*4+0][lr] = wv.x; wsT[lq*4+1][lr] = wv.y;
            wsT[lq*4+2][lr] = wv.z; wsT[lq*4+3][lr] = wv.w;
            __syncthreads();
            #pragma unroll
            for (int kk = 0; kk < 64; ++kk) acc = fmaf(xs[lr][kk], wsT[kk][lq], acc);
            __syncthreads();
        }
        float zv = acc + bg[lq];
        float f = 1.0f / (1.0f + expf(-zv));
        f = fminf(fmaxf(f, 0.01f), 0.999f);
        float mk = (float)mask[row0 + lr];
        f = f * mk + (1.0f - mk);
        g_f[(long)(row0 + lr)*HH + lq] = f;
    } else {
        int gid = (blockIdx.x - 256) * 256 + threadIdx.x;
        int t = gid >> 5, i = gid & 31;
        float e = (float)i * (1.0f / 32.0f);
        float inv = 1.0f / powf(10000.0f, e);
        float fr = (float)t * inv;
        g_cos[gid] = cosf(fr);
        g_sin[gid] = sinf(fr);
    }
}

// ---------- normalize att + split to bf16 hi/lo ----------
__global__ void __launch_bounds__(256) k_cvtatt() {
    int id = blockIdx.x * blockDim.x + threadIdx.x;
    int elem = id * 4;
    int bt = elem >> 10;
    int rem = elem & 1023;
    int h = rem >> 6;
    int b = bt >> 11, t = bt & (TT - 1);
    float r = g_den[((long)(b*HH + h))*TT + t];
    float4 v = *(const float4*)(g_att + (long)elem);
    v.x *= r; v.y *= r; v.z *= r; v.w *= r;
    split_store(v, g_ath, g_atl, (long)elem);
}

// ---------- bf16x3 GEMM: BK=32, 3-stage cp.async; fused epilogues ----------
#define GEMM_DSMEM (3*4*8192)

__device__ __forceinline__ void gemm_core(const __nv_bfloat16* __restrict__ Agh,
                                          const __nv_bfloat16* __restrict__ Agl,
                                          const __nv_bfloat16* __restrict__ Bgh,
                                          const __nv_bfloat16* __restrict__ Bgl,
                                          float* __restrict__ Cout,
                                          const float* __restrict__ bias,
                                          const float* __restrict__ resid,
                                          const int* __restrict__ mask,
                                          int mode)
{
    extern __shared__ __align__(16) char dynsm[];
    unsigned smb = smem_u32(dynsm);

    int tid = threadIdx.x;
    int m0 = blockIdx.y * 128;
    int n0 = blockIdx.x * 128;

    int prow = tid >> 1;
    int ph = tid & 1;
    const __nv_bfloat16* srcs[4];
    srcs[0] = Agh + (long)(m0 + prow) * CC + ph * 16;
    srcs[1] = Agl + (long)(m0 + prow) * CC + ph * 16;
    srcs[2] = Bgh + (long)(n0 + prow) * CC + ph * 16;
    srcs[3] = Bgl + (long)(n0 + prow) * CC + ph * 16;
    unsigned psw = (prow >> 1) & 3;
    unsigned d0off = prow * 64 + (((2u*ph) ^ psw) << 4);

    int warp = tid >> 5, lane = tid & 31;
    int g = lane >> 2, tg = lane & 3;
    int mbase = (warp >> 1) * 32;
    int nbase = (warp & 1) * 64;
    int lrow = lane & 15, lhi = lane >> 4;

    float c[2][8][4];
    #pragma unroll
    for (int mf = 0; mf < 2; ++mf)
        #pragma unroll
        for (int nf = 0; nf < 8; ++nf)
            #pragma unroll
            for (int j = 0; j < 4; ++j) c[mf][nf][j] = 0.0f;

    auto issue = [&](int kt) {
        unsigned sb = smb + (unsigned)(kt % 3) * 32768u;
        #pragma unroll
        for (int t = 0; t < 4; ++t) {
            const __nv_bfloat16* s = srcs[t] + kt * 32;
            unsigned d = sb + t * 8192 + d0off;
            CP_ASYNC16(d, s);
            CP_ASYNC16(d ^ 16u, s + 8);
        }
        CP_COMMIT();
    };

    auto lda = [&](unsigned sb, int t, int rowbase, int kh) -> unsigned {
        int r = rowbase + lrow;
        unsigned ch = (unsigned)(kh * 2 + lhi);
        return sb + t * 8192 + r * 64 + ((ch ^ ((unsigned)(r >> 1) & 3u)) << 4);
    };

    const int NT = CC / 32;
    issue(0);
    issue(1);

    for (int kt = 0; kt < NT; ++kt) {
        CP_WAIT1();
        __syncthreads();
        if (kt + 2 < NT) issue(kt + 2);

        unsigned sb = smb + (unsigned)(kt % 3) * 32768u;
        #pragma unroll
        for (int kh = 0; kh < 2; ++kh) {
            unsigned aH[2][4], aL[2][4];
            #pragma unroll
            for (int mf = 0; mf < 2; ++mf) {
                LDSM4(aH[mf], lda(sb, 0, mbase + mf*16, kh));
                LDSM4(aL[mf], lda(sb, 1, mbase + mf*16, kh));
            }
            #pragma unroll
            for (int nfp = 0; nfp < 4; ++nfp) {
                unsigned bh4[4], bl4[4];
                LDSM4(bh4, lda(sb, 2, nbase + nfp*16, kh));
                LDSM4(bl4, lda(sb, 3, nbase + nfp*16, kh));
                unsigned bh0[2] = {bh4[0], bh4[2]}, bh1[2] = {bh4[1], bh4[3]};
                unsigned bl0[2] = {bl4[0], bl4[2]}, bl1[2] = {bl4[1], bl4[3]};
                MMA_BF16(c[0][nfp*2],   aH[0], bh0);
                MMA_BF16(c[1][nfp*2],   aH[1], bh0);
                MMA_BF16(c[0][nfp*2+1], aH[0], bh1);
                MMA_BF16(c[1][nfp*2+1], aH[1], bh1);
                MMA_BF16(c[0][nfp*2],   aH[0], bl0);
                MMA_BF16(c[1][nfp*2],   aH[1], bl0);
                MMA_BF16(c[0][nfp*2+1], aH[0], bl1);
                MMA_BF16(c[1][nfp*2+1], aH[1], bl1);
                MMA_BF16(c[0][nfp*2],   aL[0], bh0);
                MMA_BF16(c[1][nfp*2],   aL[1], bh0);
                MMA_BF16(c[0][nfp*2+1], aL[0], bh1);
                MMA_BF16(c[1][nfp*2+1], aL[1], bh1);
            }
        }
    }

    if (mode != 2) {
        #pragma unroll
        for (int mf = 0; mf < 2; ++mf) {
            int r0_ = m0 + mbase + mf*16 + g;
            float mk0 = (float)mask[r0_];
            float mk1 = (float)mask[r0_ + 8];
            if (mode == 0) {
                #pragma unroll
                for (int nf = 0; nf < 8; ++nf) {
                    c[mf][nf][0] *= mk0; c[mf][nf][1] *= mk0;
                    c[mf][nf][2] *= mk1; c[mf][nf][3] *= mk1;
                }
            } else {
                int t_0 = r0_ & (TT-1), t_1 = (r0_+8) & (TT-1);
                #pragma unroll
                for (int nf = 0; nf < 4; ++nf) {
                    #pragma unroll
                    for (int idx = 0; idx < 2; ++idx) {
                        int i = nf*8 + 2*tg + idx;
                        float c0 = g_cos[t_0*32 + i], s0 = g_sin[t_0*32 + i];
                        float c1 = g_cos[t_1*32 + i], s1 = g_sin[t_1*32 + i];
                        float x1a = c[mf][nf][idx],   x2a = c[mf][nf+4][idx];
                        float x1b = c[mf][nf][idx+2], x2b = c[mf][nf+4][idx+2];
                        c[mf][nf][idx]     = phi_f(x1a*c0 - x2a*s0) * mk0;
                        c[mf][nf+4][idx]   = phi_f(x2a*c0 + x1a*s0) * mk0;
                        c[mf][nf][idx+2]   = phi_f(x1b*c1 - x2b*s1) * mk1;
                        c[mf][nf+4][idx+2] = phi_f(x2b*c1 + x1b*s1) * mk1;
                    }
                }
            }
        }
    }

    #pragma unroll
    for (int mf = 0; mf < 2; ++mf) {
        #pragma unroll
        for (int nf = 0; nf < 8; ++nf) {
            int r = m0 + mbase + mf*16 + g;
            int col = n0 + nbase + nf*8 + 2*tg;
            float2 v0 = make_float2(c[mf][nf][0], c[mf][nf][1]);
            float2 v1 = make_float2(c[mf][nf][2], c[mf][nf][3]);
            if (mode == 2) {
                float b0 = bias[col], b1 = bias[col+1];
                v0.x += b0 + resid[(long)r*CC + col];
                v0.y += b1 + resid[(long)r*CC + col + 1];
                v1.x += b0 + resid[(long)(r+8)*CC + col];
                v1.y += b1 + resid[(long)(r+8)*CC + col + 1];
            }
            *(float2*)&Cout[(long)r*CC + col]     = v0;
            *(float2*)&Cout[(long)(r+8)*CC + col] = v1;
        }
    }
}

__global__ void __launch_bounds__(256, 2) k_gemm_qkv(const int* __restrict__ mask) {
    int z = blockIdx.z;
    float* out = z == 0 ? g_q : (z == 1 ? g_k : g_v);
    gemm_core(g_xh, g_xl, g_wh[z], g_wl[z], out, nullptr, nullptr, mask, z == 2 ? 0 : 1);
}

__global__ void __launch_bounds__(256, 2) k_gemm_out(const float* __restrict__ bo,
                                                     const float* __restrict__ x) {
    gemm_core(g_ath, g_atl, g_wh[3], g_wl[3], g_z, bo, x, nullptr, 2);
}

// ---------- tensor-core chunked scan: 32 blocks x 256 threads ----------
#define SROWB 72
struct ScanSM {
    __nv_bfloat16 Qh[64][SROWB], Ql[64][SROWB];
    __nv_bfloat16 Kh[64][SROWB], Kl[64][SROWB];
    __nv_bfloat16 Kth[64][SROWB], Ktl[64][SROWB];
    __nv_bfloat16 Vth[64][SROWB], Vtl[64][SROWB];
    __nv_bfloat16 Vph[64][SROWB], Vpl[64][SROWB];
    __nv_bfloat16 Ah[64][SROWB], Al[64][SROWB];
    __nv_bfloat16 Sh[64][SROWB], Sl[64][SROWB];
    float Kf[64][65];
    float Vf[64][65];
    float Lc[64], Ft[64], RL[64];
    float m0[2][64];
};
#define SCAN_DSMEM ((int)sizeof(ScanSM))

__global__ void __launch_bounds__(256) k_scan() {
    extern __shared__ __align__(16) char sbuf[];
    ScanSM* sm = (ScanSM*)sbuf;
    int bh = blockIdx.x;
    int b = bh >> 4, h = bh & 15;
    int tid = threadIdx.x;
    int w = tid >> 5, lane = tid & 31;
    int g = lane >> 2, tg = lane & 3;
    int lrow = lane & 15, lhi = lane >> 4;
    int wm = (w >> 1) * 16;      // row-tile (t or e)
    int wn = (w & 1) * 32;       // col-tile (s, e, or d)

    long base = (long)b*TT*CC + h*DD;
    const float* Qg = g_q + base;
    const float* Kg = g_k + base;
    const float* Vg = g_v + base;
    float* Og = g_att + base;
    float* Dg = g_den + (long)bh*TT;

    unsigned bQh = smem_u32(sm->Qh),  bQl = smem_u32(sm->Ql);
    unsigned bKh = smem_u32(sm->Kh),  bKl = smem_u32(sm->Kl);
    unsigned bKth = smem_u32(sm->Kth), bKtl = smem_u32(sm->Ktl);
    unsigned bVth = smem_u32(sm->Vth), bVtl = smem_u32(sm->Vtl);
    unsigned bVph = smem_u32(sm->Vph), bVpl = smem_u32(sm->Vpl);
    unsigned bAh = smem_u32(sm->Ah),  bAl = smem_u32(sm->Al);
    unsigned bSh = smem_u32(sm->Sh),  bSl = smem_u32(sm->Sl);

    auto fa = [&](unsigned bbase, int rowbase, int ks) -> unsigned {
        return bbase + (unsigned)((rowbase + lrow) * (2*SROWB) + ks*32 + lhi*16);
    };

    float s0[4][4];
    #pragma unroll
    for (int i = 0; i < 4; ++i)
        #pragma unroll
        for (int j = 0; j < 4; ++j) s0[i][j] = 0.0f;
    if (tid < 64) sm->m0[0][tid] = 0.0f;
    int par = 0;
    __syncthreads();

    for (int c = 0; c < TT/64; ++c) {
        int c64 = c * 64;
        // ===== phase 1: gates (warp0), stage Q,K(+Kf),Vf, publish S0 regs to smem =====
        if (w == 0) {
            float f0 = g_f[(long)(b*TT + c64 + lane)*HH + h];
            float f1 = g_f[(long)(b*TT + c64 + 32 + lane)*HH + h];
            float l0 = __logf(f0), l1 = __logf(f1);
            #pragma unroll
            for (int o = 1; o < 32; o <<= 1) {
                float n = __shfl_up_sync(0xFFFFFFFFu, l0, o);
                if (lane >= o) l0 += n;
            }
            #pragma unroll
            for (int o = 1; o < 32; o <<= 1) {
                float n = __shfl_up_sync(0xFFFFFFFFu, l1, o);
                if (lane >= o) l1 += n;
            }
            l1 += __shfl_sync(0xFFFFFFFFu, l0, 31);
            float total = __shfl_sync(0xFFFFFFFFu, l1, 31);
            sm->Lc[lane] = l0;      sm->Lc[32 + lane] = l1;
            sm->Ft[lane] = __expf(l0);  sm->Ft[32 + lane] = __expf(l1);
            sm->RL[lane] = __expf(total - l0);
            sm->RL[32 + lane] = __expf(total - l1);
        }
        {
            int t = tid >> 2, dq = (tid & 3) * 16;
            const float* qp = Qg + (long)(c64 + t)*CC + dq;
            const float* kp = Kg + (long)(c64 + t)*CC + dq;
            const float* vp = Vg + (long)(c64 + t)*CC + dq;
            #pragma unroll
            for (int j = 0; j < 4; ++j) {
                float4 q4 = *(const float4*)(qp + j*4);
                float4 k4 = *(const float4*)(kp + j*4);
                float4 v4 = *(const float4*)(vp + j*4);
                int d = dq + j*4;
                store_hl(&sm->Qh[0][0], &sm->Ql[0][0], t*SROWB + d,     q4.x, q4.y);
                store_hl(&sm->Qh[0][0], &sm->Ql[0][0], t*SROWB + d + 2, q4.z, q4.w);
                store_hl(&sm->Kh[0][0], &sm->Kl[0][0], t*SROWB + d,     k4.x, k4.y);
                store_hl(&sm->Kh[0][0], &sm->Kl[0][0], t*SROWB + d + 2, k4.z, k4.w);
                sm->Kf[t][d+0] = k4.x; sm->Kf[t][d+1] = k4.y;
                sm->Kf[t][d+2] = k4.z; sm->Kf[t][d+3] = k4.w;
                sm->Vf[t][d+0] = v4.x; sm->Vf[t][d+1] = v4.y;
                sm->Vf[t][d+2] = v4.z; sm->Vf[t][d+3] = v4.w;
            }
        }
        {
            int e0 = wm + g, e1 = wm + g + 8;
            #pragma unroll
            for (int nf = 0; nf < 4; ++nf) {
                int dcol = wn + nf*8 + 2*tg;
                store_hl(&sm->Sh[0][0], &sm->Sl[0][0], e0*SROWB + dcol, s0[nf][0], s0[nf][1]);
                store_hl(&sm->Sh[0][0], &sm->Sl[0][0], e1*SROWB + dcol, s0[nf][2], s0[nf][3]);
            }
        }
        __syncthreads();

        // ===== phase 2: transposes (Kt, Vt, Vp) =====
        {
            int d = tid >> 2, sq = (tid & 3) * 16;
            #pragma unroll
            for (int i = 0; i < 8; ++i) {
                int s0i = sq + 2*i;
                float k0v = sm->Kf[s0i][d],   k1v = sm->Kf[s0i+1][d];
                float v0v = sm->Vf[s0i][d],   v1v = sm->Vf[s0i+1][d];
                store_hl(&sm->Kth[0][0], &sm->Ktl[0][0], d*SROWB + s0i, k0v, k1v);
                store_hl(&sm->Vth[0][0], &sm->Vtl[0][0], d*SROWB + s0i, v0v, v1v);
                float r0 = sm->RL[s0i], r1 = sm->RL[s0i+1];
                store_hl(&sm->Vph[0][0], &sm->Vpl[0][0], d*SROWB + s0i, v0v*r0, v1v*r1);
            }
        }
        __syncthreads();

        // ===== phase 3: A = Q.K^T (bf16x3 MMA), decay/mask, store A h/l =====
        {
            float a[4][4];
            #pragma unroll
            for (int i = 0; i < 4; ++i)
                #pragma unroll
                for (int j = 0; j < 4; ++j) a[i][j] = 0.0f;
            #pragma unroll
            for (int ks = 0; ks < 4; ++ks) {
                unsigned aH[4], aL[4];
                LDSM4(aH, fa(bQh, wm, ks));
                LDSM4(aL, fa(bQl, wm, ks));
                unsigned p0h[4], p0l[4], p1h[4], p1l[4];
                LDSM4(p0h, fa(bKh, wn, ks));
                LDSM4(p0l, fa(bKl, wn, ks));
                LDSM4(p1h, fa(bKh, wn + 16, ks));
                LDSM4(p1l, fa(bKl, wn + 16, ks));
                unsigned b0h[2]={p0h[0],p0h[2]}, b1h[2]={p0h[1],p0h[3]};
                unsigned b2h[2]={p1h[0],p1h[2]}, b3h[2]={p1h[1],p1h[3]};
                unsigned b0l[2]={p0l[0],p0l[2]}, b1l[2]={p0l[1],p0l[3]};
                unsigned b2l[2]={p1l[0],p1l[2]}, b3l[2]={p1l[1],p1l[3]};
                MMA_BF16(a[0], aH, b0h); MMA_BF16(a[1], aH, b1h);
                MMA_BF16(a[2], aH, b2h); MMA_BF16(a[3], aH, b3h);
                MMA_BF16(a[0], aH, b0l); MMA_BF16(a[1], aH, b1l);
                MMA_BF16(a[2], aH, b2l); MMA_BF16(a[3], aH, b3l);
                MMA_BF16(a[0], aL, b0h); MMA_BF16(a[1], aL, b1h);
                MMA_BF16(a[2], aL, b2h); MMA_BF16(a[3], aL, b3h);
            }
            int t0 = wm + g, t1 = t0 + 8;
            float lct0 = sm->Lc[t0], lct1 = sm->Lc[t1];
            #pragma unroll
            for (int nf = 0; nf < 4; ++nf) {
                int sc = wn + nf*8 + 2*tg;
                float lcs0 = sm->Lc[sc], lcs1 = sm->Lc[sc+1];
                a[nf][0] = (sc   <= t0) ? a[nf][0] * __expf(lct0 - lcs0) : 0.0f;
                a[nf][1] = (sc+1 <= t0) ? a[nf][1] * __expf(lct0 - lcs1) : 0.0f;
                a[nf][2] = (sc   <= t1) ? a[nf][2] * __expf(lct1 - lcs0) : 0.0f;
                a[nf][3] = (sc+1 <= t1) ? a[nf][3] * __expf(lct1 - lcs1) : 0.0f;
                store_hl(&sm->Ah[0][0], &sm->Al[0][0], t0*SROWB + sc, a[nf][0], a[nf][1]);
                store_hl(&sm->Ah[0][0], &sm->Al[0][0], t1*SROWB + sc, a[nf][2], a[nf][3]);
            }
        }
        __syncthreads();

        // ===== phase 4: O = Ft*(Q.S0T) + A.Vt ; S0 update; denom; m0 =====
        {
            float o1[4][4], o2[4][4];
            #pragma unroll
            for (int i = 0; i < 4; ++i)
                #pragma unroll
                for (int j = 0; j < 4; ++j) { o1[i][j] = 0.0f; o2[i][j] = 0.0f; }
            #pragma unroll
            for (int ks = 0; ks < 4; ++ks) {
                unsigned qH[4], qL[4], aAH[4], aAL[4];
                LDSM4(qH, fa(bQh, wm, ks));
                LDSM4(qL, fa(bQl, wm, ks));
                LDSM4(aAH, fa(bAh, wm, ks));
                LDSM4(aAL, fa(bAl, wm, ks));
                unsigned s0h4[4], s0l4[4], s1h4[4], s1l4[4];
                LDSM4(s0h4, fa(bSh, wn, ks));
                LDSM4(s0l4, fa(bSl, wn, ks));
                LDSM4(s1h4, fa(bSh, wn + 16, ks));
                LDSM4(s1l4, fa(bSl, wn + 16, ks));
                unsigned v0h4[4], v0l4[4], v1h4[4], v1l4[4];
                LDSM4(v0h4, fa(bVth, wn, ks));
                LDSM4(v0l4, fa(bVtl, wn, ks));
                LDSM4(v1h4, fa(bVth, wn + 16, ks));
                LDSM4(v1l4, fa(bVtl, wn + 16, ks));
                unsigned sb0h[2]={s0h4[0],s0h4[2]}, sb1h[2]={s0h4[1],s0h4[3]};
                unsigned sb2h[2]={s1h4[0],s1h4[2]}, sb3h[2]={s1h4[1],s1h4[3]};
                unsigned sb0l[2]={s0l4[0],s0l4[2]}, sb1l[2]={s0l4[1],s0l4[3]};
                unsigned sb2l[2]={s1l4[0],s1l4[2]}, sb3l[2]={s1l4[1],s1l4[3]};
                unsigned vb0h[2]={v0h4[0],v0h4[2]}, vb1h[2]={v0h4[1],v0h4[3]};
                unsigned vb2h[2]={v1h4[0],v1h4[2]}, vb3h[2]={v1h4[1],v1h4[3]};
                unsigned vb0l[2]={v0l4[0],v0l4[2]}, vb1l[2]={v0l4[1],v0l4[3]};
                unsigned vb2l[2]={v1l4[0],v1l4[2]}, vb3l[2]={v1l4[1],v1l4[3]};
                MMA_BF16(o1[0], qH, sb0h); MMA_BF16(o2[0], aAH, vb0h);
                MMA_BF16(o1[1], qH, sb1h); MMA_BF16(o2[1], aAH, vb1h);
                MMA_BF16(o1[2], qH, sb2h); MMA_BF16(o2[2], aAH, vb2h);
                MMA_BF16(o1[3], qH, sb3h); MMA_BF16(o2[3], aAH, vb3h);
                MMA_BF16(o1[0], qH, sb0l); MMA_BF16(o2[0], aAH, vb0l);
                MMA_BF16(o1[1], qH, sb1l); MMA_BF16(o2[1], aAH, vb1l);
                MMA_BF16(o1[2], qH, sb2l); MMA_BF16(o2[2], aAH, vb2l);
                MMA_BF16(o1[3], qH, sb3l); MMA_BF16(o2[3], aAH, vb3l);
                MMA_BF16(o1[0], qL, sb0h); MMA_BF16(o2[0], aAL, vb0h);
                MMA_BF16(o1[1], qL, sb1h); MMA_BF16(o2[1], aAL, vb1h);
                MMA_BF16(o1[2], qL, sb2h); MMA_BF16(o2[2], aAL, vb2h);
                MMA_BF16(o1[3], qL, sb3h); MMA_BF16(o2[3], aAL, vb3h);
            }
            int t0 = wm + g, t1 = t0 + 8;
            float ft0 = sm->Ft[t0], ft1 = sm->Ft[t1];
            #pragma unroll
            for (int nf = 0; nf < 4; ++nf) {
                int ec = wn + nf*8 + 2*tg;
                float2 w0 = make_float2(ft0*o1[nf][0] + o2[nf][0], ft0*o1[nf][1] + o2[nf][1]);
                float2 w1 = make_float2(ft1*o1[nf][2] + o2[nf][2], ft1*o1[nf][3] + o2[nf][3]);
                *(float2*)&Og[(long)(c64 + t0)*CC + ec] = w0;
                *(float2*)&Og[(long)(c64 + t1)*CC + ec] = w1;
            }

            // state update: s0[e][d] = FL*s0 + Vp^T.K^T  (A-op Vp[e][s], B-op Kt[d][s])
            float FL = sm->Ft[63];
            #pragma unroll
            for (int i = 0; i < 4; ++i)
                #pragma unroll
                for (int j = 0; j < 4; ++j) s0[i][j] *= FL;
            #pragma unroll
            for (int ks = 0; ks < 4; ++ks) {
                unsigned aH[4], aL[4];
                LDSM4(aH, fa(bVph, wm, ks));
                LDSM4(aL, fa(bVpl, wm, ks));
                unsigned p0h[4], p0l[4], p1h[4], p1l[4];
                LDSM4(p0h, fa(bKth, wn, ks));
                LDSM4(p0l, fa(bKtl, wn, ks));
                LDSM4(p1h, fa(bKth, wn + 16, ks));
                LDSM4(p1l, fa(bKtl, wn + 16, ks));
                unsigned b0h[2]={p0h[0],p0h[2]}, b1h[2]={p0h[1],p0h[3]};
                unsigned b2h[2]={p1h[0],p1h[2]}, b3h[2]={p1h[1],p1h[3]};
                unsigned b0l[2]={p0l[0],p0l[2]}, b1l[2]={p0l[1],p0l[3]};
                unsigned b2l[2]={p1l[0],p1l[2]}, b3l[2]={p1l[1],p1l[3]};
                MMA_BF16(s0[0], aH, b0h); MMA_BF16(s0[1], aH, b1h);
                MMA_BF16(s0[2], aH, b2h); MMA_BF16(s0[3], aH, b3h);
                MMA_BF16(s0[0], aH, b0l); MMA_BF16(s0[1], aH, b1l);
                MMA_BF16(s0[2], aH, b2l); MMA_BF16(s0[3], aH, b3l);
                MMA_BF16(s0[0], aL, b0h); MMA_BF16(s0[1], aL, b1h);
                MMA_BF16(s0[2], aL, b2h); MMA_BF16(s0[3], aL, b3h);
            }

            // denominator (t = tid) and m0 update (d = tid-64)
            if (tid < 64) {
                int t = tid;
                float rs = 0.0f, qm = 0.0f;
                const __nv_bfloat162* ah = (const __nv_bfloat162*)&sm->Ah[t][0];
                const __nv_bfloat162* al = (const __nv_bfloat162*)&sm->Al[t][0];
                const __nv_bfloat162* qh = (const __nv_bfloat162*)&sm->Qh[t][0];
                const __nv_bfloat162* ql = (const __nv_bfloat162*)&sm->Ql[t][0];
                #pragma unroll 8
                for (int i = 0; i < 32; ++i) {
                    __nv_bfloat162 hv = ah[i], lv = al[i];
                    rs += __bfloat162float(hv.x) + __bfloat162float(hv.y)
                        + __bfloat162float(lv.x) + __bfloat162float(lv.y);
                    __nv_bfloat162 qhv = qh[i], qlv = ql[i];
                    float q0 = __bfloat162float(qhv.x) + __bfloat162float(qlv.x);
                    float q1 = __bfloat162float(qhv.y) + __bfloat162float(qlv.y);
                    qm += q0 * sm->m0[par][2*i] + q1 * sm->m0[par][2*i+1];
                }
                float den = sm->Ft[t] * qm + rs;
                Dg[c64 + t] = 1.0f / fmaxf(den, 1e-6f);
            } else if (tid < 128) {
                int d = tid - 64;
                float acc = 0.0f;
                #pragma unroll 8
                for (int s = 0; s < 64; ++s) acc += sm->RL[s] * sm->Kf[s][d];
                sm->m0[par ^ 1][d] = sm->Ft[63] * sm->m0[par][d] + acc;
            }
        }
        __syncthreads();
        par ^= 1;
    }
}

// ---------- LayerNorm ----------
__global__ void __launch_bounds__(256) k_ln(const float* __restrict__ lw,
                                            const float* __restrict__ lb,
                                            float* __restrict__ out) {
    int row = blockIdx.x, tid = threadIdx.x;
    int w = tid >> 5, l = tid & 31;
    const float4* y4 = (const float4*)(g_z + (long)row*CC);
    float4 a = y4[tid];
    float s1 = a.x + a.y + a.z + a.w;
    float s2 = a.x*a.x + a.y*a.y + a.z*a.z + a.w*a.w;
    #pragma unroll
    for (int off = 16; off; off >>= 1) {
        s1 += __shfl_xor_sync(0xFFFFFFFFu, s1, off);
        s2 += __shfl_xor_sync(0xFFFFFFFFu, s2, off);
    }
    __shared__ float r1[8], r2[8];
    if (l == 0) { r1[w] = s1; r2[w] = s2; }
    __syncthreads();
    if (w == 0) {
        s1 = (l < 8) ? r1[l] : 0.0f;
        s2 = (l < 8) ? r2[l] : 0.0f;
        #pragma unroll
        for (int off = 4; off; off >>= 1) {
            s1 += __shfl_xor_sync(0xFFFFFFFFu, s1, off);
            s2 += __shfl_xor_sync(0xFFFFFFFFu, s2, off);
        }
        if (l == 0) { r1[0] = s1; r2[0] = s2; }
    }
    __syncthreads();
    float mu = r1[0] * (1.0f / CC);
    float var = r2[0] * (1.0f / CC) - mu*mu;
    float rs = rsqrtf(var + 1e-5f);
    float4 wv = ((const float4*)lw)[tid];
    float4 bv = ((const float4*)lb)[tid];
    float4 o;
    o.x = (a.x - mu)*rs*wv.x + bv.x;
    o.y = (a.y - mu)*rs*wv.y + bv.y;
    o.z = (a.z - mu)*rs*wv.z + bv.z;
    o.w = (a.w - mu)*rs*wv.w + bv.w;
    ((float4*)(out + (long)row*CC))[tid] = o;
}

extern "C" void kernel_launch(void* const* d_in, const int* in_sizes, int n_in,
                              void* d_out, int out_size) {
    (void)in_sizes; (void)n_in; (void)out_size;
    const float* x    = (const float*)d_in[0];
    const int*   mask = (const int*)  d_in[1];
    const float* Wq   = (const float*)d_in[2];
    const float* Wk   = (const float*)d_in[3];
    const float* Wv   = (const float*)d_in[4];
    const float* Wg   = (const float*)d_in[5];
    const float* bg   = (const float*)d_in[6];
    const float* Wo   = (const float*)d_in[7];
    const float* bo   = (const float*)d_in[8];
    const float* lw   = (const float*)d_in[9];
    const float* lb   = (const float*)d_in[10];
    float* out = (float*)d_out;

    cudaFuncSetAttribute(k_gemm_qkv, cudaFuncAttributeMaxDynamicSharedMemorySize, GEMM_DSMEM);
    cudaFuncSetAttribute(k_gemm_out, cudaFuncAttributeMaxDynamicSharedMemorySize, GEMM_DSMEM);
    cudaFuncSetAttribute(k_scan, cudaFuncAttributeMaxDynamicSharedMemorySize, SCAN_DSMEM);

    k_cvtall<<<4096 + 1024, 256>>>(x, Wq, Wk, Wv, Wo);                   // 1
    k_misc<<<512, 256>>>(x, Wg, bg, mask);                               // 2
    k_gemm_qkv<<<dim3(CC/128, BT/128, 3), 256, GEMM_DSMEM>>>(mask);      // 3
    k_scan<<<BB*HH, 256, SCAN_DSMEM>>>();                                // 4 (ncu slot)
    k_cvtatt<<<(BT*CC/4)/256, 256>>>();                                  // 5
    k_gemm_out<<<dim3(CC/128, BT/128), 256, GEMM_DSMEM>>>(bo, x);        // 6
    k_ln<<<BT, 256>>>(lw, lb, out);                                      // 7
}

// round 14
// speedup vs baseline: 3.3662x; 1.2297x over previous
#include <cuda_runtime.h>
#include <cuda_bf16.h>
#include <math.h>

#define BB 2
#define TT 2048
#define CC 1024
#define HH 16
#define DD 64
#define BT (BB*TT)
#define NP 4
#define PLEN (TT/NP)   // 512

// ---------- scratch ----------
__device__ float g_q[BT*CC];
__device__ float g_k[BT*CC];
__device__ float g_v[BT*CC];
__device__ float g_att[BT*CC];   // raw numerator
__device__ float g_z[BT*CC];
__device__ float g_f[BT*HH];
__device__ float g_den[BB*HH*TT];  // reciprocal of denom
__device__ float g_cos[TT*32];
__device__ float g_sin[TT*32];

__device__ float g_dS[BB*HH*NP*4096];   // partition state deltas [e][d]
__device__ float g_SIn[BB*HH*NP*4096];  // partition inbound states
__device__ float g_dM[BB*HH*NP*64];
__device__ float g_MIn[BB*HH*NP*64];
__device__ float g_FP[BB*HH*NP];

__device__ __nv_bfloat16 g_xh[BT*CC], g_xl[BT*CC];
__device__ __nv_bfloat16 g_ath[BT*CC], g_atl[BT*CC];
__device__ __nv_bfloat16 g_wh[4][CC*CC], g_wl[4][CC*CC];

__device__ __forceinline__ float phi_f(float x) { return x > 0.0f ? x + 1.0f : expf(x); }

__device__ __forceinline__ unsigned smem_u32(const void* p) {
    unsigned a;
    asm("{ .reg .u64 t; cvta.to.shared.u64 t, %1; cvt.u32.u64 %0, t; }" : "=r"(a) : "l"(p));
    return a;
}

// ---------- cp.async / ldmatrix / mma ----------
#define CP_ASYNC16(dst, src) \
    asm volatile("cp.async.cg.shared.global [%0], [%1], 16;" :: "r"(dst), "l"(src))
#define CP_COMMIT() asm volatile("cp.async.commit_group;")
#define CP_WAIT1()  asm volatile("cp.async.wait_group 1;")

#define LDSM4(r, addr) \
    asm volatile("ldmatrix.sync.aligned.m8n8.x4.shared.b16 {%0,%1,%2,%3}, [%4];" \
        : "=r"((r)[0]), "=r"((r)[1]), "=r"((r)[2]), "=r"((r)[3]) : "r"(addr))

#define MMA_BF16(c, a, b) \
    asm volatile("mma.sync.aligned.m16n8k16.row.col.f32.bf16.bf16.f32 " \
                 "{%0,%1,%2,%3},{%4,%5,%6,%7},{%8,%9},{%0,%1,%2,%3};" \
                 : "+f"((c)[0]), "+f"((c)[1]), "+f"((c)[2]), "+f"((c)[3]) \
                 : "r"((a)[0]), "r"((a)[1]), "r"((a)[2]), "r"((a)[3]), \
                   "r"((b)[0]), "r"((b)[1]))

// ---------- bf16 hi/lo split stores ----------
__device__ __forceinline__ void store_hl(__nv_bfloat16* H, __nv_bfloat16* L, int idx,
                                         float v0, float v1) {
    __nv_bfloat16 h0 = __float2bfloat16(v0), h1 = __float2bfloat16(v1);
    __nv_bfloat162 hh; hh.x = h0; hh.y = h1;
    *(__nv_bfloat162*)(H + idx) = hh;
    __nv_bfloat162 ll;
    ll.x = __float2bfloat16(v0 - __bfloat162float(h0));
    ll.y = __float2bfloat16(v1 - __bfloat162float(h1));
    *(__nv_bfloat162*)(L + idx) = ll;
}

__device__ __forceinline__ void split_store(float4 v, __nv_bfloat16* dh, __nv_bfloat16* dl, long idx) {
    float vv[4] = {v.x, v.y, v.z, v.w};
    unsigned short h[4], l[4];
    #pragma unroll
    for (int i = 0; i < 4; ++i) {
        __nv_bfloat16 hb = __float2bfloat16(vv[i]);
        h[i] = __bfloat16_as_ushort(hb);
        l[i] = __bfloat16_as_ushort(__float2bfloat16(vv[i] - __bfloat162float(hb)));
    }
    *(uint2*)(dh + idx) = make_uint2(h[0] | ((unsigned)h[1]<<16), h[2] | ((unsigned)h[3]<<16));
    *(uint2*)(dl + idx) = make_uint2(l[0] | ((unsigned)l[1]<<16), l[2] | ((unsigned)l[3]<<16));
}

__global__ void __launch_bounds__(256) k_cvtall(const float* __restrict__ x,
                                                const float* __restrict__ Wq,
                                                const float* __restrict__ Wk,
                                                const float* __restrict__ Wv,
                                                const float* __restrict__ Wo) {
    int id = blockIdx.x * blockDim.x + threadIdx.x;
    if (blockIdx.x < 4096) {
        float4 v = ((const float4*)x)[id];
        split_store(v, g_xh, g_xl, (long)id*4);
    } else {
        int wid = id - 4096*256;
        int seg = wid >> 16;
        int off = wid & 0xFFFF;
        const float* src = seg == 0 ? Wq : seg == 1 ? Wk : seg == 2 ? Wv : Wo;
        #pragma unroll
        for (int r = 0; r < 4; ++r) {
            int o = off + r * 65536;
            float4 v = ((const float4*)src)[o];
            split_store(v, g_wh[seg], g_wl[seg], (long)o*4);
        }
    }
}

// ---------- fused fgate (blocks 0..255) + trig (blocks 256..511) ----------
__global__ void __launch_bounds__(256) k_misc(const float* __restrict__ x,
                                              const float* __restrict__ Wg,
                                              const float* __restrict__ bg,
                                              const int* __restrict__ mask) {
    if (blockIdx.x < 256) {
        __shared__ float xs[16][64];
        __shared__ float wsT[64][17];
        int tid = threadIdx.x;
        int row0 = blockIdx.x * 16;
        int lr = tid >> 4, lq = tid & 15;
        float acc = 0.0f;
        for (int k0 = 0; k0 < CC; k0 += 64) {
            float4 xv = *(const float4*)&x[(long)(row0+lr)*CC + k0 + lq*4];
            *(float4*)&xs[lr][lq*4] = xv;
            float4 wv = *(const float4*)&Wg[(long)lr*CC + k0 + lq*4];
            wsT[lq*4+0][lr] = wv.x; wsT[lq*4+1][lr] = wv.y;
            wsT[lq*4+2][lr] = wv.z; wsT[lq*4+3][lr] = wv.w;
            __syncthreads();
            #pragma unroll
            for (int kk = 0; kk < 64; ++kk) acc = fmaf(xs[lr][kk], wsT[kk][lq], acc);
            __syncthreads();
        }
        float zv = acc + bg[lq];
        float f = 1.0f / (1.0f + expf(-zv));
        f = fminf(fmaxf(f, 0.01f), 0.999f);
        float mk = (float)mask[row0 + lr];
        f = f * mk + (1.0f - mk);
        g_f[(long)(row0 + lr)*HH + lq] = f;
    } else {
        int gid = (blockIdx.x - 256) * 256 + threadIdx.x;
        int t = gid >> 5, i = gid & 31;
        float e = (float)i * (1.0f / 32.0f);
        float inv = 1.0f / powf(10000.0f, e);
        float fr = (float)t * inv;
        g_cos[gid] = cosf(fr);
        g_sin[gid] = sinf(fr);
    }
}

// ---------- normalize att + split to bf16 hi/lo ----------
__global__ void __launch_bounds__(256) k_cvtatt() {
    int id = blockIdx.x * blockDim.x + threadIdx.x;
    int elem = id * 4;
    int bt = elem >> 10;
    int rem = elem & 1023;
    int h = rem >> 6;
    int b = bt >> 11, t = bt & (TT - 1);
    float r = g_den[((long)(b*HH + h))*TT + t];
    float4 v = *(const float4*)(g_att + (long)elem);
    v.x *= r; v.y *= r; v.z *= r; v.w *= r;
    split_store(v, g_ath, g_atl, (long)elem);
}

// ---------- bf16x3 GEMM: BK=32, 3-stage cp.async; fused epilogues ----------
#define GEMM_DSMEM (3*4*8192)

__device__ __forceinline__ void gemm_core(const __nv_bfloat16* __restrict__ Agh,
                                          const __nv_bfloat16* __restrict__ Agl,
                                          const __nv_bfloat16* __restrict__ Bgh,
                                          const __nv_bfloat16* __restrict__ Bgl,
                                          float* __restrict__ Cout,
                                          const float* __restrict__ bias,
                                          const float* __restrict__ resid,
                                          const int* __restrict__ mask,
                                          int mode)
{
    extern __shared__ __align__(16) char dynsm[];
    unsigned smb = smem_u32(dynsm);

    int tid = threadIdx.x;
    int m0 = blockIdx.y * 128;
    int n0 = blockIdx.x * 128;

    int prow = tid >> 1;
    int ph = tid & 1;
    const __nv_bfloat16* srcs[4];
    srcs[0] = Agh + (long)(m0 + prow) * CC + ph * 16;
    srcs[1] = Agl + (long)(m0 + prow) * CC + ph * 16;
    srcs[2] = Bgh + (long)(n0 + prow) * CC + ph * 16;
    srcs[3] = Bgl + (long)(n0 + prow) * CC + ph * 16;
    unsigned psw = (prow >> 1) & 3;
    unsigned d0off = prow * 64 + (((2u*ph) ^ psw) << 4);

    int warp = tid >> 5, lane = tid & 31;
    int g = lane >> 2, tg = lane & 3;
    int mbase = (warp >> 1) * 32;
    int nbase = (warp & 1) * 64;
    int lrow = lane & 15, lhi = lane >> 4;

    float c[2][8][4];
    #pragma unroll
    for (int mf = 0; mf < 2; ++mf)
        #pragma unroll
        for (int nf = 0; nf < 8; ++nf)
            #pragma unroll
            for (int j = 0; j < 4; ++j) c[mf][nf][j] = 0.0f;

    auto issue = [&](int kt) {
        unsigned sb = smb + (unsigned)(kt % 3) * 32768u;
        #pragma unroll
        for (int t = 0; t < 4; ++t) {
            const __nv_bfloat16* s = srcs[t] + kt * 32;
            unsigned d = sb + t * 8192 + d0off;
            CP_ASYNC16(d, s);
            CP_ASYNC16(d ^ 16u, s + 8);
        }
        CP_COMMIT();
    };

    auto lda = [&](unsigned sb, int t, int rowbase, int kh) -> unsigned {
        int r = rowbase + lrow;
        unsigned ch = (unsigned)(kh * 2 + lhi);
        return sb + t * 8192 + r * 64 + ((ch ^ ((unsigned)(r >> 1) & 3u)) << 4);
    };

    const int NT = CC / 32;
    issue(0);
    issue(1);

    for (int kt = 0; kt < NT; ++kt) {
        CP_WAIT1();
        __syncthreads();
        if (kt + 2 < NT) issue(kt + 2);

        unsigned sb = smb + (unsigned)(kt % 3) * 32768u;
        #pragma unroll
        for (int kh = 0; kh < 2; ++kh) {
            unsigned aH[2][4], aL[2][4];
            #pragma unroll
            for (int mf = 0; mf < 2; ++mf) {
                LDSM4(aH[mf], lda(sb, 0, mbase + mf*16, kh));
                LDSM4(aL[mf], lda(sb, 1, mbase + mf*16, kh));
            }
            #pragma unroll
            for (int nfp = 0; nfp < 4; ++nfp) {
                unsigned bh4[4], bl4[4];
                LDSM4(bh4, lda(sb, 2, nbase + nfp*16, kh));
                LDSM4(bl4, lda(sb, 3, nbase + nfp*16, kh));
                unsigned bh0[2] = {bh4[0], bh4[2]}, bh1[2] = {bh4[1], bh4[3]};
                unsigned bl0[2] = {bl4[0], bl4[2]}, bl1[2] = {bl4[1], bl4[3]};
                MMA_BF16(c[0][nfp*2],   aH[0], bh0);
                MMA_BF16(c[1][nfp*2],   aH[1], bh0);
                MMA_BF16(c[0][nfp*2+1], aH[0], bh1);
                MMA_BF16(c[1][nfp*2+1], aH[1], bh1);
                MMA_BF16(c[0][nfp*2],   aH[0], bl0);
                MMA_BF16(c[1][nfp*2],   aH[1], bl0);
                MMA_BF16(c[0][nfp*2+1], aH[0], bl1);
                MMA_BF16(c[1][nfp*2+1], aH[1], bl1);
                MMA_BF16(c[0][nfp*2],   aL[0], bh0);
                MMA_BF16(c[1][nfp*2],   aL[1], bh0);
                MMA_BF16(c[0][nfp*2+1], aL[0], bh1);
                MMA_BF16(c[1][nfp*2+1], aL[1], bh1);
            }
        }
    }

    if (mode != 2) {
        #pragma unroll
        for (int mf = 0; mf < 2; ++mf) {
            int r0_ = m0 + mbase + mf*16 + g;
            float mk0 = (float)mask[r0_];
            float mk1 = (float)mask[r0_ + 8];
            if (mode == 0) {
                #pragma unroll
                for (int nf = 0; nf < 8; ++nf) {
                    c[mf][nf][0] *= mk0; c[mf][nf][1] *= mk0;
                    c[mf][nf][2] *= mk1; c[mf][nf][3] *= mk1;
                }
            } else {
                int t_0 = r0_ & (TT-1), t_1 = (r0_+8) & (TT-1);
                #pragma unroll
                for (int nf = 0; nf < 4; ++nf) {
                    #pragma unroll
                    for (int idx = 0; idx < 2; ++idx) {
                        int i = nf*8 + 2*tg + idx;
                        float c0 = g_cos[t_0*32 + i], s0 = g_sin[t_0*32 + i];
                        float c1 = g_cos[t_1*32 + i], s1 = g_sin[t_1*32 + i];
                        float x1a = c[mf][nf][idx],   x2a = c[mf][nf+4][idx];
                        float x1b = c[mf][nf][idx+2], x2b = c[mf][nf+4][idx+2];
                        c[mf][nf][idx]     = phi_f(x1a*c0 - x2a*s0) * mk0;
                        c[mf][nf+4][idx]   = phi_f(x2a*c0 + x1a*s0) * mk0;
                        c[mf][nf][idx+2]   = phi_f(x1b*c1 - x2b*s1) * mk1;
                        c[mf][nf+4][idx+2] = phi_f(x2b*c1 + x1b*s1) * mk1;
                    }
                }
            }
        }
    }

    #pragma unroll
    for (int mf = 0; mf < 2; ++mf) {
        #pragma unroll
        for (int nf = 0; nf < 8; ++nf) {
            int r = m0 + mbase + mf*16 + g;
            int col = n0 + nbase + nf*8 + 2*tg;
            float2 v0 = make_float2(c[mf][nf][0], c[mf][nf][1]);
            float2 v1 = make_float2(c[mf][nf][2], c[mf][nf][3]);
            if (mode == 2) {
                float b0 = bias[col], b1 = bias[col+1];
                v0.x += b0 + resid[(long)r*CC + col];
                v0.y += b1 + resid[(long)r*CC + col + 1];
                v1.x += b0 + resid[(long)(r+8)*CC + col];
                v1.y += b1 + resid[(long)(r+8)*CC + col + 1];
            }
            *(float2*)&Cout[(long)r*CC + col]     = v0;
            *(float2*)&Cout[(long)(r+8)*CC + col] = v1;
        }
    }
}

__global__ void __launch_bounds__(256, 2) k_gemm_qkv(const int* __restrict__ mask) {
    int z = blockIdx.z;
    float* out = z == 0 ? g_q : (z == 1 ? g_k : g_v);
    gemm_core(g_xh, g_xl, g_wh[z], g_wl[z], out, nullptr, nullptr, mask, z == 2 ? 0 : 1);
}

__global__ void __launch_bounds__(256, 2) k_gemm_out(const float* __restrict__ bo,
                                                     const float* __restrict__ x) {
    gemm_core(g_ath, g_atl, g_wh[3], g_wl[3], g_z, bo, x, nullptr, 2);
}

// ---------- pass A: partition state deltas (128 blocks x 256) ----------
#define SROWB 72
struct ScanASM {
    __nv_bfloat16 Kth[64][SROWB], Ktl[64][SROWB];
    __nv_bfloat16 Vph[64][SROWB], Vpl[64][SROWB];
    float Kf[64][65], Vf[64][65];
    float Lc[64], Ft[64], RL[64];
};
#define SCANA_DSMEM ((int)sizeof(ScanASM))

__global__ void __launch_bounds__(256) k_scanA() {
    extern __shared__ __align__(16) char sbuf[];
    ScanASM* sm = (ScanASM*)sbuf;
    int bh = blockIdx.x >> 2, p = blockIdx.x & 3;
    int b = bh >> 4, h = bh & 15;
    int tid = threadIdx.x;
    int w = tid >> 5, lane = tid & 31;
    int g = lane >> 2, tg = lane & 3;
    int lrow = lane & 15, lhi = lane >> 4;
    int wm = (w >> 1) * 16;
    int wn = (w & 1) * 32;

    long base = (long)b*TT*CC + h*DD + (long)(p*PLEN)*CC;
    const float* Kg = g_k + base;
    const float* Vg = g_v + base;

    unsigned bKth = smem_u32(sm->Kth), bKtl = smem_u32(sm->Ktl);
    unsigned bVph = smem_u32(sm->Vph), bVpl = smem_u32(sm->Vpl);

    auto fa = [&](unsigned bbase, int rowbase, int ks) -> unsigned {
        return bbase + (unsigned)((rowbase + lrow) * (2*SROWB) + ks*32 + lhi*16);
    };

    float s0[4][4];
    #pragma unroll
    for (int i = 0; i < 4; ++i)
        #pragma unroll
        for (int j = 0; j < 4; ++j) s0[i][j] = 0.0f;
    float mreg = 0.0f;
    float ltot = 0.0f;

    for (int cc = 0; cc < PLEN/64; ++cc) {
        int c64 = cc * 64;
        if (w == 0) {
            float f0 = g_f[(long)(b*TT + p*PLEN + c64 + lane)*HH + h];
            float f1 = g_f[(long)(b*TT + p*PLEN + c64 + 32 + lane)*HH + h];
            float l0 = __logf(f0), l1 = __logf(f1);
            #pragma unroll
            for (int o = 1; o < 32; o <<= 1) {
                float n = __shfl_up_sync(0xFFFFFFFFu, l0, o);
                if (lane >= o) l0 += n;
            }
            #pragma unroll
            for (int o = 1; o < 32; o <<= 1) {
                float n = __shfl_up_sync(0xFFFFFFFFu, l1, o);
                if (lane >= o) l1 += n;
            }
            l1 += __shfl_sync(0xFFFFFFFFu, l0, 31);
            float total = __shfl_sync(0xFFFFFFFFu, l1, 31);
            ltot += total;
            sm->Lc[lane] = l0;      sm->Lc[32 + lane] = l1;
            sm->Ft[lane] = __expf(l0);  sm->Ft[32 + lane] = __expf(l1);
            sm->RL[lane] = __expf(total - l0);
            sm->RL[32 + lane] = __expf(total - l1);
        }
        {
            int t = tid >> 2, dq = (tid & 3) * 16;
            const float* kp = Kg + (long)(c64 + t)*CC + dq;
            const float* vp = Vg + (long)(c64 + t)*CC + dq;
            #pragma unroll
            for (int j = 0; j < 4; ++j) {
                float4 k4 = *(const float4*)(kp + j*4);
                float4 v4 = *(const float4*)(vp + j*4);
                int d = dq + j*4;
                sm->Kf[t][d+0] = k4.x; sm->Kf[t][d+1] = k4.y;
                sm->Kf[t][d+2] = k4.z; sm->Kf[t][d+3] = k4.w;
                sm->Vf[t][d+0] = v4.x; sm->Vf[t][d+1] = v4.y;
                sm->Vf[t][d+2] = v4.z; sm->Vf[t][d+3] = v4.w;
            }
        }
        __syncthreads();

        {
            int d = tid >> 2, sq = (tid & 3) * 16;
            #pragma unroll
            for (int i = 0; i < 8; ++i) {
                int s0i = sq + 2*i;
                float k0v = sm->Kf[s0i][d],   k1v = sm->Kf[s0i+1][d];
                float v0v = sm->Vf[s0i][d],   v1v = sm->Vf[s0i+1][d];
                store_hl(&sm->Kth[0][0], &sm->Ktl[0][0], d*SROWB + s0i, k0v, k1v);
                float r0 = sm->RL[s0i], r1 = sm->RL[s0i+1];
                store_hl(&sm->Vph[0][0], &sm->Vpl[0][0], d*SROWB + s0i, v0v*r0, v1v*r1);
            }
        }
        __syncthreads();

        {
            float FL = sm->Ft[63];
            #pragma unroll
            for (int i = 0; i < 4; ++i)
                #pragma unroll
                for (int j = 0; j < 4; ++j) s0[i][j] *= FL;
            #pragma unroll
            for (int ks = 0; ks < 4; ++ks) {
                unsigned aH[4], aL[4];
                LDSM4(aH, fa(bVph, wm, ks));
                LDSM4(aL, fa(bVpl, wm, ks));
                unsigned p0h[4], p0l[4], p1h[4], p1l[4];
                LDSM4(p0h, fa(bKth, wn, ks));
                LDSM4(p0l, fa(bKtl, wn, ks));
                LDSM4(p1h, fa(bKth, wn + 16, ks));
                LDSM4(p1l, fa(bKtl, wn + 16, ks));
                unsigned b0h[2]={p0h[0],p0h[2]}, b1h[2]={p0h[1],p0h[3]};
                unsigned b2h[2]={p1h[0],p1h[2]}, b3h[2]={p1h[1],p1h[3]};
                unsigned b0l[2]={p0l[0],p0l[2]}, b1l[2]={p0l[1],p0l[3]};
                unsigned b2l[2]={p1l[0],p1l[2]}, b3l[2]={p1l[1],p1l[3]};
                MMA_BF16(s0[0], aH, b0h); MMA_BF16(s0[1], aH, b1h);
                MMA_BF16(s0[2], aH, b2h); MMA_BF16(s0[3], aH, b3h);
                MMA_BF16(s0[0], aH, b0l); MMA_BF16(s0[1], aH, b1l);
                MMA_BF16(s0[2], aH, b2l); MMA_BF16(s0[3], aH, b3l);
                MMA_BF16(s0[0], aL, b0h); MMA_BF16(s0[1], aL, b1h);
                MMA_BF16(s0[2], aL, b2h); MMA_BF16(s0[3], aL, b3h);
            }
            if (tid >= 64 && tid < 128) {
                int d = tid - 64;
                float acc = 0.0f;
                #pragma unroll 8
                for (int s = 0; s < 64; ++s) acc += sm->RL[s] * sm->Kf[s][d];
                mreg = FL * mreg + acc;
            }
        }
        __syncthreads();
    }

    float* dS = g_dS + ((long)bh*NP + p)*4096;
    #pragma unroll
    for (int nf = 0; nf < 4; ++nf) {
        int dc = wn + nf*8 + 2*tg;
        dS[(wm + g)*64 + dc]     = s0[nf][0];
        dS[(wm + g)*64 + dc + 1] = s0[nf][1];
        dS[(wm + g + 8)*64 + dc]     = s0[nf][2];
        dS[(wm + g + 8)*64 + dc + 1] = s0[nf][3];
    }
    if (tid >= 64 && tid < 128)
        g_dM[((long)bh*NP + p)*64 + tid - 64] = mreg;
    if (tid == 0)
        g_FP[bh*NP + p] = __expf(ltot);
}

// ---------- pass B: stitch partition states (32 blocks x 256) ----------
__global__ void __launch_bounds__(256) k_stitch() {
    int bh = blockIdx.x;
    float f1 = g_FP[bh*NP + 1], f2 = g_FP[bh*NP + 2];
    const float* dS = g_dS + (long)bh*NP*4096;
    float* SIn = g_SIn + (long)bh*NP*4096;
    for (int i = threadIdx.x; i < 4096; i += 256) {
        float s1 = dS[i];
        float s2 = f1*s1 + dS[4096 + i];
        float s3 = f2*s2 + dS[2*4096 + i];
        SIn[i] = 0.0f;
        SIn[4096 + i] = s1;
        SIn[2*4096 + i] = s2;
        SIn[3*4096 + i] = s3;
    }
    if (threadIdx.x < 64) {
        int d = threadIdx.x;
        const float* dM = g_dM + (long)bh*NP*64;
        float* MIn = g_MIn + (long)bh*NP*64;
        float m1 = dM[d];
        float m2 = f1*m1 + dM[64 + d];
        float m3 = f2*m2 + dM[128 + d];
        MIn[d] = 0.0f;
        MIn[64 + d] = m1;
        MIn[128 + d] = m2;
        MIn[192 + d] = m3;
    }
}

// ---------- pass C: full chunked scan within partition (128 blocks x 256) ----------
struct ScanSM {
    __nv_bfloat16 Qh[64][SROWB], Ql[64][SROWB];
    __nv_bfloat16 Kh[64][SROWB], Kl[64][SROWB];
    __nv_bfloat16 Kth[64][SROWB], Ktl[64][SROWB];
    __nv_bfloat16 Vth[64][SROWB], Vtl[64][SROWB];
    __nv_bfloat16 Vph[64][SROWB], Vpl[64][SROWB];
    __nv_bfloat16 Ah[64][SROWB], Al[64][SROWB];
    __nv_bfloat16 Sh[64][SROWB], Sl[64][SROWB];
    float Kf[64][65];
    float Vf[64][65];
    float Lc[64], Ft[64], RL[64];
    float m0[2][64];
};
#define SCAN_DSMEM ((int)sizeof(ScanSM))

__global__ void __launch_bounds__(256) k_scanC() {
    extern __shared__ __align__(16) char sbuf[];
    ScanSM* sm = (ScanSM*)sbuf;
    int bh = blockIdx.x >> 2, p = blockIdx.x & 3;
    int b = bh >> 4, h = bh & 15;
    int tid = threadIdx.x;
    int w = tid >> 5, lane = tid & 31;
    int g = lane >> 2, tg = lane & 3;
    int lrow = lane & 15, lhi = lane >> 4;
    int wm = (w >> 1) * 16;
    int wn = (w & 1) * 32;

    long base = (long)b*TT*CC + h*DD + (long)(p*PLEN)*CC;
    const float* Qg = g_q + base;
    const float* Kg = g_k + base;
    const float* Vg = g_v + base;
    float* Og = g_att + base;
    float* Dg = g_den + (long)bh*TT + p*PLEN;

    unsigned bQh = smem_u32(sm->Qh),  bQl = smem_u32(sm->Ql);
    unsigned bKh = smem_u32(sm->Kh),  bKl = smem_u32(sm->Kl);
    unsigned bKth = smem_u32(sm->Kth), bKtl = smem_u32(sm->Ktl);
    unsigned bVth = smem_u32(sm->Vth), bVtl = smem_u32(sm->Vtl);
    unsigned bVph = smem_u32(sm->Vph), bVpl = smem_u32(sm->Vpl);
    unsigned bAh = smem_u32(sm->Ah),  bAl = smem_u32(sm->Al);
    unsigned bSh = smem_u32(sm->Sh),  bSl = smem_u32(sm->Sl);

    auto fa = [&](unsigned bbase, int rowbase, int ks) -> unsigned {
        return bbase + (unsigned)((rowbase + lrow) * (2*SROWB) + ks*32 + lhi*16);
    };

    float s0[4][4];
    {
        const float* SIn = g_SIn + ((long)bh*NP + p)*4096;
        #pragma unroll
        for (int nf = 0; nf < 4; ++nf) {
            int dc = wn + nf*8 + 2*tg;
            s0[nf][0] = SIn[(wm + g)*64 + dc];
            s0[nf][1] = SIn[(wm + g)*64 + dc + 1];
            s0[nf][2] = SIn[(wm + g + 8)*64 + dc];
            s0[nf][3] = SIn[(wm + g + 8)*64 + dc + 1];
        }
    }
    if (tid < 64) sm->m0[0][tid] = g_MIn[((long)bh*NP + p)*64 + tid];
    int par = 0;
    __syncthreads();

    for (int c = 0; c < PLEN/64; ++c) {
        int c64 = c * 64;
        // ===== phase 1: gates, stage Q,K(+Kf),Vf, publish S0 regs =====
        if (w == 0) {
            float f0 = g_f[(long)(b*TT + p*PLEN + c64 + lane)*HH + h];
            float f1 = g_f[(long)(b*TT + p*PLEN + c64 + 32 + lane)*HH + h];
            float l0 = __logf(f0), l1 = __logf(f1);
            #pragma unroll
            for (int o = 1; o < 32; o <<= 1) {
                float n = __shfl_up_sync(0xFFFFFFFFu, l0, o);
                if (lane >= o) l0 += n;
            }
            #pragma unroll
            for (int o = 1; o < 32; o <<= 1) {
                float n = __shfl_up_sync(0xFFFFFFFFu, l1, o);
                if (lane >= o) l1 += n;
            }
            l1 += __shfl_sync(0xFFFFFFFFu, l0, 31);
            float total = __shfl_sync(0xFFFFFFFFu, l1, 31);
            sm->Lc[lane] = l0;      sm->Lc[32 + lane] = l1;
            sm->Ft[lane] = __expf(l0);  sm->Ft[32 + lane] = __expf(l1);
            sm->RL[lane] = __expf(total - l0);
            sm->RL[32 + lane] = __expf(total - l1);
        }
        {
            int t = tid >> 2, dq = (tid & 3) * 16;
            const float* qp = Qg + (long)(c64 + t)*CC + dq;
            const float* kp = Kg + (long)(c64 + t)*CC + dq;
            const float* vp = Vg + (long)(c64 + t)*CC + dq;
            #pragma unroll
            for (int j = 0; j < 4; ++j) {
                float4 q4 = *(const float4*)(qp + j*4);
                float4 k4 = *(const float4*)(kp + j*4);
                float4 v4 = *(const float4*)(vp + j*4);
                int d = dq + j*4;
                store_hl(&sm->Qh[0][0], &sm->Ql[0][0], t*SROWB + d,     q4.x, q4.y);
                store_hl(&sm->Qh[0][0], &sm->Ql[0][0], t*SROWB + d + 2, q4.z, q4.w);
                store_hl(&sm->Kh[0][0], &sm->Kl[0][0], t*SROWB + d,     k4.x, k4.y);
                store_hl(&sm->Kh[0][0], &sm->Kl[0][0], t*SROWB + d + 2, k4.z, k4.w);
                sm->Kf[t][d+0] = k4.x; sm->Kf[t][d+1] = k4.y;
                sm->Kf[t][d+2] = k4.z; sm->Kf[t][d+3] = k4.w;
                sm->Vf[t][d+0] = v4.x; sm->Vf[t][d+1] = v4.y;
                sm->Vf[t][d+2] = v4.z; sm->Vf[t][d+3] = v4.w;
            }
        }
        {
            int e0 = wm + g, e1 = wm + g + 8;
            #pragma unroll
            for (int nf = 0; nf < 4; ++nf) {
                int dcol = wn + nf*8 + 2*tg;
                store_hl(&sm->Sh[0][0], &sm->Sl[0][0], e0*SROWB + dcol, s0[nf][0], s0[nf][1]);
                store_hl(&sm->Sh[0][0], &sm->Sl[0][0], e1*SROWB + dcol, s0[nf][2], s0[nf][3]);
            }
        }
        __syncthreads();

        // ===== phase 2: transposes =====
        {
            int d = tid >> 2, sq = (tid & 3) * 16;
            #pragma unroll
            for (int i = 0; i < 8; ++i) {
                int s0i = sq + 2*i;
                float k0v = sm->Kf[s0i][d],   k1v = sm->Kf[s0i+1][d];
                float v0v = sm->Vf[s0i][d],   v1v = sm->Vf[s0i+1][d];
                store_hl(&sm->Kth[0][0], &sm->Ktl[0][0], d*SROWB + s0i, k0v, k1v);
                store_hl(&sm->Vth[0][0], &sm->Vtl[0][0], d*SROWB + s0i, v0v, v1v);
                float r0 = sm->RL[s0i], r1 = sm->RL[s0i+1];
                store_hl(&sm->Vph[0][0], &sm->Vpl[0][0], d*SROWB + s0i, v0v*r0, v1v*r1);
            }
        }
        __syncthreads();

        // ===== phase 3: A = Q.K^T, decay/mask =====
        {
            float a[4][4];
            #pragma unroll
            for (int i = 0; i < 4; ++i)
                #pragma unroll
                for (int j = 0; j < 4; ++j) a[i][j] = 0.0f;
            #pragma unroll
            for (int ks = 0; ks < 4; ++ks) {
                unsigned aH[4], aL[4];
                LDSM4(aH, fa(bQh, wm, ks));
                LDSM4(aL, fa(bQl, wm, ks));
                unsigned p0h[4], p0l[4], p1h[4], p1l[4];
                LDSM4(p0h, fa(bKh, wn, ks));
                LDSM4(p0l, fa(bKl, wn, ks));
                LDSM4(p1h, fa(bKh, wn + 16, ks));
                LDSM4(p1l, fa(bKl, wn + 16, ks));
                unsigned b0h[2]={p0h[0],p0h[2]}, b1h[2]={p0h[1],p0h[3]};
                unsigned b2h[2]={p1h[0],p1h[2]}, b3h[2]={p1h[1],p1h[3]};
                unsigned b0l[2]={p0l[0],p0l[2]}, b1l[2]={p0l[1],p0l[3]};
                unsigned b2l[2]={p1l[0],p1l[2]}, b3l[2]={p1l[1],p1l[3]};
                MMA_BF16(a[0], aH, b0h); MMA_BF16(a[1], aH, b1h);
                MMA_BF16(a[2], aH, b2h); MMA_BF16(a[3], aH, b3h);
                MMA_BF16(a[0], aH, b0l); MMA_BF16(a[1], aH, b1l);
                MMA_BF16(a[2], aH, b2l); MMA_BF16(a[3], aH, b3l);
                MMA_BF16(a[0], aL, b0h); MMA_BF16(a[1], aL, b1h);
                MMA_BF16(a[2], aL, b2h); MMA_BF16(a[3], aL, b3h);
            }
            int t0 = wm + g, t1 = t0 + 8;
            float lct0 = sm->Lc[t0], lct1 = sm->Lc[t1];
            #pragma unroll
            for (int nf = 0; nf < 4; ++nf) {
                int sc = wn + nf*8 + 2*tg;
                float lcs0 = sm->Lc[sc], lcs1 = sm->Lc[sc+1];
                a[nf][0] = (sc   <= t0) ? a[nf][0] * __expf(lct0 - lcs0) : 0.0f;
                a[nf][1] = (sc+1 <= t0) ? a[nf][1] * __expf(lct0 - lcs1) : 0.0f;
                a[nf][2] = (sc   <= t1) ? a[nf][2] * __expf(lct1 - lcs0) : 0.0f;
                a[nf][3] = (sc+1 <= t1) ? a[nf][3] * __expf(lct1 - lcs1) : 0.0f;
                store_hl(&sm->Ah[0][0], &sm->Al[0][0], t0*SROWB + sc, a[nf][0], a[nf][1]);
                store_hl(&sm->Ah[0][0], &sm->Al[0][0], t1*SROWB + sc, a[nf][2], a[nf][3]);
            }
        }
        __syncthreads();

        // ===== phase 4: O, state update, denom, m0 =====
        {
            float o1[4][4], o2[4][4];
            #pragma unroll
            for (int i = 0; i < 4; ++i)
                #pragma unroll
                for (int j = 0; j < 4; ++j) { o1[i][j] = 0.0f; o2[i][j] = 0.0f; }
            #pragma unroll
            for (int ks = 0; ks < 4; ++ks) {
                unsigned qH[4], qL[4], aAH[4], aAL[4];
                LDSM4(qH, fa(bQh, wm, ks));
                LDSM4(qL, fa(bQl, wm, ks));
                LDSM4(aAH, fa(bAh, wm, ks));
                LDSM4(aAL, fa(bAl, wm, ks));
                unsigned s0h4[4], s0l4[4], s1h4[4], s1l4[4];
                LDSM4(s0h4, fa(bSh, wn, ks));
                LDSM4(s0l4, fa(bSl, wn, ks));
                LDSM4(s1h4, fa(bSh, wn + 16, ks));
                LDSM4(s1l4, fa(bSl, wn + 16, ks));
                unsigned v0h4[4], v0l4[4], v1h4[4], v1l4[4];
                LDSM4(v0h4, fa(bVth, wn, ks));
                LDSM4(v0l4, fa(bVtl, wn, ks));
                LDSM4(v1h4, fa(bVth, wn + 16, ks));
                LDSM4(v1l4, fa(bVtl, wn + 16, ks));
                unsigned sb0h[2]={s0h4[0],s0h4[2]}, sb1h[2]={s0h4[1],s0h4[3]};
                unsigned sb2h[2]={s1h4[0],s1h4[2]}, sb3h[2]={s1h4[1],s1h4[3]};
                unsigned sb0l[2]={s0l4[0],s0l4[2]}, sb1l[2]={s0l4[1],s0l4[3]};
                unsigned sb2l[2]={s1l4[0],s1l4[2]}, sb3l[2]={s1l4[1],s1l4[3]};
                unsigned vb0h[2]={v0h4[0],v0h4[2]}, vb1h[2]={v0h4[1],v0h4[3]};
                unsigned vb2h[2]={v1h4[0],v1h4[2]}, vb3h[2]={v1h4[1],v1h4[3]};
                unsigned vb0l[2]={v0l4[0],v0l4[2]}, vb1l[2]={v0l4[1],v0l4[3]};
                unsigned vb2l[2]={v1l4[0],v1l4[2]}, vb3l[2]={v1l4[1],v1l4[3]};
                MMA_BF16(o1[0], qH, sb0h); MMA_BF16(o2[0], aAH, vb0h);
                MMA_BF16(o1[1], qH, sb1h); MMA_BF16(o2[1], aAH, vb1h);
                MMA_BF16(o1[2], qH, sb2h); MMA_BF16(o2[2], aAH, vb2h);
                MMA_BF16(o1[3], qH, sb3h); MMA_BF16(o2[3], aAH, vb3h);
                MMA_BF16(o1[0], qH, sb0l); MMA_BF16(o2[0], aAH, vb0l);
                MMA_BF16(o1[1], qH, sb1l); MMA_BF16(o2[1], aAH, vb1l);
                MMA_BF16(o1[2], qH, sb2l); MMA_BF16(o2[2], aAH, vb2l);
                MMA_BF16(o1[3], qH, sb3l); MMA_BF16(o2[3], aAH, vb3l);
                MMA_BF16(o1[0], qL, sb0h); MMA_BF16(o2[0], aAL, vb0h);
                MMA_BF16(o1[1], qL, sb1h); MMA_BF16(o2[1], aAL, vb1h);
                MMA_BF16(o1[2], qL, sb2h); MMA_BF16(o2[2], aAL, vb2h);
                MMA_BF16(o1[3], qL, sb3h); MMA_BF16(o2[3], aAL, vb3h);
            }
            int t0 = wm + g, t1 = t0 + 8;
            float ft0 = sm->Ft[t0], ft1 = sm->Ft[t1];
            #pragma unroll
            for (int nf = 0; nf < 4; ++nf) {
                int ec = wn + nf*8 + 2*tg;
                float2 w0 = make_float2(ft0*o1[nf][0] + o2[nf][0], ft0*o1[nf][1] + o2[nf][1]);
                float2 w1 = make_float2(ft1*o1[nf][2] + o2[nf][2], ft1*o1[nf][3] + o2[nf][3]);
                *(float2*)&Og[(long)(c64 + t0)*CC + ec] = w0;
                *(float2*)&Og[(long)(c64 + t1)*CC + ec] = w1;
            }

            float FL = sm->Ft[63];
            #pragma unroll
            for (int i = 0; i < 4; ++i)
                #pragma unroll
                for (int j = 0; j < 4; ++j) s0[i][j] *= FL;
            #pragma unroll
            for (int ks = 0; ks < 4; ++ks) {
                unsigned aH[4], aL[4];
                LDSM4(aH, fa(bVph, wm, ks));
                LDSM4(aL, fa(bVpl, wm, ks));
                unsigned p0h[4], p0l[4], p1h[4], p1l[4];
                LDSM4(p0h, fa(bKth, wn, ks));
                LDSM4(p0l, fa(bKtl, wn, ks));
                LDSM4(p1h, fa(bKth, wn + 16, ks));
                LDSM4(p1l, fa(bKtl, wn + 16, ks));
                unsigned b0h[2]={p0h[0],p0h[2]}, b1h[2]={p0h[1],p0h[3]};
                unsigned b2h[2]={p1h[0],p1h[2]}, b3h[2]={p1h[1],p1h[3]};
                unsigned b0l[2]={p0l[0],p0l[2]}, b1l[2]={p0l[1],p0l[3]};
                unsigned b2l[2]={p1l[0],p1l[2]}, b3l[2]={p1l[1],p1l[3]};
                MMA_BF16(s0[0], aH, b0h); MMA_BF16(s0[1], aH, b1h);
                MMA_BF16(s0[2], aH, b2h); MMA_BF16(s0[3], aH, b3h);
                MMA_BF16(s0[0], aH, b0l); MMA_BF16(s0[1], aH, b1l);
                MMA_BF16(s0[2], aH, b2l); MMA_BF16(s0[3], aH, b3l);
                MMA_BF16(s0[0], aL, b0h); MMA_BF16(s0[1], aL, b1h);
                MMA_BF16(s0[2], aL, b2h); MMA_BF16(s0[3], aL, b3h);
            }

            if (tid < 64) {
                int t = tid;
                float rs = 0.0f, qm = 0.0f;
                const __nv_bfloat162* ah = (const __nv_bfloat162*)&sm->Ah[t][0];
                const __nv_bfloat162* al = (const __nv_bfloat162*)&sm->Al[t][0];
                const __nv_bfloat162* qh = (const __nv_bfloat162*)&sm->Qh[t][0];
                const __nv_bfloat162* ql = (const __nv_bfloat162*)&sm->Ql[t][0];
                #pragma unroll 8
                for (int i = 0; i < 32; ++i) {
                    __nv_bfloat162 hv = ah[i], lv = al[i];
                    rs += __bfloat162float(hv.x) + __bfloat162float(hv.y)
                        + __bfloat162float(lv.x) + __bfloat162float(lv.y);
                    __nv_bfloat162 qhv = qh[i], qlv = ql[i];
                    float q0 = __bfloat162float(qhv.x) + __bfloat162float(qlv.x);
                    float q1 = __bfloat162float(qhv.y) + __bfloat162float(qlv.y);
                    qm += q0 * sm->m0[par][2*i] + q1 * sm->m0[par][2*i+1];
                }
                float den = sm->Ft[t] * qm + rs;
                Dg[c64 + t] = 1.0f / fmaxf(den, 1e-6f);
            } else if (tid < 128) {
                int d = tid - 64;
                float acc = 0.0f;
                #pragma unroll 8
                for (int s = 0; s < 64; ++s) acc += sm->RL[s] * sm->Kf[s][d];
                sm->m0[par ^ 1][d] = sm->Ft[63] * sm->m0[par][d] + acc;
            }
        }
        __syncthreads();
        par ^= 1;
    }
}

// ---------- LayerNorm ----------
__global__ void __launch_bounds__(256) k_ln(const float* __restrict__ lw,
                                            const float* __restrict__ lb,
                                            float* __restrict__ out) {
    int row = blockIdx.x, tid = threadIdx.x;
    int w = tid >> 5, l = tid & 31;
    const float4* y4 = (const float4*)(g_z + (long)row*CC);
    float4 a = y4[tid];
    float s1 = a.x + a.y + a.z + a.w;
    float s2 = a.x*a.x + a.y*a.y + a.z*a.z + a.w*a.w;
    #pragma unroll
    for (int off = 16; off; off >>= 1) {
        s1 += __shfl_xor_sync(0xFFFFFFFFu, s1, off);
        s2 += __shfl_xor_sync(0xFFFFFFFFu, s2, off);
    }
    __shared__ float r1[8], r2[8];
    if (l == 0) { r1[w] = s1; r2[w] = s2; }
    __syncthreads();
    if (w == 0) {
        s1 = (l < 8) ? r1[l] : 0.0f;
        s2 = (l < 8) ? r2[l] : 0.0f;
        #pragma unroll
        for (int off = 4; off; off >>= 1) {
            s1 += __shfl_xor_sync(0xFFFFFFFFu, s1, off);
            s2 += __shfl_xor_sync(0xFFFFFFFFu, s2, off);
        }
        if (l == 0) { r1[0] = s1; r2[0] = s2; }
    }
    __syncthreads();
    float mu = r1[0] * (1.0f / CC);
    float var = r2[0] * (1.0f / CC) - mu*mu;
    float rs = rsqrtf(var + 1e-5f);
    float4 wv = ((const float4*)lw)[tid];
    float4 bv = ((const float4*)lb)[tid];
    float4 o;
    o.x = (a.x - mu)*rs*wv.x + bv.x;
    o.y = (a.y - mu)*rs*wv.y + bv.y;
    o.z = (a.z - mu)*rs*wv.z + bv.z;
    o.w = (a.w - mu)*rs*wv.w + bv.w;
    ((float4*)(out + (long)row*CC))[tid] = o;
}

extern "C" void kernel_launch(void* const* d_in, const int* in_sizes, int n_in,
                              void* d_out, int out_size) {
    (void)in_sizes; (void)n_in; (void)out_size;
    const float* x    = (const float*)d_in[0];
    const int*   mask = (const int*)  d_in[1];
    const float* Wq   = (const float*)d_in[2];
    const float* Wk   = (const float*)d_in[3];
    const float* Wv   = (const float*)d_in[4];
    const float* Wg   = (const float*)d_in[5];
    const float* bg   = (const float*)d_in[6];
    const float* Wo   = (const float*)d_in[7];
    const float* bo   = (const float*)d_in[8];
    const float* lw   = (const float*)d_in[9];
    const float* lb   = (const float*)d_in[10];
    float* out = (float*)d_out;

    cudaFuncSetAttribute(k_gemm_qkv, cudaFuncAttributeMaxDynamicSharedMemorySize, GEMM_DSMEM);
    cudaFuncSetAttribute(k_gemm_out, cudaFuncAttributeMaxDynamicSharedMemorySize, GEMM_DSMEM);
    cudaFuncSetAttribute(k_scanA, cudaFuncAttributeMaxDynamicSharedMemorySize, SCANA_DSMEM);
    cudaFuncSetAttribute(k_scanC, cudaFuncAttributeMaxDynamicSharedMemorySize, SCAN_DSMEM);

    k_cvtall<<<4096 + 1024, 256>>>(x, Wq, Wk, Wv, Wo);                   // 1
    k_misc<<<512, 256>>>(x, Wg, bg, mask);                               // 2
    k_gemm_qkv<<<dim3(CC/128, BT/128, 3), 256, GEMM_DSMEM>>>(mask);      // 3
    k_scanA<<<BB*HH*NP, 256, SCANA_DSMEM>>>();                           // 4 (ncu slot)
    k_stitch<<<BB*HH, 256>>>();                                          // 5
    k_scanC<<<BB*HH*NP, 256, SCAN_DSMEM>>>();                            // 6
    k_cvtatt<<<(BT*CC/4)/256, 256>>>();                                  // 7
    k_gemm_out<<<dim3(CC/128, BT/128), 256, GEMM_DSMEM>>>(bo, x);        // 8
    k_ln<<<BT, 256>>>(lw, lb, out);                                      // 9
}

// round 16
// speedup vs baseline: 3.4048x; 1.0114x over previous
#include <cuda_runtime.h>
#include <cuda_bf16.h>
#include <math.h>

#define BB 2
#define TT 2048
#define CC 1024
#define HH 16
#define DD 64
#define BT (BB*TT)
#define NP 4
#define PLEN (TT/NP)   // 512

// ---------- scratch ----------
__device__ float g_q[BT*CC];
__device__ float g_k[BT*CC];
__device__ float g_v[BT*CC];
__device__ float g_z[BT*CC];
__device__ float g_f[BT*HH];
__device__ float g_cos[TT*32];
__device__ float g_sin[TT*32];

__device__ float g_dS[BB*HH*NP*4096];   // partition state deltas [e][d]
__device__ float g_SIn[BB*HH*NP*4096];  // partition inbound states
__device__ float g_dM[BB*HH*NP*64];
__device__ float g_MIn[BB*HH*NP*64];
__device__ float g_FP[BB*HH*NP];

__device__ __nv_bfloat16 g_xh[BT*CC], g_xl[BT*CC];
__device__ __nv_bfloat16 g_ath[BT*CC], g_atl[BT*CC];
__device__ __nv_bfloat16 g_wh[4][CC*CC], g_wl[4][CC*CC];

__device__ __forceinline__ float phi_f(float x) { return x > 0.0f ? x + 1.0f : expf(x); }

__device__ __forceinline__ unsigned smem_u32(const void* p) {
    unsigned a;
    asm("{ .reg .u64 t; cvta.to.shared.u64 t, %1; cvt.u32.u64 %0, t; }" : "=r"(a) : "l"(p));
    return a;
}

// ---------- cp.async / ldmatrix / mma ----------
#define CP_ASYNC16(dst, src) \
    asm volatile("cp.async.cg.shared.global [%0], [%1], 16;" :: "r"(dst), "l"(src))
#define CP_COMMIT() asm volatile("cp.async.commit_group;")
#define CP_WAIT1()  asm volatile("cp.async.wait_group 1;")

#define LDSM4(r, addr) \
    asm volatile("ldmatrix.sync.aligned.m8n8.x4.shared.b16 {%0,%1,%2,%3}, [%4];" \
        : "=r"((r)[0]), "=r"((r)[1]), "=r"((r)[2]), "=r"((r)[3]) : "r"(addr))

#define MMA_BF16(c, a, b) \
    asm volatile("mma.sync.aligned.m16n8k16.row.col.f32.bf16.bf16.f32 " \
                 "{%0,%1,%2,%3},{%4,%5,%6,%7},{%8,%9},{%0,%1,%2,%3};" \
                 : "+f"((c)[0]), "+f"((c)[1]), "+f"((c)[2]), "+f"((c)[3]) \
                 : "r"((a)[0]), "r"((a)[1]), "r"((a)[2]), "r"((a)[3]), \
                   "r"((b)[0]), "r"((b)[1]))

// ---------- bf16 hi/lo split stores ----------
__device__ __forceinline__ void store_hl(__nv_bfloat16* H, __nv_bfloat16* L, long idx,
                                         float v0, float v1) {
    __nv_bfloat16 h0 = __float2bfloat16(v0), h1 = __float2bfloat16(v1);
    __nv_bfloat162 hh; hh.x = h0; hh.y = h1;
    *(__nv_bfloat162*)(H + idx) = hh;
    __nv_bfloat162 ll;
    ll.x = __float2bfloat16(v0 - __bfloat162float(h0));
    ll.y = __float2bfloat16(v1 - __bfloat162float(h1));
    *(__nv_bfloat162*)(L + idx) = ll;
}

__device__ __forceinline__ void split_store(float4 v, __nv_bfloat16* dh, __nv_bfloat16* dl, long idx) {
    float vv[4] = {v.x, v.y, v.z, v.w};
    unsigned short h[4], l[4];
    #pragma unroll
    for (int i = 0; i < 4; ++i) {
        __nv_bfloat16 hb = __float2bfloat16(vv[i]);
        h[i] = __bfloat16_as_ushort(hb);
        l[i] = __bfloat16_as_ushort(__float2bfloat16(vv[i] - __bfloat162float(hb)));
    }
    *(uint2*)(dh + idx) = make_uint2(h[0] | ((unsigned)h[1]<<16), h[2] | ((unsigned)h[3]<<16));
    *(uint2*)(dl + idx) = make_uint2(l[0] | ((unsigned)l[1]<<16), l[2] | ((unsigned)l[3]<<16));
}

__global__ void __launch_bounds__(256) k_cvtall(const float* __restrict__ x,
                                                const float* __restrict__ Wq,
                                                const float* __restrict__ Wk,
                                                const float* __restrict__ Wv,
                                                const float* __restrict__ Wo) {
    int id = blockIdx.x * blockDim.x + threadIdx.x;
    if (blockIdx.x < 4096) {
        float4 v = ((const float4*)x)[id];
        split_store(v, g_xh, g_xl, (long)id*4);
    } else {
        int wid = id - 4096*256;
        int seg = wid >> 16;
        int off = wid & 0xFFFF;
        const float* src = seg == 0 ? Wq : seg == 1 ? Wk : seg == 2 ? Wv : Wo;
        #pragma unroll
        for (int r = 0; r < 4; ++r) {
            int o = off + r * 65536;
            float4 v = ((const float4*)src)[o];
            split_store(v, g_wh[seg], g_wl[seg], (long)o*4);
        }
    }
}

// ---------- fused fgate (blocks 0..255) + trig (blocks 256..511) ----------
__global__ void __launch_bounds__(256) k_misc(const float* __restrict__ x,
                                              const float* __restrict__ Wg,
                                              const float* __restrict__ bg,
                                              const int* __restrict__ mask) {
    if (blockIdx.x < 256) {
        __shared__ float xs[16][64];
        __shared__ float wsT[64][17];
        int tid = threadIdx.x;
        int row0 = blockIdx.x * 16;
        int lr = tid >> 4, lq = tid & 15;
        float acc = 0.0f;
        for (int k0 = 0; k0 < CC; k0 += 64) {
            float4 xv = *(const float4*)&x[(long)(row0+lr)*CC + k0 + lq*4];
            *(float4*)&xs[lr][lq*4] = xv;
            float4 wv = *(const float4*)&Wg[(long)lr*CC + k0 + lq*4];
            wsT[lq*4+0][lr] = wv.x; wsT[lq*4+1][lr] = wv.y;
            wsT[lq*4+2][lr] = wv.z; wsT[lq*4+3][lr] = wv.w;
            __syncthreads();
            #pragma unroll
            for (int kk = 0; kk < 64; ++kk) acc = fmaf(xs[lr][kk], wsT[kk][lq], acc);
            __syncthreads();
        }
        float zv = acc + bg[lq];
        float f = 1.0f / (1.0f + expf(-zv));
        f = fminf(fmaxf(f, 0.01f), 0.999f);
        float mk = (float)mask[row0 + lr];
        f = f * mk + (1.0f - mk);
        g_f[(long)(row0 + lr)*HH + lq] = f;
    } else {
        int gid = (blockIdx.x - 256) * 256 + threadIdx.x;
        int t = gid >> 5, i = gid & 31;
        float e = (float)i * (1.0f / 32.0f);
        float inv = 1.0f / powf(10000.0f, e);
        float fr = (float)t * inv;
        g_cos[gid] = cosf(fr);
        g_sin[gid] = sinf(fr);
    }
}

// ---------- bf16x3 GEMM: BK=32, 3-stage cp.async; fused epilogues ----------
#define GEMM_DSMEM (3*4*8192)

__device__ __forceinline__ void gemm_core(const __nv_bfloat16* __restrict__ Agh,
                                          const __nv_bfloat16* __restrict__ Agl,
                                          const __nv_bfloat16* __restrict__ Bgh,
                                          const __nv_bfloat16* __restrict__ Bgl,
                                          float* __restrict__ Cout,
                                          const float* __restrict__ bias,
                                          const float* __restrict__ resid,
                                          const int* __restrict__ mask,
                                          int mode)
{
    extern __shared__ __align__(16) char dynsm[];
    unsigned smb = smem_u32(dynsm);

    int tid = threadIdx.x;
    int m0 = blockIdx.y * 128;
    int n0 = blockIdx.x * 128;

    int prow = tid >> 1;
    int ph = tid & 1;
    const __nv_bfloat16* srcs[4];
    srcs[0] = Agh + (long)(m0 + prow) * CC + ph * 16;
    srcs[1] = Agl + (long)(m0 + prow) * CC + ph * 16;
    srcs[2] = Bgh + (long)(n0 + prow) * CC + ph * 16;
    srcs[3] = Bgl + (long)(n0 + prow) * CC + ph * 16;
    unsigned psw = (prow >> 1) & 3;
    unsigned d0off = prow * 64 + (((2u*ph) ^ psw) << 4);

    int warp = tid >> 5, lane = tid & 31;
    int g = lane >> 2, tg = lane & 3;
    int mbase = (warp >> 1) * 32;
    int nbase = (warp & 1) * 64;
    int lrow = lane & 15, lhi = lane >> 4;

    float c[2][8][4];
    #pragma unroll
    for (int mf = 0; mf < 2; ++mf)
        #pragma unroll
        for (int nf = 0; nf < 8; ++nf)
            #pragma unroll
            for (int j = 0; j < 4; ++j) c[mf][nf][j] = 0.0f;

    auto issue = [&](int kt) {
        unsigned sb = smb + (unsigned)(kt % 3) * 32768u;
        #pragma unroll
        for (int t = 0; t < 4; ++t) {
            const __nv_bfloat16* s = srcs[t] + kt * 32;
            unsigned d = sb + t * 8192 + d0off;
            CP_ASYNC16(d, s);
            CP_ASYNC16(d ^ 16u, s + 8);
        }
        CP_COMMIT();
    };

    auto lda = [&](unsigned sb, int t, int rowbase, int kh) -> unsigned {
        int r = rowbase + lrow;
        unsigned ch = (unsigned)(kh * 2 + lhi);
        return sb + t * 8192 + r * 64 + ((ch ^ ((unsigned)(r >> 1) & 3u)) << 4);
    };

    const int NT = CC / 32;
    issue(0);
    issue(1);

    for (int kt = 0; kt < NT; ++kt) {
        CP_WAIT1();
        __syncthreads();
        if (kt + 2 < NT) issue(kt + 2);

        unsigned sb = smb + (unsigned)(kt % 3) * 32768u;
        #pragma unroll
        for (int kh = 0; kh < 2; ++kh) {
            unsigned aH[2][4], aL[2][4];
            #pragma unroll
            for (int mf = 0; mf < 2; ++mf) {
                LDSM4(aH[mf], lda(sb, 0, mbase + mf*16, kh));
                LDSM4(aL[mf], lda(sb, 1, mbase + mf*16, kh));
            }
            #pragma unroll
            for (int nfp = 0; nfp < 4; ++nfp) {
                unsigned bh4[4], bl4[4];
                LDSM4(bh4, lda(sb, 2, nbase + nfp*16, kh));
                LDSM4(bl4, lda(sb, 3, nbase + nfp*16, kh));
                unsigned bh0[2] = {bh4[0], bh4[2]}, bh1[2] = {bh4[1], bh4[3]};
                unsigned bl0[2] = {bl4[0], bl4[2]}, bl1[2] = {bl4[1], bl4[3]};
                MMA_BF16(c[0][nfp*2],   aH[0], bh0);
                MMA_BF16(c[1][nfp*2],   aH[1], bh0);
                MMA_BF16(c[0][nfp*2+1], aH[0], bh1);
                MMA_BF16(c[1][nfp*2+1], aH[1], bh1);
                MMA_BF16(c[0][nfp*2],   aH[0], bl0);
                MMA_BF16(c[1][nfp*2],   aH[1], bl0);
                MMA_BF16(c[0][nfp*2+1], aH[0], bl1);
                MMA_BF16(c[1][nfp*2+1], aH[1], bl1);
                MMA_BF16(c[0][nfp*2],   aL[0], bh0);
                MMA_BF16(c[1][nfp*2],   aL[1], bh0);
                MMA_BF16(c[0][nfp*2+1], aL[0], bh1);
                MMA_BF16(c[1][nfp*2+1], aL[1], bh1);
            }
        }
    }

    if (mode != 2) {
        #pragma unroll
        for (int mf = 0; mf < 2; ++mf) {
            int r0_ = m0 + mbase + mf*16 + g;
            float mk0 = (float)mask[r0_];
            float mk1 = (float)mask[r0_ + 8];
            if (mode == 0) {
                #pragma unroll
                for (int nf = 0; nf < 8; ++nf) {
                    c[mf][nf][0] *= mk0; c[mf][nf][1] *= mk0;
                    c[mf][nf][2] *= mk1; c[mf][nf][3] *= mk1;
                }
            } else {
                int t_0 = r0_ & (TT-1), t_1 = (r0_+8) & (TT-1);
                #pragma unroll
                for (int nf = 0; nf < 4; ++nf) {
                    #pragma unroll
                    for (int idx = 0; idx < 2; ++idx) {
                        int i = nf*8 + 2*tg + idx;
                        float c0 = g_cos[t_0*32 + i], s0 = g_sin[t_0*32 + i];
                        float c1 = g_cos[t_1*32 + i], s1 = g_sin[t_1*32 + i];
                        float x1a = c[mf][nf][idx],   x2a = c[mf][nf+4][idx];
                        float x1b = c[mf][nf][idx+2], x2b = c[mf][nf+4][idx+2];
                        c[mf][nf][idx]     = phi_f(x1a*c0 - x2a*s0) * mk0;
                        c[mf][nf+4][idx]   = phi_f(x2a*c0 + x1a*s0) * mk0;
                        c[mf][nf][idx+2]   = phi_f(x1b*c1 - x2b*s1) * mk1;
                        c[mf][nf+4][idx+2] = phi_f(x2b*c1 + x1b*s1) * mk1;
                    }
                }
            }
        }
    }

    #pragma unroll
    for (int mf = 0; mf < 2; ++mf) {
        #pragma unroll
        for (int nf = 0; nf < 8; ++nf) {
            int r = m0 + mbase + mf*16 + g;
            int col = n0 + nbase + nf*8 + 2*tg;
            float2 v0 = make_float2(c[mf][nf][0], c[mf][nf][1]);
            float2 v1 = make_float2(c[mf][nf][2], c[mf][nf][3]);
            if (mode == 2) {
                float b0 = bias[col], b1 = bias[col+1];
                v0.x += b0 + resid[(long)r*CC + col];
                v0.y += b1 + resid[(long)r*CC + col + 1];
                v1.x += b0 + resid[(long)(r+8)*CC + col];
                v1.y += b1 + resid[(long)(r+8)*CC + col + 1];
            }
            *(float2*)&Cout[(long)r*CC + col]     = v0;
            *(float2*)&Cout[(long)(r+8)*CC + col] = v1;
        }
    }
}

__global__ void __launch_bounds__(256, 2) k_gemm_qkv(const int* __restrict__ mask) {
    int z = blockIdx.z;
    float* out = z == 0 ? g_q : (z == 1 ? g_k : g_v);
    gemm_core(g_xh, g_xl, g_wh[z], g_wl[z], out, nullptr, nullptr, mask, z == 2 ? 0 : 1);
}

__global__ void __launch_bounds__(256, 2) k_gemm_out(const float* __restrict__ bo,
                                                     const float* __restrict__ x) {
    gemm_core(g_ath, g_atl, g_wh[3], g_wl[3], g_z, bo, x, nullptr, 2);
}

// ---------- pass A: partition state deltas (128 blocks x 256) ----------
#define SROWB 72
struct ScanASM {
    __nv_bfloat16 Kth[64][SROWB], Ktl[64][SROWB];
    __nv_bfloat16 Vph[64][SROWB], Vpl[64][SROWB];
    float Kf[64][65], Vf[64][65];
    float Lc[64], Ft[64], RL[64];
};
#define SCANA_DSMEM ((int)sizeof(ScanASM))

__global__ void __launch_bounds__(256) k_scanA() {
    extern __shared__ __align__(16) char sbuf[];
    ScanASM* sm = (ScanASM*)sbuf;
    int bh = blockIdx.x >> 2, p = blockIdx.x & 3;
    int b = bh >> 4, h = bh & 15;
    int tid = threadIdx.x;
    int w = tid >> 5, lane = tid & 31;
    int g = lane >> 2, tg = lane & 3;
    int lrow = lane & 15, lhi = lane >> 4;
    int wm = (w >> 1) * 16;
    int wn = (w & 1) * 32;

    long base = (long)b*TT*CC + h*DD + (long)(p*PLEN)*CC;
    const float* Kg = g_k + base;
    const float* Vg = g_v + base;

    unsigned bKth = smem_u32(sm->Kth), bKtl = smem_u32(sm->Ktl);
    unsigned bVph = smem_u32(sm->Vph), bVpl = smem_u32(sm->Vpl);

    auto fa = [&](unsigned bbase, int rowbase, int ks) -> unsigned {
        return bbase + (unsigned)((rowbase + lrow) * (2*SROWB) + ks*32 + lhi*16);
    };

    float s0[4][4];
    #pragma unroll
    for (int i = 0; i < 4; ++i)
        #pragma unroll
        for (int j = 0; j < 4; ++j) s0[i][j] = 0.0f;
    float mreg = 0.0f;
    float ltot = 0.0f;

    for (int cc = 0; cc < PLEN/64; ++cc) {
        int c64 = cc * 64;
        if (w == 0) {
            float f0 = g_f[(long)(b*TT + p*PLEN + c64 + lane)*HH + h];
            float f1 = g_f[(long)(b*TT + p*PLEN + c64 + 32 + lane)*HH + h];
            float l0 = __logf(f0), l1 = __logf(f1);
            #pragma unroll
            for (int o = 1; o < 32; o <<= 1) {
                float n = __shfl_up_sync(0xFFFFFFFFu, l0, o);
                if (lane >= o) l0 += n;
            }
            #pragma unroll
            for (int o = 1; o < 32; o <<= 1) {
                float n = __shfl_up_sync(0xFFFFFFFFu, l1, o);
                if (lane >= o) l1 += n;
            }
            l1 += __shfl_sync(0xFFFFFFFFu, l0, 31);
            float total = __shfl_sync(0xFFFFFFFFu, l1, 31);
            ltot += total;
            sm->Lc[lane] = l0;      sm->Lc[32 + lane] = l1;
            sm->Ft[lane] = __expf(l0);  sm->Ft[32 + lane] = __expf(l1);
            sm->RL[lane] = __expf(total - l0);
            sm->RL[32 + lane] = __expf(total - l1);
        }
        {
            int t = tid >> 2, dq = (tid & 3) * 16;
            const float* kp = Kg + (long)(c64 + t)*CC + dq;
            const float* vp = Vg + (long)(c64 + t)*CC + dq;
            #pragma unroll
            for (int j = 0; j < 4; ++j) {
                float4 k4 = *(const float4*)(kp + j*4);
                float4 v4 = *(const float4*)(vp + j*4);
                int d = dq + j*4;
                sm->Kf[t][d+0] = k4.x; sm->Kf[t][d+1] = k4.y;
                sm->Kf[t][d+2] = k4.z; sm->Kf[t][d+3] = k4.w;
                sm->Vf[t][d+0] = v4.x; sm->Vf[t][d+1] = v4.y;
                sm->Vf[t][d+2] = v4.z; sm->Vf[t][d+3] = v4.w;
            }
        }
        __syncthreads();

        {
            int d = tid >> 2, sq = (tid & 3) * 16;
            #pragma unroll
            for (int i = 0; i < 8; ++i) {
                int s0i = sq + 2*i;
                float k0v = sm->Kf[s0i][d],   k1v = sm->Kf[s0i+1][d];
                float v0v = sm->Vf[s0i][d],   v1v = sm->Vf[s0i+1][d];
                store_hl(&sm->Kth[0][0], &sm->Ktl[0][0], d*SROWB + s0i, k0v, k1v);
                float r0 = sm->RL[s0i], r1 = sm->RL[s0i+1];
                store_hl(&sm->Vph[0][0], &sm->Vpl[0][0], d*SROWB + s0i, v0v*r0, v1v*r1);
            }
        }
        __syncthreads();

        {
            float FL = sm->Ft[63];
            #pragma unroll
            for (int i = 0; i < 4; ++i)
                #pragma unroll
                for (int j = 0; j < 4; ++j) s0[i][j] *= FL;
            #pragma unroll
            for (int ks = 0; ks < 4; ++ks) {
                unsigned aH[4], aL[4];
                LDSM4(aH, fa(bVph, wm, ks));
                LDSM4(aL, fa(bVpl, wm, ks));
                unsigned p0h[4], p0l[4], p1h[4], p1l[4];
                LDSM4(p0h, fa(bKth, wn, ks));
                LDSM4(p0l, fa(bKtl, wn, ks));
                LDSM4(p1h, fa(bKth, wn + 16, ks));
                LDSM4(p1l, fa(bKtl, wn + 16, ks));
                unsigned b0h[2]={p0h[0],p0h[2]}, b1h[2]={p0h[1],p0h[3]};
                unsigned b2h[2]={p1h[0],p1h[2]}, b3h[2]={p1h[1],p1h[3]};
                unsigned b0l[2]={p0l[0],p0l[2]}, b1l[2]={p0l[1],p0l[3]};
                unsigned b2l[2]={p1l[0],p1l[2]}, b3l[2]={p1l[1],p1l[3]};
                MMA_BF16(s0[0], aH, b0h); MMA_BF16(s0[1], aH, b1h);
                MMA_BF16(s0[2], aH, b2h); MMA_BF16(s0[3], aH, b3h);
                MMA_BF16(s0[0], aH, b0l); MMA_BF16(s0[1], aH, b1l);
                MMA_BF16(s0[2], aH, b2l); MMA_BF16(s0[3], aH, b3l);
                MMA_BF16(s0[0], aL, b0h); MMA_BF16(s0[1], aL, b1h);
                MMA_BF16(s0[2], aL, b2h); MMA_BF16(s0[3], aL, b3h);
            }
            if (tid >= 64 && tid < 128) {
                int d = tid - 64;
                float acc = 0.0f;
                #pragma unroll 8
                for (int s = 0; s < 64; ++s) acc += sm->RL[s] * sm->Kf[s][d];
                mreg = FL * mreg + acc;
            }
        }
        __syncthreads();
    }

    float* dS = g_dS + ((long)bh*NP + p)*4096;
    #pragma unroll
    for (int nf = 0; nf < 4; ++nf) {
        int dc = wn + nf*8 + 2*tg;
        dS[(wm + g)*64 + dc]     = s0[nf][0];
        dS[(wm + g)*64 + dc + 1] = s0[nf][1];
        dS[(wm + g + 8)*64 + dc]     = s0[nf][2];
        dS[(wm + g + 8)*64 + dc + 1] = s0[nf][3];
    }
    if (tid >= 64 && tid < 128)
        g_dM[((long)bh*NP + p)*64 + tid - 64] = mreg;
    if (tid == 0)
        g_FP[bh*NP + p] = __expf(ltot);
}

// ---------- pass B: stitch partition states (32 blocks x 256) ----------
__global__ void __launch_bounds__(256) k_stitch() {
    int bh = blockIdx.x;
    float f1 = g_FP[bh*NP + 1], f2 = g_FP[bh*NP + 2];
    const float* dS = g_dS + (long)bh*NP*4096;
    float* SIn = g_SIn + (long)bh*NP*4096;
    for (int i = threadIdx.x; i < 4096; i += 256) {
        float s1 = dS[i];
        float s2 = f1*s1 + dS[4096 + i];
        float s3 = f2*s2 + dS[2*4096 + i];
        SIn[i] = 0.0f;
        SIn[4096 + i] = s1;
        SIn[2*4096 + i] = s2;
        SIn[3*4096 + i] = s3;
    }
    if (threadIdx.x < 64) {
        int d = threadIdx.x;
        const float* dM = g_dM + (long)bh*NP*64;
        float* MIn = g_MIn + (long)bh*NP*64;
        float m1 = dM[d];
        float m2 = f1*m1 + dM[64 + d];
        float m3 = f2*m2 + dM[128 + d];
        MIn[d] = 0.0f;
        MIn[64 + d] = m1;
        MIn[128 + d] = m2;
        MIn[192 + d] = m3;
    }
}

// ---------- pass C: chunked scan, fused normalize + bf16 split output ----------
struct ScanSM {
    __nv_bfloat16 Qh[64][SROWB], Ql[64][SROWB];
    __nv_bfloat16 Kh[64][SROWB], Kl[64][SROWB];
    __nv_bfloat16 Kth[64][SROWB], Ktl[64][SROWB];
    __nv_bfloat16 Vth[64][SROWB], Vtl[64][SROWB];
    __nv_bfloat16 Vph[64][SROWB], Vpl[64][SROWB];
    __nv_bfloat16 Ah[64][SROWB], Al[64][SROWB];
    __nv_bfloat16 Sh[64][SROWB], Sl[64][SROWB];
    float Kf[64][65];
    float Vf[64][65];
    float Lc[64], Ft[64], RL[64], Rd[64];
    float m0[2][64];
};
#define SCAN_DSMEM ((int)sizeof(ScanSM))

__global__ void __launch_bounds__(256) k_scanC() {
    extern __shared__ __align__(16) char sbuf[];
    ScanSM* sm = (ScanSM*)sbuf;
    int bh = blockIdx.x >> 2, p = blockIdx.x & 3;
    int b = bh >> 4, h = bh & 15;
    int tid = threadIdx.x;
    int w = tid >> 5, lane = tid & 31;
    int g = lane >> 2, tg = lane & 3;
    int lrow = lane & 15, lhi = lane >> 4;
    int wm = (w >> 1) * 16;
    int wn = (w & 1) * 32;

    long base = (long)b*TT*CC + h*DD + (long)(p*PLEN)*CC;
    const float* Qg = g_q + base;
    const float* Kg = g_k + base;
    const float* Vg = g_v + base;
    __nv_bfloat16* Ohg = g_ath + base;
    __nv_bfloat16* Olg = g_atl + base;

    unsigned bQh = smem_u32(sm->Qh),  bQl = smem_u32(sm->Ql);
    unsigned bKh = smem_u32(sm->Kh),  bKl = smem_u32(sm->Kl);
    unsigned bKth = smem_u32(sm->Kth), bKtl = smem_u32(sm->Ktl);
    unsigned bVth = smem_u32(sm->Vth), bVtl = smem_u32(sm->Vtl);
    unsigned bVph = smem_u32(sm->Vph), bVpl = smem_u32(sm->Vpl);
    unsigned bAh = smem_u32(sm->Ah),  bAl = smem_u32(sm->Al);
    unsigned bSh = smem_u32(sm->Sh),  bSl = smem_u32(sm->Sl);

    auto fa = [&](unsigned bbase, int rowbase, int ks) -> unsigned {
        return bbase + (unsigned)((rowbase + lrow) * (2*SROWB) + ks*32 + lhi*16);
    };

    float s0[4][4];
    {
        const float* SIn = g_SIn + ((long)bh*NP + p)*4096;
        #pragma unroll
        for (int nf = 0; nf < 4; ++nf) {
            int dc = wn + nf*8 + 2*tg;
            s0[nf][0] = SIn[(wm + g)*64 + dc];
            s0[nf][1] = SIn[(wm + g)*64 + dc + 1];
            s0[nf][2] = SIn[(wm + g + 8)*64 + dc];
            s0[nf][3] = SIn[(wm + g + 8)*64 + dc + 1];
        }
    }
    if (tid < 64) sm->m0[0][tid] = g_MIn[((long)bh*NP + p)*64 + tid];
    int par = 0;
    __syncthreads();

    for (int c = 0; c < PLEN/64; ++c) {
        int c64 = c * 64;
        // ===== phase 1: gates, stage Q,K(+Kf),Vf, publish S0 regs =====
        if (w == 0) {
            float f0 = g_f[(long)(b*TT + p*PLEN + c64 + lane)*HH + h];
            float f1 = g_f[(long)(b*TT + p*PLEN + c64 + 32 + lane)*HH + h];
            float l0 = __logf(f0), l1 = __logf(f1);
            #pragma unroll
            for (int o = 1; o < 32; o <<= 1) {
                float n = __shfl_up_sync(0xFFFFFFFFu, l0, o);
                if (lane >= o) l0 += n;
            }
            #pragma unroll
            for (int o = 1; o < 32; o <<= 1) {
                float n = __shfl_up_sync(0xFFFFFFFFu, l1, o);
                if (lane >= o) l1 += n;
            }
            l1 += __shfl_sync(0xFFFFFFFFu, l0, 31);
            float total = __shfl_sync(0xFFFFFFFFu, l1, 31);
            sm->Lc[lane] = l0;      sm->Lc[32 + lane] = l1;
            sm->Ft[lane] = __expf(l0);  sm->Ft[32 + lane] = __expf(l1);
            sm->RL[lane] = __expf(total - l0);
            sm->RL[32 + lane] = __expf(total - l1);
        }
        {
            int t = tid >> 2, dq = (tid & 3) * 16;
            const float* qp = Qg + (long)(c64 + t)*CC + dq;
            const float* kp = Kg + (long)(c64 + t)*CC + dq;
            const float* vp = Vg + (long)(c64 + t)*CC + dq;
            #pragma unroll
            for (int j = 0; j < 4; ++j) {
                float4 q4 = *(const float4*)(qp + j*4);
                float4 k4 = *(const float4*)(kp + j*4);
                float4 v4 = *(const float4*)(vp + j*4);
                int d = dq + j*4;
                store_hl(&sm->Qh[0][0], &sm->Ql[0][0], t*SROWB + d,     q4.x, q4.y);
                store_hl(&sm->Qh[0][0], &sm->Ql[0][0], t*SROWB + d + 2, q4.z, q4.w);
                store_hl(&sm->Kh[0][0], &sm->Kl[0][0], t*SROWB + d,     k4.x, k4.y);
                store_hl(&sm->Kh[0][0], &sm->Kl[0][0], t*SROWB + d + 2, k4.z, k4.w);
                sm->Kf[t][d+0] = k4.x; sm->Kf[t][d+1] = k4.y;
                sm->Kf[t][d+2] = k4.z; sm->Kf[t][d+3] = k4.w;
                sm->Vf[t][d+0] = v4.x; sm->Vf[t][d+1] = v4.y;
                sm->Vf[t][d+2] = v4.z; sm->Vf[t][d+3] = v4.w;
            }
        }
        {
            int e0 = wm + g, e1 = wm + g + 8;
            #pragma unroll
            for (int nf = 0; nf < 4; ++nf) {
                int dcol = wn + nf*8 + 2*tg;
                store_hl(&sm->Sh[0][0], &sm->Sl[0][0], e0*SROWB + dcol, s0[nf][0], s0[nf][1]);
                store_hl(&sm->Sh[0][0], &sm->Sl[0][0], e1*SROWB + dcol, s0[nf][2], s0[nf][3]);
            }
        }
        __syncthreads();

        // ===== phase 2: transposes =====
        {
            int d = tid >> 2, sq = (tid & 3) * 16;
            #pragma unroll
            for (int i = 0; i < 8; ++i) {
                int s0i = sq + 2*i;
                float k0v = sm->Kf[s0i][d],   k1v = sm->Kf[s0i+1][d];
                float v0v = sm->Vf[s0i][d],   v1v = sm->Vf[s0i+1][d];
                store_hl(&sm->Kth[0][0], &sm->Ktl[0][0], d*SROWB + s0i, k0v, k1v);
                store_hl(&sm->Vth[0][0], &sm->Vtl[0][0], d*SROWB + s0i, v0v, v1v);
                float r0 = sm->RL[s0i], r1 = sm->RL[s0i+1];
                store_hl(&sm->Vph[0][0], &sm->Vpl[0][0], d*SROWB + s0i, v0v*r0, v1v*r1);
            }
        }
        __syncthreads();

        // ===== phase 3: A = Q.K^T, decay/mask =====
        {
            float a[4][4];
            #pragma unroll
            for (int i = 0; i < 4; ++i)
                #pragma unroll
                for (int j = 0; j < 4; ++j) a[i][j] = 0.0f;
            #pragma unroll
            for (int ks = 0; ks < 4; ++ks) {
                unsigned aH[4], aL[4];
                LDSM4(aH, fa(bQh, wm, ks));
                LDSM4(aL, fa(bQl, wm, ks));
                unsigned p0h[4], p0l[4], p1h[4], p1l[4];
                LDSM4(p0h, fa(bKh, wn, ks));
                LDSM4(p0l, fa(bKl, wn, ks));
                LDSM4(p1h, fa(bKh, wn + 16, ks));
                LDSM4(p1l, fa(bKl, wn + 16, ks));
                unsigned b0h[2]={p0h[0],p0h[2]}, b1h[2]={p0h[1],p0h[3]};
                unsigned b2h[2]={p1h[0],p1h[2]}, b3h[2]={p1h[1],p1h[3]};
                unsigned b0l[2]={p0l[0],p0l[2]}, b1l[2]={p0l[1],p0l[3]};
                unsigned b2l[2]={p1l[0],p1l[2]}, b3l[2]={p1l[1],p1l[3]};
                MMA_BF16(a[0], aH, b0h); MMA_BF16(a[1], aH, b1h);
                MMA_BF16(a[2], aH, b2h); MMA_BF16(a[3], aH, b3h);
                MMA_BF16(a[0], aH, b0l); MMA_BF16(a[1], aH, b1l);
                MMA_BF16(a[2], aH, b2l); MMA_BF16(a[3], aH, b3l);
                MMA_BF16(a[0], aL, b0h); MMA_BF16(a[1], aL, b1h);
                MMA_BF16(a[2], aL, b2h); MMA_BF16(a[3], aL, b3h);
            }
            int t0 = wm + g, t1 = t0 + 8;
            float lct0 = sm->Lc[t0], lct1 = sm->Lc[t1];
            #pragma unroll
            for (int nf = 0; nf < 4; ++nf) {
                int sc = wn + nf*8 + 2*tg;
                float lcs0 = sm->Lc[sc], lcs1 = sm->Lc[sc+1];
                a[nf][0] = (sc   <= t0) ? a[nf][0] * __expf(lct0 - lcs0) : 0.0f;
                a[nf][1] = (sc+1 <= t0) ? a[nf][1] * __expf(lct0 - lcs1) : 0.0f;
                a[nf][2] = (sc   <= t1) ? a[nf][2] * __expf(lct1 - lcs0) : 0.0f;
                a[nf][3] = (sc+1 <= t1) ? a[nf][3] * __expf(lct1 - lcs1) : 0.0f;
                store_hl(&sm->Ah[0][0], &sm->Al[0][0], t0*SROWB + sc, a[nf][0], a[nf][1]);
                store_hl(&sm->Ah[0][0], &sm->Al[0][0], t1*SROWB + sc, a[nf][2], a[nf][3]);
            }
        }
        __syncthreads();

        // ===== phase 4a: denominator + m0 update =====
        if (tid < 64) {
            int t = tid;
            float rs = 0.0f, qm = 0.0f;
            const __nv_bfloat162* ah = (const __nv_bfloat162*)&sm->Ah[t][0];
            const __nv_bfloat162* al = (const __nv_bfloat162*)&sm->Al[t][0];
            const __nv_bfloat162* qh = (const __nv_bfloat162*)&sm->Qh[t][0];
            const __nv_bfloat162* ql = (const __nv_bfloat162*)&sm->Ql[t][0];
            #pragma unroll 8
            for (int i = 0; i < 32; ++i) {
                __nv_bfloat162 hv = ah[i], lv = al[i];
                rs += __bfloat162float(hv.x) + __bfloat162float(hv.y)
                    + __bfloat162float(lv.x) + __bfloat162float(lv.y);
                __nv_bfloat162 qhv = qh[i], qlv = ql[i];
                float q0 = __bfloat162float(qhv.x) + __bfloat162float(qlv.x);
                float q1 = __bfloat162float(qhv.y) + __bfloat162float(qlv.y);
                qm += q0 * sm->m0[par][2*i] + q1 * sm->m0[par][2*i+1];
            }
            float den = sm->Ft[t] * qm + rs;
            sm->Rd[t] = 1.0f / fmaxf(den, 1e-6f);
        } else if (tid < 128) {
            int d = tid - 64;
            float acc = 0.0f;
            #pragma unroll 8
            for (int s = 0; s < 64; ++s) acc += sm->RL[s] * sm->Kf[s][d];
            sm->m0[par ^ 1][d] = sm->Ft[63] * sm->m0[par][d] + acc;
        }
        __syncthreads();

        // ===== phase 4b: O = Rd*(Ft*(Q.S0T) + A.Vt) -> bf16 h/l ; state update =====
        {
            float o1[4][4], o2[4][4];
            #pragma unroll
            for (int i = 0; i < 4; ++i)
                #pragma unroll
                for (int j = 0; j < 4; ++j) { o1[i][j] = 0.0f; o2[i][j] = 0.0f; }
            #pragma unroll
            for (int ks = 0; ks < 4; ++ks) {
                unsigned qH[4], qL[4], aAH[4], aAL[4];
                LDSM4(qH, fa(bQh, wm, ks));
                LDSM4(qL, fa(bQl, wm, ks));
                LDSM4(aAH, fa(bAh, wm, ks));
                LDSM4(aAL, fa(bAl, wm, ks));
                unsigned s0h4[4], s0l4[4], s1h4[4], s1l4[4];
                LDSM4(s0h4, fa(bSh, wn, ks));
                LDSM4(s0l4, fa(bSl, wn, ks));
                LDSM4(s1h4, fa(bSh, wn + 16, ks));
                LDSM4(s1l4, fa(bSl, wn + 16, ks));
                unsigned v0h4[4], v0l4[4], v1h4[4], v1l4[4];
                LDSM4(v0h4, fa(bVth, wn, ks));
                LDSM4(v0l4, fa(bVtl, wn, ks));
                LDSM4(v1h4, fa(bVth, wn + 16, ks));
                LDSM4(v1l4, fa(bVtl, wn + 16, ks));
                unsigned sb0h[2]={s0h4[0],s0h4[2]}, sb1h[2]={s0h4[1],s0h4[3]};
                unsigned sb2h[2]={s1h4[0],s1h4[2]}, sb3h[2]={s1h4[1],s1h4[3]};
                unsigned sb0l[2]={s0l4[0],s0l4[2]}, sb1l[2]={s0l4[1],s0l4[3]};
                unsigned sb2l[2]={s1l4[0],s1l4[2]}, sb3l[2]={s1l4[1],s1l4[3]};
                unsigned vb0h[2]={v0h4[0],v0h4[2]}, vb1h[2]={v0h4[1],v0h4[3]};
                unsigned vb2h[2]={v1h4[0],v1h4[2]}, vb3h[2]={v1h4[1],v1h4[3]};
                unsigned vb0l[2]={v0l4[0],v0l4[2]}, vb1l[2]={v0l4[1],v0l4[3]};
                unsigned vb2l[2]={v1l4[0],v1l4[2]}, vb3l[2]={v1l4[1],v1l4[3]};
                MMA_BF16(o1[0], qH, sb0h); MMA_BF16(o2[0], aAH, vb0h);
                MMA_BF16(o1[1], qH, sb1h); MMA_BF16(o2[1], aAH, vb1h);
                MMA_BF16(o1[2], qH, sb2h); MMA_BF16(o2[2], aAH, vb2h);
                MMA_BF16(o1[3], qH, sb3h); MMA_BF16(o2[3], aAH, vb3h);
                MMA_BF16(o1[0], qH, sb0l); MMA_BF16(o2[0], aAH, vb0l);
                MMA_BF16(o1[1], qH, sb1l); MMA_BF16(o2[1], aAH, vb1l);
                MMA_BF16(o1[2], qH, sb2l); MMA_BF16(o2[2], aAH, vb2l);
                MMA_BF16(o1[3], qH, sb3l); MMA_BF16(o2[3], aAH, vb3l);
                MMA_BF16(o1[0], qL, sb0h); MMA_BF16(o2[0], aAL, vb0h);
                MMA_BF16(o1[1], qL, sb1h); MMA_BF16(o2[1], aAL, vb1h);
                MMA_BF16(o1[2], qL, sb2h); MMA_BF16(o2[2], aAL, vb2h);
                MMA_BF16(o1[3], qL, sb3h); MMA_BF16(o2[3], aAL, vb3h);
            }
            int t0 = wm + g, t1 = t0 + 8;
            float ft0 = sm->Ft[t0], ft1 = sm->Ft[t1];
            float rd0 = sm->Rd[t0], rd1 = sm->Rd[t1];
            #pragma unroll
            for (int nf = 0; nf < 4; ++nf) {
                int ec = wn + nf*8 + 2*tg;
                float w0x = (ft0*o1[nf][0] + o2[nf][0]) * rd0;
                float w0y = (ft0*o1[nf][1] + o2[nf][1]) * rd0;
                float w1x = (ft1*o1[nf][2] + o2[nf][2]) * rd1;
                float w1y = (ft1*o1[nf][3] + o2[nf][3]) * rd1;
                store_hl(Ohg, Olg, (long)(c64 + t0)*CC + ec, w0x, w0y);
                store_hl(Ohg, Olg, (long)(c64 + t1)*CC + ec, w1x, w1y);
            }

            float FL = sm->Ft[63];
            #pragma unroll
            for (int i = 0; i < 4; ++i)
                #pragma unroll
                for (int j = 0; j < 4; ++j) s0[i][j] *= FL;
            #pragma unroll
            for (int ks = 0; ks < 4; ++ks) {
                unsigned aH[4], aL[4];
                LDSM4(aH, fa(bVph, wm, ks));
                LDSM4(aL, fa(bVpl, wm, ks));
                unsigned p0h[4], p0l[4], p1h[4], p1l[4];
                LDSM4(p0h, fa(bKth, wn, ks));
                LDSM4(p0l, fa(bKtl, wn, ks));
                LDSM4(p1h, fa(bKth, wn + 16, ks));
                LDSM4(p1l, fa(bKtl, wn + 16, ks));
                unsigned b0h[2]={p0h[0],p0h[2]}, b1h[2]={p0h[1],p0h[3]};
                unsigned b2h[2]={p1h[0],p1h[2]}, b3h[2]={p1h[1],p1h[3]};
                unsigned b0l[2]={p0l[0],p0l[2]}, b1l[2]={p0l[1],p0l[3]};
                unsigned b2l[2]={p1l[0],p1l[2]}, b3l[2]={p1l[1],p1l[3]};
                MMA_BF16(s0[0], aH, b0h); MMA_BF16(s0[1], aH, b1h);
                MMA_BF16(s0[2], aH, b2h); MMA_BF16(s0[3], aH, b3h);
                MMA_BF16(s0[0], aH, b0l); MMA_BF16(s0[1], aH, b1l);
                MMA_BF16(s0[2], aH, b2l); MMA_BF16(s0[3], aH, b3l);
                MMA_BF16(s0[0], aL, b0h); MMA_BF16(s0[1], aL, b1h);
                MMA_BF16(s0[2], aL, b2h); MMA_BF16(s0[3], aL, b3h);
            }
        }
        __syncthreads();
        par ^= 1;
    }
}

// ---------- LayerNorm ----------
__global__ void __launch_bounds__(256) k_ln(const float* __restrict__ lw,
                                            const float* __restrict__ lb,
                                            float* __restrict__ out) {
    int row = blockIdx.x, tid = threadIdx.x;
    int w = tid >> 5, l = tid & 31;
    const float4* y4 = (const float4*)(g_z + (long)row*CC);
    float4 a = y4[tid];
    float s1 = a.x + a.y + a.z + a.w;
    float s2 = a.x*a.x + a.y*a.y + a.z*a.z + a.w*a.w;
    #pragma unroll
    for (int off = 16; off; off >>= 1) {
        s1 += __shfl_xor_sync(0xFFFFFFFFu, s1, off);
        s2 += __shfl_xor_sync(0xFFFFFFFFu, s2, off);
    }
    __shared__ float r1[8], r2[8];
    if (l == 0) { r1[w] = s1; r2[w] = s2; }
    __syncthreads();
    if (w == 0) {
        s1 = (l < 8) ? r1[l] : 0.0f;
        s2 = (l < 8) ? r2[l] : 0.0f;
        #pragma unroll
        for (int off = 4; off; off >>= 1) {
            s1 += __shfl_xor_sync(0xFFFFFFFFu, s1, off);
            s2 += __shfl_xor_sync(0xFFFFFFFFu, s2, off);
        }
        if (l == 0) { r1[0] = s1; r2[0] = s2; }
    }
    __syncthreads();
    float mu = r1[0] * (1.0f / CC);
    float var = r2[0] * (1.0f / CC) - mu*mu;
    float rs = rsqrtf(var + 1e-5f);
    float4 wv = ((const float4*)lw)[tid];
    float4 bv = ((const float4*)lb)[tid];
    float4 o;
    o.x = (a.x - mu)*rs*wv.x + bv.x;
    o.y = (a.y - mu)*rs*wv.y + bv.y;
    o.z = (a.z - mu)*rs*wv.z + bv.z;
    o.w = (a.w - mu)*rs*wv.w + bv.w;
    ((float4*)(out + (long)row*CC))[tid] = o;
}

extern "C" void kernel_launch(void* const* d_in, const int* in_sizes, int n_in,
                              void* d_out, int out_size) {
    (void)in_sizes; (void)n_in; (void)out_size;
    const float* x    = (const float*)d_in[0];
    const int*   mask = (const int*)  d_in[1];
    const float* Wq   = (const float*)d_in[2];
    const float* Wk   = (const float*)d_in[3];
    const float* Wv   = (const float*)d_in[4];
    const float* Wg   = (const float*)d_in[5];
    const float* bg   = (const float*)d_in[6];
    const float* Wo   = (const float*)d_in[7];
    const float* bo   = (const float*)d_in[8];
    const float* lw   = (const float*)d_in[9];
    const float* lb   = (const float*)d_in[10];
    float* out = (float*)d_out;

    cudaFuncSetAttribute(k_gemm_qkv, cudaFuncAttributeMaxDynamicSharedMemorySize, GEMM_DSMEM);
    cudaFuncSetAttribute(k_gemm_out, cudaFuncAttributeMaxDynamicSharedMemorySize, GEMM_DSMEM);
    cudaFuncSetAttribute(k_scanA, cudaFuncAttributeMaxDynamicSharedMemorySize, SCANA_DSMEM);
    cudaFuncSetAttribute(k_scanC, cudaFuncAttributeMaxDynamicSharedMemorySize, SCAN_DSMEM);

    k_cvtall<<<4096 + 1024, 256>>>(x, Wq, Wk, Wv, Wo);                   // 1
    k_misc<<<512, 256>>>(x, Wg, bg, mask);                               // 2
    k_gemm_qkv<<<dim3(CC/128, BT/128, 3), 256, GEMM_DSMEM>>>(mask);      // 3
    k_scanA<<<BB*HH*NP, 256, SCANA_DSMEM>>>();                           // 4 (ncu slot)
    k_stitch<<<BB*HH, 256>>>();                                          // 5
    k_scanC<<<BB*HH*NP, 256, SCAN_DSMEM>>>();                            // 6
    k_gemm_out<<<dim3(CC/128, BT/128), 256, GEMM_DSMEM>>>(bo, x);        // 7
    k_ln<<<BT, 256>>>(lw, lb, out);                                      // 8
}